// round 4
// baseline (speedup 1.0000x reference)
#include <cuda_runtime.h>
#include <math.h>

#define B 128
#define LSEQ 4096
#define NF 2049          // rfft bins
#define NFP 2052         // padded row stride for g_h1 (16B-aligned rows)
#define L1E 1025         // expert conv1 out length
#define L1P 1028         // padded stride
#define L2E 513          // expert conv2/conv3 out length
#define L2P 516          // padded stride
#define NTASK 256        // B * TOP_K

// ---------------- packed f32x2 helpers (FFMA2: PTX-only dual fp32 FMA) ---------
__device__ __forceinline__ unsigned long long pack2(float lo, float hi) {
    unsigned long long r;
    asm("mov.b64 %0, {%1, %2};" : "=l"(r) : "f"(lo), "f"(hi));
    return r;
}
__device__ __forceinline__ void unpack2(unsigned long long v, float& lo, float& hi) {
    asm("mov.b64 {%0, %1}, %2;" : "=f"(lo), "=f"(hi) : "l"(v));
}
__device__ __forceinline__ unsigned long long ffma2(unsigned long long a,
                                                    unsigned long long b,
                                                    unsigned long long c) {
    unsigned long long d;
    asm("fma.rn.f32x2 %0, %1, %2, %3;" : "=l"(d) : "l"(a), "l"(b), "l"(c));
    return d;
}

// ---------------- scratch (device globals; no allocations allowed) -------------
__device__ float g_fft[B * 2 * NF];          // windowed rfft, [b][re/im][f]
__device__ float g_h1 [B * 32 * NFP];        // gate conv1 out (padded rows)
__device__ float g_pooled[B * 64];           // gate conv2 mean-pool accum
__device__ float g_tw[NTASK];                // normalized top-2 weights
__device__ int   g_ti[NTASK];                // top-2 expert ids
__device__ float g_e1[NTASK * 64  * L1P];
__device__ float g_e2[NTASK * 128 * L2P];
__device__ float g_e3[NTASK * 128 * L2P];

// ---------------- 1) Hann window + 4096-pt radix-2 FFT (one block per row) -----
__global__ void fft_kernel(const float* __restrict__ x) {
    __shared__ float re[4096];
    __shared__ float im[4096];
    __shared__ float twr[2048];
    __shared__ float twi[2048];
    int b = blockIdx.x;
    const float* xb = x + b * LSEQ;

    for (int i = threadIdx.x; i < 2048; i += blockDim.x) {
        float si, sr;
        sincospif(-(float)i * (1.0f / 2048.0f), &si, &sr);
        twr[i] = sr; twi[i] = si;
    }
    for (int i = threadIdx.x; i < 4096; i += blockDim.x) {
        float w = 0.5f * (1.0f - cospif((float)i * (1.0f / 2048.0f)));
        int j = __brev((unsigned)i) >> 20;   // 12-bit reversal
        re[j] = xb[i] * w;
        im[j] = 0.0f;
    }
    __syncthreads();

    for (int s = 1; s <= 12; s++) {
        int half = 1 << (s - 1);
        int len  = 1 << s;
        int shft = 12 - s;
        for (int t = threadIdx.x; t < 2048; t += blockDim.x) {
            int g   = t >> (s - 1);
            int pos = t & (half - 1);
            int i0  = g * len + pos;
            int i1  = i0 + half;
            int j   = pos << shft;
            float sr = twr[j], si = twi[j];
            float ar = re[i1], ai = im[i1];
            float tr = ar * sr - ai * si;
            float ti = ar * si + ai * sr;
            float br = re[i0], bi = im[i0];
            re[i1] = br - tr; im[i1] = bi - ti;
            re[i0] = br + tr; im[i0] = bi + ti;
        }
        __syncthreads();
    }
    const float sc = 1.0f / 64.0f;   // ortho norm: 1/sqrt(4096)
    for (int f = threadIdx.x; f < NF; f += blockDim.x) {
        g_fft[(b * 2 + 0) * NF + f] = re[f] * sc;
        g_fft[(b * 2 + 1) * NF + f] = im[f] * sc;
    }
}

// ---------------- 2) gate conv1: (2 -> 32), k=5, s=1, p=2, relu ----------------
__global__ void gconv1_kernel(const float* __restrict__ w1, const float* __restrict__ b1) {
    __shared__ __align__(16) float sin_[2][1036];
    __shared__ float sw[32][11];
    __shared__ float sb[32];
    int b  = blockIdx.y;
    int l0 = blockIdx.x * 1024;
    int tid = threadIdx.x;   // 256

    for (int i = tid; i < 2 * 1032; i += 256) {
        int ci = i / 1032, j = i % 1032;
        int g = l0 + j - 2;
        sin_[ci][j] = (g >= 0 && g < NF) ? g_fft[(b * 2 + ci) * NF + g] : 0.0f;
    }
    for (int i = tid; i < 320; i += 256) sw[i / 10][i % 10] = w1[i];
    if (tid < 32) sb[tid] = b1[tid];
    __syncthreads();

    float v[2][8];
    #pragma unroll
    for (int ci = 0; ci < 2; ci++) {
        float4 a = *(const float4*)&sin_[ci][4 * tid];
        float4 c = *(const float4*)&sin_[ci][4 * tid + 4];
        v[ci][0] = a.x; v[ci][1] = a.y; v[ci][2] = a.z; v[ci][3] = a.w;
        v[ci][4] = c.x; v[ci][5] = c.y; v[ci][6] = c.z; v[ci][7] = c.w;
    }

    #pragma unroll 4
    for (int co = 0; co < 32; co++) {
        float acc[4];
        #pragma unroll
        for (int i = 0; i < 4; i++) acc[i] = sb[co];
        #pragma unroll
        for (int ci = 0; ci < 2; ci++)
            #pragma unroll
            for (int k = 0; k < 5; k++) {
                float w = sw[co][ci * 5 + k];
                #pragma unroll
                for (int i = 0; i < 4; i++) acc[i] += w * v[ci][i + k];
            }
        float4 r;
        r.x = fmaxf(acc[0], 0.0f); r.y = fmaxf(acc[1], 0.0f);
        r.z = fmaxf(acc[2], 0.0f); r.w = fmaxf(acc[3], 0.0f);
        *(float4*)&g_h1[(b * 32 + co) * NFP + l0 + 4 * tid] = r;
    }

    if (blockIdx.x == 1 && tid == 0) {
        for (int co = 0; co < 32; co++) {
            float acc = sb[co];
            #pragma unroll
            for (int ci = 0; ci < 2; ci++)
                #pragma unroll
                for (int k = 0; k < 5; k++)
                    acc += sin_[ci][1024 + k] * sw[co][ci * 5 + k];
            g_h1[(b * 32 + co) * NFP + 2048] = fmaxf(acc, 0.0f);
        }
    }
}

__global__ void zero_pooled_kernel() {
    int i = blockIdx.x * blockDim.x + threadIdx.x;
    if (i < B * 64) g_pooled[i] = 0.0f;
}

// ---------------- 3) gate conv2 (32 -> 64, k5, p2) + mean pool, FFMA2 ----------
// grid (17, B), 256 thr; warp owns 8 co (4 co-pairs) x 4 contiguous l per lane.
__global__ void gconv2_pool_kernel(const float* __restrict__ w2, const float* __restrict__ b2) {
    __shared__ __align__(16) float sin_[16][132];
    __shared__ __align__(16) float swT[80][64];   // [ci*5+k][co], co adjacent
    int b   = blockIdx.y;
    int l0  = blockIdx.x * 128;
    int tid = threadIdx.x;
    int lane = tid & 31;
    int wid  = tid >> 5;

    unsigned long long acc2[4][4];
    #pragma unroll
    for (int j = 0; j < 4; j++)
        #pragma unroll
        for (int i = 0; i < 4; i++) acc2[j][i] = 0ull;

    for (int cb = 0; cb < 2; cb++) {
        __syncthreads();
        for (int i = tid; i < 16 * 132; i += 256) {
            int ci = i / 132, j = i % 132;
            int g = l0 + j - 2;
            sin_[ci][j] = (g >= 0 && g < NF) ? g_h1[(b * 32 + cb * 16 + ci) * NFP + g] : 0.0f;
        }
        for (int i = tid; i < 80 * 64; i += 256) {
            int r = i >> 6, co = i & 63;
            swT[r][co] = w2[co * 160 + cb * 80 + r];
        }
        __syncthreads();

        #pragma unroll 2
        for (int ci = 0; ci < 16; ci++) {
            float4 a = *(const float4*)&sin_[ci][4 * lane];
            float4 c = *(const float4*)&sin_[ci][4 * lane + 4];
            float v[8] = {a.x, a.y, a.z, a.w, c.x, c.y, c.z, c.w};
            unsigned long long vd[8];
            #pragma unroll
            for (int i = 0; i < 8; i++) vd[i] = pack2(v[i], v[i]);
            int rb = ci * 5;
            #pragma unroll
            for (int j = 0; j < 4; j++) {
                #pragma unroll
                for (int k = 0; k < 5; k++) {
                    unsigned long long wp =
                        *(const unsigned long long*)&swT[rb + k][(wid * 4 + j) * 2];
                    #pragma unroll
                    for (int i = 0; i < 4; i++)
                        acc2[j][i] = ffma2(wp, vd[i + k], acc2[j][i]);
                }
            }
        }
    }

    #pragma unroll
    for (int j = 0; j < 4; j++) {
        int co0 = (wid * 4 + j) * 2;
        float b0 = b2[co0], b1_ = b2[co0 + 1];
        float p0 = 0.0f, p1 = 0.0f;
        #pragma unroll
        for (int i = 0; i < 4; i++) {
            int l = l0 + 4 * lane + i;
            float lo, hi;
            unpack2(acc2[j][i], lo, hi);
            if (l < NF) {
                p0 += fmaxf(lo + b0, 0.0f);
                p1 += fmaxf(hi + b1_, 0.0f);
            }
        }
        #pragma unroll
        for (int off = 16; off; off >>= 1) {
            p0 += __shfl_down_sync(0xffffffffu, p0, off, 32);
            p1 += __shfl_down_sync(0xffffffffu, p1, off, 32);
        }
        if (lane == 0) {
            atomicAdd(&g_pooled[b * 64 + co0], p0);
            atomicAdd(&g_pooled[b * 64 + co0 + 1], p1);
        }
    }
}

// ---------------- 4) router MLP + softmax + top2 + aux (one block) -------------
__global__ void gate_mlp_kernel(const float* __restrict__ w1, const float* __restrict__ b1,
                                const float* __restrict__ w2, const float* __restrict__ b2,
                                float* __restrict__ out, int out_size) {
    int b = threadIdx.x;   // 128
    const float inv = 1.0f / 2049.0f;
    float p[64];
    #pragma unroll
    for (int i = 0; i < 64; i++) p[i] = g_pooled[b * 64 + i] * inv;

    float lg[8];
    #pragma unroll
    for (int e = 0; e < 8; e++) lg[e] = b2[e];

    for (int j = 0; j < 128; j++) {
        float h0 = 0.f, h1 = 0.f, h2 = 0.f, h3 = 0.f;
        #pragma unroll
        for (int i = 0; i < 64; i += 4) {
            h0 += p[i + 0] * w1[j * 64 + i + 0];
            h1 += p[i + 1] * w1[j * 64 + i + 1];
            h2 += p[i + 2] * w1[j * 64 + i + 2];
            h3 += p[i + 3] * w1[j * 64 + i + 3];
        }
        float h = fmaxf((h0 + h1) + (h2 + h3) + b1[j], 0.0f);
        #pragma unroll
        for (int e = 0; e < 8; e++) lg[e] += h * w2[e * 128 + j];
    }

    float m = lg[0];
    #pragma unroll
    for (int e = 1; e < 8; e++) m = fmaxf(m, lg[e]);
    float rw[8], s = 0.0f;
    #pragma unroll
    for (int e = 0; e < 8; e++) { rw[e] = expf(lg[e] - m); s += rw[e]; }
    float invs = 1.0f / s;
    #pragma unroll
    for (int e = 0; e < 8; e++) rw[e] *= invs;

    int i0 = 0;
    #pragma unroll
    for (int e = 1; e < 8; e++) if (rw[e] > rw[i0]) i0 = e;
    int i1 = (i0 == 0) ? 1 : 0;
    #pragma unroll
    for (int e = 0; e < 8; e++) if (e != i1 && e != i0 && rw[e] > rw[i1]) i1 = e;

    float t0 = rw[i0], t1 = rw[i1];
    float tn = 1.0f / (t0 + t1);
    g_ti[b * 2 + 0] = i0; g_ti[b * 2 + 1] = i1;
    g_tw[b * 2 + 0] = t0 * tn; g_tw[b * 2 + 1] = t1 * tn;

    __shared__ float srw[8], slg[8];
    if (b < 8) { srw[b] = 0.0f; slg[b] = 0.0f; }
    __syncthreads();
    #pragma unroll
    for (int e = 0; e < 8; e++) {
        atomicAdd(&srw[e], rw[e]);
        atomicAdd(&slg[e], lg[e]);
    }
    __syncthreads();
    if (b == 0) {
        float aux = 0.0f;
        #pragma unroll
        for (int e = 0; e < 8; e++)
            aux += (srw[e] * (1.0f / 128.0f)) * (slg[e] * (1.0f / 128.0f));
        out[out_size - 1] = 0.01f * 8.0f * aux;
    }
}

// ---------------- 5) expert conv1: (2 -> 64), k=7, s=2, p=3, relu --------------
__global__ void econv1_kernel(const float* __restrict__ ew1, const float* __restrict__ eb1) {
    __shared__ __align__(16) float sin_[2][2056];
    __shared__ float sw[64][16];
    __shared__ float sb[64];
    int t = blockIdx.x;
    int b = t >> 1;
    int e = g_ti[t];
    int tid = threadIdx.x;   // 256

    for (int i = tid; i < 2 * 2056; i += 256) {
        int ci = i / 2056, j = i % 2056;
        int g = j - 3;
        sin_[ci][j] = (g >= 0 && g < NF) ? g_fft[(b * 2 + ci) * NF + g] : 0.0f;
    }
    for (int i = tid; i < 64 * 14; i += 256) sw[i / 14][i % 14] = ew1[e * 896 + i];
    if (tid < 64) sb[tid] = eb1[e * 64 + tid];
    __syncthreads();

    float v[2][16];
    #pragma unroll
    for (int ci = 0; ci < 2; ci++) {
        float4 a = *(const float4*)&sin_[ci][8 * tid];
        float4 c = *(const float4*)&sin_[ci][8 * tid + 4];
        float4 d = *(const float4*)&sin_[ci][8 * tid + 8];
        float4 f = *(const float4*)&sin_[ci][8 * tid + 12];
        v[ci][0]=a.x;  v[ci][1]=a.y;  v[ci][2]=a.z;  v[ci][3]=a.w;
        v[ci][4]=c.x;  v[ci][5]=c.y;  v[ci][6]=c.z;  v[ci][7]=c.w;
        v[ci][8]=d.x;  v[ci][9]=d.y;  v[ci][10]=d.z; v[ci][11]=d.w;
        v[ci][12]=f.x; v[ci][13]=f.y; v[ci][14]=f.z; v[ci][15]=f.w;
    }

    #pragma unroll 2
    for (int co = 0; co < 64; co++) {
        float acc[4];
        #pragma unroll
        for (int i = 0; i < 4; i++) acc[i] = sb[co];
        #pragma unroll
        for (int ci = 0; ci < 2; ci++)
            #pragma unroll
            for (int k = 0; k < 7; k++) {
                float w = sw[co][ci * 7 + k];
                #pragma unroll
                for (int i = 0; i < 4; i++) acc[i] += w * v[ci][2 * i + k];
            }
        float4 r;
        r.x = fmaxf(acc[0], 0.0f); r.y = fmaxf(acc[1], 0.0f);
        r.z = fmaxf(acc[2], 0.0f); r.w = fmaxf(acc[3], 0.0f);
        *(float4*)&g_e1[((size_t)t * 64 + co) * L1P + 4 * tid] = r;
    }

    if (tid < 64) {
        int co = tid;
        float acc = sb[co];
        #pragma unroll
        for (int ci = 0; ci < 2; ci++)
            #pragma unroll
            for (int k = 0; k < 7; k++)
                acc += sin_[ci][2048 + k] * sw[co][ci * 7 + k];
        g_e1[((size_t)t * 64 + co) * L1P + 1024] = fmaxf(acc, 0.0f);
    }
}

// ---------------- 6) expert conv2: (64 -> 128), k=5, s=2, p=2, relu, FFMA2 -----
__global__ void econv2_kernel(const float* __restrict__ ew2, const float* __restrict__ eb2) {
    __shared__ __align__(16) float sin_[16][260];
    __shared__ __align__(16) float swT[80][64];
    int t  = blockIdx.z;
    int e  = g_ti[t];
    int l0 = blockIdx.x * 128;
    int cgrp = blockIdx.y;             // co base = cgrp*64
    int tid = threadIdx.x;
    int lane = tid & 31;
    int wid  = tid >> 5;

    unsigned long long acc2[4][4];
    #pragma unroll
    for (int j = 0; j < 4; j++)
        #pragma unroll
        for (int i = 0; i < 4; i++) acc2[j][i] = 0ull;

    const float* e1base = g_e1 + (size_t)t * 64 * L1P;

    for (int cb = 0; cb < 4; cb++) {
        __syncthreads();
        for (int i = tid; i < 16 * 260; i += 256) {
            int ci = i / 260, j = i % 260;
            int g = 2 * l0 - 2 + j;
            sin_[ci][j] = (g >= 0 && g < L1E) ? e1base[(cb * 16 + ci) * L1P + g] : 0.0f;
        }
        for (int i = tid; i < 80 * 64; i += 256) {
            int r = i >> 6, co = i & 63;
            swT[r][co] = ew2[((e * 128 + cgrp * 64 + co) * 64 + cb * 16) * 5 + r];
        }
        __syncthreads();

        #pragma unroll 2
        for (int ci = 0; ci < 16; ci++) {
            float4 a = *(const float4*)&sin_[ci][8 * lane];
            float4 c = *(const float4*)&sin_[ci][8 * lane + 4];
            float4 d = *(const float4*)&sin_[ci][8 * lane + 8];
            float v[12] = {a.x,a.y,a.z,a.w, c.x,c.y,c.z,c.w, d.x,d.y,d.z,d.w};
            unsigned long long vd[11];
            #pragma unroll
            for (int i = 0; i < 11; i++) vd[i] = pack2(v[i], v[i]);
            int rb = ci * 5;
            #pragma unroll
            for (int j = 0; j < 4; j++) {
                #pragma unroll
                for (int k = 0; k < 5; k++) {
                    unsigned long long wp =
                        *(const unsigned long long*)&swT[rb + k][(wid * 4 + j) * 2];
                    #pragma unroll
                    for (int i = 0; i < 4; i++)
                        acc2[j][i] = ffma2(wp, vd[2 * i + k], acc2[j][i]);
                }
            }
        }
    }

    #pragma unroll
    for (int j = 0; j < 4; j++) {
        int co0 = cgrp * 64 + (wid * 4 + j) * 2;
        float b0 = eb2[e * 128 + co0];
        float b1_ = eb2[e * 128 + co0 + 1];
        int lbase = l0 + 4 * lane;
        float r0[4], r1[4];
        #pragma unroll
        for (int i = 0; i < 4; i++) {
            float lo, hi;
            unpack2(acc2[j][i], lo, hi);
            r0[i] = fmaxf(lo + b0, 0.0f);
            r1[i] = fmaxf(hi + b1_, 0.0f);
        }
        float* d0 = &g_e2[((size_t)t * 128 + co0) * L2P + lbase];
        float* d1 = &g_e2[((size_t)t * 128 + co0 + 1) * L2P + lbase];
        if (lbase + 3 < L2E) {
            *(float4*)d0 = make_float4(r0[0], r0[1], r0[2], r0[3]);
            *(float4*)d1 = make_float4(r1[0], r1[1], r1[2], r1[3]);
        } else {
            #pragma unroll
            for (int i = 0; i < 4; i++)
                if (lbase + i < L2E) { d0[i] = r0[i]; d1[i] = r1[i]; }
        }
    }
}

// ---------------- 7) expert conv3: (128 -> 128), k=3, s=1, p=1, relu, FFMA2 ----
__global__ void econv3_kernel(const float* __restrict__ ew3, const float* __restrict__ eb3) {
    __shared__ __align__(16) float sin_[16][132];
    __shared__ __align__(16) float swT[48][64];
    int t  = blockIdx.z;
    int e  = g_ti[t];
    int l0 = blockIdx.x * 128;
    int cgrp = blockIdx.y;
    int tid = threadIdx.x;
    int lane = tid & 31;
    int wid  = tid >> 5;

    unsigned long long acc2[4][4];
    #pragma unroll
    for (int j = 0; j < 4; j++)
        #pragma unroll
        for (int i = 0; i < 4; i++) acc2[j][i] = 0ull;

    const float* e2base = g_e2 + (size_t)t * 128 * L2P;

    for (int cb = 0; cb < 8; cb++) {
        __syncthreads();
        for (int i = tid; i < 16 * 132; i += 256) {
            int ci = i / 132, j = i % 132;
            int g = l0 - 1 + j;
            sin_[ci][j] = (g >= 0 && g < L2E) ? e2base[(cb * 16 + ci) * L2P + g] : 0.0f;
        }
        for (int i = tid; i < 48 * 64; i += 256) {
            int r = i >> 6, co = i & 63;
            swT[r][co] = ew3[((e * 128 + cgrp * 64 + co) * 128 + cb * 16) * 3 + r];
        }
        __syncthreads();

        #pragma unroll 2
        for (int ci = 0; ci < 16; ci++) {
            float4 a = *(const float4*)&sin_[ci][4 * lane];
            float4 c = *(const float4*)&sin_[ci][4 * lane + 4];
            float v[8] = {a.x,a.y,a.z,a.w, c.x,c.y,c.z,c.w};
            unsigned long long vd[6];
            #pragma unroll
            for (int i = 0; i < 6; i++) vd[i] = pack2(v[i], v[i]);
            int rb = ci * 3;
            #pragma unroll
            for (int j = 0; j < 4; j++) {
                #pragma unroll
                for (int k = 0; k < 3; k++) {
                    unsigned long long wp =
                        *(const unsigned long long*)&swT[rb + k][(wid * 4 + j) * 2];
                    #pragma unroll
                    for (int i = 0; i < 4; i++)
                        acc2[j][i] = ffma2(wp, vd[i + k], acc2[j][i]);
                }
            }
        }
    }

    #pragma unroll
    for (int j = 0; j < 4; j++) {
        int co0 = cgrp * 64 + (wid * 4 + j) * 2;
        float b0 = eb3[e * 128 + co0];
        float b1_ = eb3[e * 128 + co0 + 1];
        int lbase = l0 + 4 * lane;
        float r0[4], r1[4];
        #pragma unroll
        for (int i = 0; i < 4; i++) {
            float lo, hi;
            unpack2(acc2[j][i], lo, hi);
            r0[i] = fmaxf(lo + b0, 0.0f);
            r1[i] = fmaxf(hi + b1_, 0.0f);
        }
        float* d0 = &g_e3[((size_t)t * 128 + co0) * L2P + lbase];
        float* d1 = &g_e3[((size_t)t * 128 + co0 + 1) * L2P + lbase];
        if (lbase + 3 < L2E) {
            *(float4*)d0 = make_float4(r0[0], r0[1], r0[2], r0[3]);
            *(float4*)d1 = make_float4(r1[0], r1[1], r1[2], r1[3]);
        } else {
            #pragma unroll
            for (int i = 0; i < 4; i++)
                if (lbase + i < L2E) { d0[i] = r0[i]; d1[i] = r1[i]; }
        }
    }
}

// ---------------- 8) top-2 weighted combine + adaptive max-pool (513 -> 256) ---
__global__ void pool_kernel(float* __restrict__ out) {
    int idx = blockIdx.x * blockDim.x + threadIdx.x;
    if (idx >= B * 128 * 256) return;
    int o  = idx & 255;
    int co = (idx >> 8) & 127;
    int b  = idx >> 15;
    float w0 = g_tw[b * 2 + 0];
    float w1 = g_tw[b * 2 + 1];
    const float* p0 = g_e3 + ((size_t)(b * 2 + 0) * 128 + co) * L2P;
    const float* p1 = g_e3 + ((size_t)(b * 2 + 1) * 128 + co) * L2P;
    int s  = (o * 513) >> 8;
    int en = (o * 513 + 513 + 255) >> 8;
    float m = -INFINITY;
    for (int l = s; l < en; l++)
        m = fmaxf(m, w0 * p0[l] + w1 * p1[l]);
    out[idx] = m;
}

// ---------------- launch --------------------------------------------------------
extern "C" void kernel_launch(void* const* d_in, const int* in_sizes, int n_in,
                              void* d_out, int out_size) {
    const float* x    = (const float*)d_in[0];
    const float* gw1  = (const float*)d_in[1];
    const float* gb1  = (const float*)d_in[2];
    const float* gw2  = (const float*)d_in[3];
    const float* gb2  = (const float*)d_in[4];
    const float* mw1  = (const float*)d_in[5];
    const float* mb1  = (const float*)d_in[6];
    const float* mw2  = (const float*)d_in[7];
    const float* mb2  = (const float*)d_in[8];
    const float* ew1  = (const float*)d_in[9];
    const float* eb1  = (const float*)d_in[10];
    const float* ew2  = (const float*)d_in[11];
    const float* eb2  = (const float*)d_in[12];
    const float* ew3  = (const float*)d_in[13];
    const float* eb3  = (const float*)d_in[14];
    float* out = (float*)d_out;

    fft_kernel<<<B, 1024>>>(x);
    gconv1_kernel<<<dim3(2, B), 256>>>(gw1, gb1);
    zero_pooled_kernel<<<32, 256>>>();
    gconv2_pool_kernel<<<dim3(17, B), 256>>>(gw2, gb2);
    gate_mlp_kernel<<<1, 128>>>(mw1, mb1, mw2, mb2, out, out_size);
    econv1_kernel<<<NTASK, 256>>>(ew1, eb1);
    econv2_kernel<<<dim3(5, 2, NTASK), 256>>>(ew2, eb2);
    econv3_kernel<<<dim3(5, 2, NTASK), 256>>>(ew3, eb3);
    pool_kernel<<<16384, 256>>>(out);
}

// round 6
// speedup vs baseline: 1.3347x; 1.3347x over previous
#include <cuda_runtime.h>
#include <math.h>

#define B 128
#define LSEQ 4096
#define NF 2049          // rfft bins
#define NFP 2052         // padded row stride for g_h1
#define L1E 1025         // expert conv1 out length
#define L1P 1028
#define L2E 513          // expert conv2/conv3 out length
#define L2P 516
#define NTASK 256        // B * TOP_K

// ---------------- scratch (device globals) -------------------------------------
__device__ float g_fft[B * 2 * NF];
__device__ float g_h1 [B * 32 * NFP];
__device__ float g_pooled[B * 64];
__device__ float g_tw[NTASK];
__device__ int   g_ti[NTASK];
__device__ float g_e1[NTASK * 64  * L1P];
__device__ float g_e2[NTASK * 128 * L2P];
__device__ float g_e3[NTASK * 128 * L2P];

// ---------------- 1) Hann window + 4096-pt radix-2 FFT + zero pooled -----------
__global__ void fft_kernel(const float* __restrict__ x) {
    __shared__ float re[4096];
    __shared__ float im[4096];
    __shared__ float twr[2048];
    __shared__ float twi[2048];
    int b = blockIdx.x;
    const float* xb = x + b * LSEQ;

    if (threadIdx.x < 64) g_pooled[b * 64 + threadIdx.x] = 0.0f;

    for (int i = threadIdx.x; i < 2048; i += blockDim.x) {
        float si, sr;
        sincospif(-(float)i * (1.0f / 2048.0f), &si, &sr);
        twr[i] = sr; twi[i] = si;
    }
    for (int i = threadIdx.x; i < 4096; i += blockDim.x) {
        float w = 0.5f * (1.0f - cospif((float)i * (1.0f / 2048.0f)));
        int j = __brev((unsigned)i) >> 20;
        re[j] = xb[i] * w;
        im[j] = 0.0f;
    }
    __syncthreads();

    for (int s = 1; s <= 12; s++) {
        int half = 1 << (s - 1);
        int len  = 1 << s;
        int shft = 12 - s;
        for (int t = threadIdx.x; t < 2048; t += blockDim.x) {
            int g   = t >> (s - 1);
            int pos = t & (half - 1);
            int i0  = g * len + pos;
            int i1  = i0 + half;
            int j   = pos << shft;
            float sr = twr[j], si = twi[j];
            float ar = re[i1], ai = im[i1];
            float tr = ar * sr - ai * si;
            float ti = ar * si + ai * sr;
            float br = re[i0], bi = im[i0];
            re[i1] = br - tr; im[i1] = bi - ti;
            re[i0] = br + tr; im[i0] = bi + ti;
        }
        __syncthreads();
    }
    const float sc = 1.0f / 64.0f;
    for (int f = threadIdx.x; f < NF; f += blockDim.x) {
        g_fft[(b * 2 + 0) * NF + f] = re[f] * sc;
        g_fft[(b * 2 + 1) * NF + f] = im[f] * sc;
    }
}

// ---------------- 2) gate conv1: (2 -> 32), k=5, s=1, p=2, relu ----------------
__global__ void gconv1_kernel(const float* __restrict__ w1, const float* __restrict__ b1) {
    __shared__ __align__(16) float sin_[2][1036];
    __shared__ float sw[32][11];
    __shared__ float sb[32];
    int b  = blockIdx.y;
    int l0 = blockIdx.x * 1024;
    int tid = threadIdx.x;   // 256

    for (int i = tid; i < 2 * 1032; i += 256) {
        int ci = i / 1032, j = i % 1032;
        int g = l0 + j - 2;
        sin_[ci][j] = (g >= 0 && g < NF) ? g_fft[(b * 2 + ci) * NF + g] : 0.0f;
    }
    for (int i = tid; i < 320; i += 256) sw[i / 10][i % 10] = w1[i];
    if (tid < 32) sb[tid] = b1[tid];
    __syncthreads();

    float v[2][8];
    #pragma unroll
    for (int ci = 0; ci < 2; ci++) {
        float4 a = *(const float4*)&sin_[ci][4 * tid];
        float4 c = *(const float4*)&sin_[ci][4 * tid + 4];
        v[ci][0] = a.x; v[ci][1] = a.y; v[ci][2] = a.z; v[ci][3] = a.w;
        v[ci][4] = c.x; v[ci][5] = c.y; v[ci][6] = c.z; v[ci][7] = c.w;
    }

    #pragma unroll 4
    for (int co = 0; co < 32; co++) {
        float acc[4];
        #pragma unroll
        for (int i = 0; i < 4; i++) acc[i] = sb[co];
        #pragma unroll
        for (int ci = 0; ci < 2; ci++)
            #pragma unroll
            for (int k = 0; k < 5; k++) {
                float w = sw[co][ci * 5 + k];
                #pragma unroll
                for (int i = 0; i < 4; i++) acc[i] += w * v[ci][i + k];
            }
        float4 r;
        r.x = fmaxf(acc[0], 0.0f); r.y = fmaxf(acc[1], 0.0f);
        r.z = fmaxf(acc[2], 0.0f); r.w = fmaxf(acc[3], 0.0f);
        *(float4*)&g_h1[(b * 32 + co) * NFP + l0 + 4 * tid] = r;
    }

    if (blockIdx.x == 1 && tid == 0) {
        for (int co = 0; co < 32; co++) {
            float acc = sb[co];
            #pragma unroll
            for (int ci = 0; ci < 2; ci++)
                #pragma unroll
                for (int k = 0; k < 5; k++)
                    acc += sin_[ci][1024 + k] * sw[co][ci * 5 + k];
            g_h1[(b * 32 + co) * NFP + 2048] = fmaxf(acc, 0.0f);
        }
    }
}

// ---------------- 3) gate conv2 (32 -> 64, k5, p2) + mean pool -----------------
// grid (8, B), 256 thr; warp owns 8 co; lane owns 8 contiguous l (256 l/block).
// Tail l=2048 handled by tid<64 of block x=7.
__global__ void __launch_bounds__(256, 2)
gconv2_pool_kernel(const float* __restrict__ w2, const float* __restrict__ b2) {
    __shared__ __align__(16) float sin_[16][264];
    __shared__ float sw[64][81];
    int b   = blockIdx.y;
    int l0  = blockIdx.x * 256;
    int tid = threadIdx.x;
    int lane = tid & 31;
    int wid  = tid >> 5;
    bool tail = (blockIdx.x == 7) && (tid < 64);

    float acc[8][8];
    #pragma unroll
    for (int j = 0; j < 8; j++)
        #pragma unroll
        for (int i = 0; i < 8; i++) acc[j][i] = 0.0f;
    float tacc = 0.0f;

    for (int cb = 0; cb < 2; cb++) {
        __syncthreads();
        for (int i = tid; i < 16 * 261; i += 256) {
            int ci = i / 261, j = i % 261;
            int g = l0 + j - 2;
            sin_[ci][j] = (g >= 0 && g < NF) ? g_h1[(b * 32 + cb * 16 + ci) * NFP + g] : 0.0f;
        }
        for (int i = tid; i < 64 * 80; i += 256) {
            int co = i / 80, r = i % 80;
            sw[co][r] = w2[co * 160 + cb * 80 + r];
        }
        __syncthreads();

        #pragma unroll 1
        for (int ci = 0; ci < 16; ci++) {
            float4 a = *(const float4*)&sin_[ci][8 * lane];
            float4 c = *(const float4*)&sin_[ci][8 * lane + 4];
            float4 d = *(const float4*)&sin_[ci][8 * lane + 8];
            float v[12] = {a.x,a.y,a.z,a.w, c.x,c.y,c.z,c.w, d.x,d.y,d.z,d.w};
            #pragma unroll
            for (int j = 0; j < 8; j++) {
                #pragma unroll
                for (int k = 0; k < 5; k++) {
                    float w = sw[wid * 8 + j][ci * 5 + k];
                    #pragma unroll
                    for (int i = 0; i < 8; i++)
                        acc[j][i] += w * v[i + k];
                }
            }
        }
        if (tail) {
            // l = 2048: g = 2046+k -> j = 256+k
            #pragma unroll 1
            for (int ci = 0; ci < 16; ci++)
                #pragma unroll
                for (int k = 0; k < 5; k++)
                    tacc += sin_[ci][256 + k] * sw[tid][ci * 5 + k];
        }
    }

    #pragma unroll
    for (int j = 0; j < 8; j++) {
        int co = wid * 8 + j;
        float bias = b2[co];
        float p = 0.0f;
        #pragma unroll
        for (int i = 0; i < 8; i++)
            p += fmaxf(acc[j][i] + bias, 0.0f);
        #pragma unroll
        for (int off = 16; off; off >>= 1)
            p += __shfl_down_sync(0xffffffffu, p, off, 32);
        if (lane == 0) atomicAdd(&g_pooled[b * 64 + co], p);
    }
    if (tail)
        atomicAdd(&g_pooled[b * 64 + tid], fmaxf(tacc + b2[tid], 0.0f));
}

// ---------------- 4) router MLP + softmax + top2 + aux (one block) -------------
__global__ void gate_mlp_kernel(const float* __restrict__ w1, const float* __restrict__ b1,
                                const float* __restrict__ w2, const float* __restrict__ b2,
                                float* __restrict__ out, int out_size) {
    __shared__ float s1[128 * 64];
    __shared__ float s2[8 * 128];
    int b = threadIdx.x;   // 128
    for (int i = b; i < 128 * 64; i += 128) s1[i] = w1[i];
    for (int i = b; i < 8 * 128; i += 128) s2[i] = w2[i];
    __syncthreads();

    const float inv = 1.0f / 2049.0f;
    float p[64];
    #pragma unroll
    for (int i = 0; i < 64; i++) p[i] = g_pooled[b * 64 + i] * inv;

    float lg[8];
    #pragma unroll
    for (int e = 0; e < 8; e++) lg[e] = b2[e];

    for (int j = 0; j < 128; j++) {
        float h0 = 0.f, h1 = 0.f, h2 = 0.f, h3 = 0.f;
        #pragma unroll
        for (int i = 0; i < 64; i += 4) {
            h0 += p[i + 0] * s1[j * 64 + i + 0];
            h1 += p[i + 1] * s1[j * 64 + i + 1];
            h2 += p[i + 2] * s1[j * 64 + i + 2];
            h3 += p[i + 3] * s1[j * 64 + i + 3];
        }
        float h = fmaxf((h0 + h1) + (h2 + h3) + b1[j], 0.0f);
        #pragma unroll
        for (int e = 0; e < 8; e++) lg[e] += h * s2[e * 128 + j];
    }

    float m = lg[0];
    #pragma unroll
    for (int e = 1; e < 8; e++) m = fmaxf(m, lg[e]);
    float rw[8], s = 0.0f;
    #pragma unroll
    for (int e = 0; e < 8; e++) { rw[e] = expf(lg[e] - m); s += rw[e]; }
    float invs = 1.0f / s;
    #pragma unroll
    for (int e = 0; e < 8; e++) rw[e] *= invs;

    int i0 = 0;
    #pragma unroll
    for (int e = 1; e < 8; e++) if (rw[e] > rw[i0]) i0 = e;
    int i1 = (i0 == 0) ? 1 : 0;
    #pragma unroll
    for (int e = 0; e < 8; e++) if (e != i1 && e != i0 && rw[e] > rw[i1]) i1 = e;

    float t0 = rw[i0], t1 = rw[i1];
    float tn = 1.0f / (t0 + t1);
    g_ti[b * 2 + 0] = i0; g_ti[b * 2 + 1] = i1;
    g_tw[b * 2 + 0] = t0 * tn; g_tw[b * 2 + 1] = t1 * tn;

    __shared__ float srw[8], slg[8];
    if (b < 8) { srw[b] = 0.0f; slg[b] = 0.0f; }
    __syncthreads();
    #pragma unroll
    for (int e = 0; e < 8; e++) {
        atomicAdd(&srw[e], rw[e]);
        atomicAdd(&slg[e], lg[e]);
    }
    __syncthreads();
    if (b == 0) {
        float aux = 0.0f;
        #pragma unroll
        for (int e = 0; e < 8; e++)
            aux += (srw[e] * (1.0f / 128.0f)) * (slg[e] * (1.0f / 128.0f));
        out[out_size - 1] = 0.01f * 8.0f * aux;
    }
}

// ---------------- 5) expert conv1: (2 -> 64), k=7, s=2, p=3, relu --------------
__global__ void econv1_kernel(const float* __restrict__ ew1, const float* __restrict__ eb1) {
    __shared__ __align__(16) float sin_[2][2056];
    __shared__ float sw[64][16];
    __shared__ float sb[64];
    int t = blockIdx.x;
    int b = t >> 1;
    int e = g_ti[t];
    int tid = threadIdx.x;   // 256

    for (int i = tid; i < 2 * 2056; i += 256) {
        int ci = i / 2056, j = i % 2056;
        int g = j - 3;
        sin_[ci][j] = (g >= 0 && g < NF) ? g_fft[(b * 2 + ci) * NF + g] : 0.0f;
    }
    for (int i = tid; i < 64 * 14; i += 256) sw[i / 14][i % 14] = ew1[e * 896 + i];
    if (tid < 64) sb[tid] = eb1[e * 64 + tid];
    __syncthreads();

    float v[2][16];
    #pragma unroll
    for (int ci = 0; ci < 2; ci++) {
        float4 a = *(const float4*)&sin_[ci][8 * tid];
        float4 c = *(const float4*)&sin_[ci][8 * tid + 4];
        float4 d = *(const float4*)&sin_[ci][8 * tid + 8];
        float4 f = *(const float4*)&sin_[ci][8 * tid + 12];
        v[ci][0]=a.x;  v[ci][1]=a.y;  v[ci][2]=a.z;  v[ci][3]=a.w;
        v[ci][4]=c.x;  v[ci][5]=c.y;  v[ci][6]=c.z;  v[ci][7]=c.w;
        v[ci][8]=d.x;  v[ci][9]=d.y;  v[ci][10]=d.z; v[ci][11]=d.w;
        v[ci][12]=f.x; v[ci][13]=f.y; v[ci][14]=f.z; v[ci][15]=f.w;
    }

    #pragma unroll 2
    for (int co = 0; co < 64; co++) {
        float acc[4];
        #pragma unroll
        for (int i = 0; i < 4; i++) acc[i] = sb[co];
        #pragma unroll
        for (int ci = 0; ci < 2; ci++)
            #pragma unroll
            for (int k = 0; k < 7; k++) {
                float w = sw[co][ci * 7 + k];
                #pragma unroll
                for (int i = 0; i < 4; i++) acc[i] += w * v[ci][2 * i + k];
            }
        float4 r;
        r.x = fmaxf(acc[0], 0.0f); r.y = fmaxf(acc[1], 0.0f);
        r.z = fmaxf(acc[2], 0.0f); r.w = fmaxf(acc[3], 0.0f);
        *(float4*)&g_e1[((size_t)t * 64 + co) * L1P + 4 * tid] = r;
    }

    if (tid < 64) {
        int co = tid;
        float acc = sb[co];
        #pragma unroll
        for (int ci = 0; ci < 2; ci++)
            #pragma unroll
            for (int k = 0; k < 7; k++)
                acc += sin_[ci][2048 + k] * sw[co][ci * 7 + k];
        g_e1[((size_t)t * 64 + co) * L1P + 1024] = fmaxf(acc, 0.0f);
    }
}

// ---------------- 6) expert conv2: (64 -> 128), k=5, s=2, p=2, relu ------------
// grid (2, 2, NTASK), 256 thr; warp: 8 co, lane: 8 contiguous out-l (256/block).
// Tail l=512 handled by tid<64 of block x=1.
__global__ void __launch_bounds__(256, 2)
econv2_kernel(const float* __restrict__ ew2, const float* __restrict__ eb2) {
    __shared__ __align__(16) float sin_[8][520];
    __shared__ float sw[64][41];
    int t  = blockIdx.z;
    int e  = g_ti[t];
    int l0 = blockIdx.x * 256;
    int cgrp = blockIdx.y;             // co base = cgrp*64
    int tid = threadIdx.x;
    int lane = tid & 31;
    int wid  = tid >> 5;
    bool tail = (blockIdx.x == 1) && (tid < 64);

    float acc[8][8];
    #pragma unroll
    for (int j = 0; j < 8; j++)
        #pragma unroll
        for (int i = 0; i < 8; i++) acc[j][i] = 0.0f;
    float tacc = 0.0f;

    const float* e1base = g_e1 + (size_t)t * 64 * L1P;

    for (int cb = 0; cb < 8; cb++) {
        __syncthreads();
        for (int i = tid; i < 8 * 517; i += 256) {
            int ci = i / 517, j = i % 517;
            int g = 2 * l0 - 2 + j;
            sin_[ci][j] = (g >= 0 && g < L1E) ? e1base[(cb * 8 + ci) * L1P + g] : 0.0f;
        }
        for (int i = tid; i < 64 * 40; i += 256) {
            int co = i / 40, r = i % 40;
            sw[co][r] = ew2[((e * 128 + cgrp * 64 + co) * 64 + cb * 8) * 5 + r];
        }
        __syncthreads();

        #pragma unroll 1
        for (int ci = 0; ci < 8; ci++) {
            // j = 16*lane + 2i + k, i<=7, k<=4 -> 20 floats
            float4 a0 = *(const float4*)&sin_[ci][16 * lane];
            float4 a1 = *(const float4*)&sin_[ci][16 * lane + 4];
            float4 a2 = *(const float4*)&sin_[ci][16 * lane + 8];
            float4 a3 = *(const float4*)&sin_[ci][16 * lane + 12];
            float4 a4 = *(const float4*)&sin_[ci][16 * lane + 16];
            float v[20] = {a0.x,a0.y,a0.z,a0.w, a1.x,a1.y,a1.z,a1.w,
                           a2.x,a2.y,a2.z,a2.w, a3.x,a3.y,a3.z,a3.w,
                           a4.x,a4.y,a4.z,a4.w};
            #pragma unroll
            for (int j = 0; j < 8; j++) {
                #pragma unroll
                for (int k = 0; k < 5; k++) {
                    float w = sw[wid * 8 + j][ci * 5 + k];
                    #pragma unroll
                    for (int i = 0; i < 8; i++)
                        acc[j][i] += w * v[2 * i + k];
                }
            }
        }
        if (tail) {
            // l = 512: g = 1022+k -> j = 512+k
            #pragma unroll 1
            for (int ci = 0; ci < 8; ci++)
                #pragma unroll
                for (int k = 0; k < 5; k++)
                    tacc += sin_[ci][512 + k] * sw[tid][ci * 5 + k];
        }
    }

    #pragma unroll
    for (int j = 0; j < 8; j++) {
        int co = cgrp * 64 + wid * 8 + j;
        float bias = eb2[e * 128 + co];
        int lbase = l0 + 8 * lane;
        float* dst = &g_e2[((size_t)t * 128 + co) * L2P + lbase];
        float4 r0, r1;
        r0.x = fmaxf(acc[j][0] + bias, 0.0f); r0.y = fmaxf(acc[j][1] + bias, 0.0f);
        r0.z = fmaxf(acc[j][2] + bias, 0.0f); r0.w = fmaxf(acc[j][3] + bias, 0.0f);
        r1.x = fmaxf(acc[j][4] + bias, 0.0f); r1.y = fmaxf(acc[j][5] + bias, 0.0f);
        r1.z = fmaxf(acc[j][6] + bias, 0.0f); r1.w = fmaxf(acc[j][7] + bias, 0.0f);
        *(float4*)dst = r0;
        *(float4*)(dst + 4) = r1;
    }
    if (tail) {
        int co = cgrp * 64 + tid;
        g_e2[((size_t)t * 128 + co) * L2P + 512] = fmaxf(tacc + eb2[e * 128 + co], 0.0f);
    }
}

// ---------------- 7) expert conv3: (128 -> 128), k=3, s=1, p=1, relu -----------
// grid (2, 2, NTASK), 256 thr; warp: 8 co, lane: 8 contiguous l.
__global__ void __launch_bounds__(256, 2)
econv3_kernel(const float* __restrict__ ew3, const float* __restrict__ eb3) {
    __shared__ __align__(16) float sin_[16][260];
    __shared__ float sw[64][49];
    int t  = blockIdx.z;
    int e  = g_ti[t];
    int l0 = blockIdx.x * 256;
    int cgrp = blockIdx.y;
    int tid = threadIdx.x;
    int lane = tid & 31;
    int wid  = tid >> 5;
    bool tail = (blockIdx.x == 1) && (tid < 64);

    float acc[8][8];
    #pragma unroll
    for (int j = 0; j < 8; j++)
        #pragma unroll
        for (int i = 0; i < 8; i++) acc[j][i] = 0.0f;
    float tacc = 0.0f;

    const float* e2base = g_e2 + (size_t)t * 128 * L2P;

    for (int cb = 0; cb < 8; cb++) {
        __syncthreads();
        for (int i = tid; i < 16 * 259; i += 256) {
            int ci = i / 259, j = i % 259;
            int g = l0 - 1 + j;
            sin_[ci][j] = (g >= 0 && g < L2E) ? e2base[(cb * 16 + ci) * L2P + g] : 0.0f;
        }
        for (int i = tid; i < 64 * 48; i += 256) {
            int co = i / 48, r = i % 48;
            sw[co][r] = ew3[((e * 128 + cgrp * 64 + co) * 128 + cb * 16) * 3 + r];
        }
        __syncthreads();

        #pragma unroll 1
        for (int ci = 0; ci < 16; ci++) {
            // j = 8*lane + i + k, i<=7, k<=2 -> 10 floats, load 12
            float4 a0 = *(const float4*)&sin_[ci][8 * lane];
            float4 a1 = *(const float4*)&sin_[ci][8 * lane + 4];
            float4 a2 = *(const float4*)&sin_[ci][8 * lane + 8];
            float v[12] = {a0.x,a0.y,a0.z,a0.w, a1.x,a1.y,a1.z,a1.w,
                           a2.x,a2.y,a2.z,a2.w};
            #pragma unroll
            for (int j = 0; j < 8; j++) {
                #pragma unroll
                for (int k = 0; k < 3; k++) {
                    float w = sw[wid * 8 + j][ci * 3 + k];
                    #pragma unroll
                    for (int i = 0; i < 8; i++)
                        acc[j][i] += w * v[i + k];
                }
            }
        }
        if (tail) {
            // l = 512: g = 511+k -> j = 256+k
            #pragma unroll 1
            for (int ci = 0; ci < 16; ci++)
                #pragma unroll
                for (int k = 0; k < 3; k++)
                    tacc += sin_[ci][256 + k] * sw[tid][ci * 3 + k];
        }
    }

    #pragma unroll
    for (int j = 0; j < 8; j++) {
        int co = cgrp * 64 + wid * 8 + j;
        float bias = eb3[e * 128 + co];
        int lbase = l0 + 8 * lane;
        float* dst = &g_e3[((size_t)t * 128 + co) * L2P + lbase];
        float4 r0, r1;
        r0.x = fmaxf(acc[j][0] + bias, 0.0f); r0.y = fmaxf(acc[j][1] + bias, 0.0f);
        r0.z = fmaxf(acc[j][2] + bias, 0.0f); r0.w = fmaxf(acc[j][3] + bias, 0.0f);
        r1.x = fmaxf(acc[j][4] + bias, 0.0f); r1.y = fmaxf(acc[j][5] + bias, 0.0f);
        r1.z = fmaxf(acc[j][6] + bias, 0.0f); r1.w = fmaxf(acc[j][7] + bias, 0.0f);
        *(float4*)dst = r0;
        *(float4*)(dst + 4) = r1;
    }
    if (tail) {
        int co = cgrp * 64 + tid;
        g_e3[((size_t)t * 128 + co) * L2P + 512] = fmaxf(tacc + eb3[e * 128 + co], 0.0f);
    }
}

// ---------------- 8) top-2 weighted combine + adaptive max-pool (513 -> 256) ---
__global__ void pool_kernel(float* __restrict__ out) {
    int idx = blockIdx.x * blockDim.x + threadIdx.x;
    if (idx >= B * 128 * 256) return;
    int o  = idx & 255;
    int co = (idx >> 8) & 127;
    int b  = idx >> 15;
    float w0 = g_tw[b * 2 + 0];
    float w1 = g_tw[b * 2 + 1];
    const float* p0 = g_e3 + ((size_t)(b * 2 + 0) * 128 + co) * L2P;
    const float* p1 = g_e3 + ((size_t)(b * 2 + 1) * 128 + co) * L2P;
    int s  = (o * 513) >> 8;
    int en = (o * 513 + 513 + 255) >> 8;
    float m = -INFINITY;
    for (int l = s; l < en; l++)
        m = fmaxf(m, w0 * p0[l] + w1 * p1[l]);
    out[idx] = m;
}

// ---------------- launch --------------------------------------------------------
extern "C" void kernel_launch(void* const* d_in, const int* in_sizes, int n_in,
                              void* d_out, int out_size) {
    const float* x    = (const float*)d_in[0];
    const float* gw1  = (const float*)d_in[1];
    const float* gb1  = (const float*)d_in[2];
    const float* gw2  = (const float*)d_in[3];
    const float* gb2  = (const float*)d_in[4];
    const float* mw1  = (const float*)d_in[5];
    const float* mb1  = (const float*)d_in[6];
    const float* mw2  = (const float*)d_in[7];
    const float* mb2  = (const float*)d_in[8];
    const float* ew1  = (const float*)d_in[9];
    const float* eb1  = (const float*)d_in[10];
    const float* ew2  = (const float*)d_in[11];
    const float* eb2  = (const float*)d_in[12];
    const float* ew3  = (const float*)d_in[13];
    const float* eb3  = (const float*)d_in[14];
    float* out = (float*)d_out;

    fft_kernel<<<B, 512>>>(x);
    gconv1_kernel<<<dim3(2, B), 256>>>(gw1, gb1);
    gconv2_pool_kernel<<<dim3(8, B), 256>>>(gw2, gb2);
    gate_mlp_kernel<<<1, 128>>>(mw1, mb1, mw2, mb2, out, out_size);
    econv1_kernel<<<NTASK, 256>>>(ew1, eb1);
    econv2_kernel<<<dim3(2, 2, NTASK), 256>>>(ew2, eb2);
    econv3_kernel<<<dim3(2, 2, NTASK), 256>>>(ew3, eb3);
    pool_kernel<<<16384, 256>>>(out);
}

// round 7
// speedup vs baseline: 1.4761x; 1.1059x over previous
#include <cuda_runtime.h>
#include <math.h>

#define B 128
#define LSEQ 4096
#define NF 2049          // rfft bins
#define NFP 2052         // padded row stride for g_h1
#define L1E 1025         // expert conv1 out length
#define L1P 1028
#define L2E 513          // expert conv2/conv3 out length
#define L2P 516
#define NTASK 256        // B * TOP_K

// ---------------- scratch (device globals) -------------------------------------
__device__ float g_fft[B * 2 * NF];
__device__ float g_h1 [B * 32 * NFP];
__device__ float g_pooled[B * 64];
__device__ float g_tw[NTASK];
__device__ int   g_ti[NTASK];
__device__ float g_srw[8];
__device__ float g_slg[8];
__device__ float g_e1[NTASK * 64  * L1P];
__device__ float g_e2[NTASK * 128 * L2P];
__device__ float g_e3[NTASK * 128 * L2P];

// ---------------- 1) Hann window + 4096-pt radix-2 FFT + zero accumulators -----
__global__ void fft_kernel(const float* __restrict__ x) {
    __shared__ float re[4096];
    __shared__ float im[4096];
    __shared__ float twr[2048];
    __shared__ float twi[2048];
    int b = blockIdx.x;
    const float* xb = x + b * LSEQ;

    if (threadIdx.x < 64) g_pooled[b * 64 + threadIdx.x] = 0.0f;
    if (b == 0 && threadIdx.x >= 64 && threadIdx.x < 72) {
        g_srw[threadIdx.x - 64] = 0.0f;
        g_slg[threadIdx.x - 64] = 0.0f;
    }

    for (int i = threadIdx.x; i < 2048; i += blockDim.x) {
        float si, sr;
        sincospif(-(float)i * (1.0f / 2048.0f), &si, &sr);
        twr[i] = sr; twi[i] = si;
    }
    for (int i = threadIdx.x; i < 4096; i += blockDim.x) {
        float w = 0.5f * (1.0f - cospif((float)i * (1.0f / 2048.0f)));
        int j = __brev((unsigned)i) >> 20;
        re[j] = xb[i] * w;
        im[j] = 0.0f;
    }
    __syncthreads();

    for (int s = 1; s <= 12; s++) {
        int half = 1 << (s - 1);
        int len  = 1 << s;
        int shft = 12 - s;
        for (int t = threadIdx.x; t < 2048; t += blockDim.x) {
            int g   = t >> (s - 1);
            int pos = t & (half - 1);
            int i0  = g * len + pos;
            int i1  = i0 + half;
            int j   = pos << shft;
            float sr = twr[j], si = twi[j];
            float ar = re[i1], ai = im[i1];
            float tr = ar * sr - ai * si;
            float ti = ar * si + ai * sr;
            float br = re[i0], bi = im[i0];
            re[i1] = br - tr; im[i1] = bi - ti;
            re[i0] = br + tr; im[i0] = bi + ti;
        }
        __syncthreads();
    }
    const float sc = 1.0f / 64.0f;
    for (int f = threadIdx.x; f < NF; f += blockDim.x) {
        g_fft[(b * 2 + 0) * NF + f] = re[f] * sc;
        g_fft[(b * 2 + 1) * NF + f] = im[f] * sc;
    }
}

// ---------------- 2) gate conv1: (2 -> 32), k=5, s=1, p=2, relu ----------------
__global__ void gconv1_kernel(const float* __restrict__ w1, const float* __restrict__ b1) {
    __shared__ __align__(16) float sin_[2][1036];
    __shared__ float sw[32][11];
    __shared__ float sb[32];
    int b  = blockIdx.y;
    int l0 = blockIdx.x * 1024;
    int tid = threadIdx.x;   // 256

    for (int i = tid; i < 2 * 1032; i += 256) {
        int ci = i / 1032, j = i % 1032;
        int g = l0 + j - 2;
        sin_[ci][j] = (g >= 0 && g < NF) ? g_fft[(b * 2 + ci) * NF + g] : 0.0f;
    }
    for (int i = tid; i < 320; i += 256) sw[i / 10][i % 10] = w1[i];
    if (tid < 32) sb[tid] = b1[tid];
    __syncthreads();

    float v[2][8];
    #pragma unroll
    for (int ci = 0; ci < 2; ci++) {
        float4 a = *(const float4*)&sin_[ci][4 * tid];
        float4 c = *(const float4*)&sin_[ci][4 * tid + 4];
        v[ci][0] = a.x; v[ci][1] = a.y; v[ci][2] = a.z; v[ci][3] = a.w;
        v[ci][4] = c.x; v[ci][5] = c.y; v[ci][6] = c.z; v[ci][7] = c.w;
    }

    #pragma unroll 4
    for (int co = 0; co < 32; co++) {
        float acc[4];
        #pragma unroll
        for (int i = 0; i < 4; i++) acc[i] = sb[co];
        #pragma unroll
        for (int ci = 0; ci < 2; ci++)
            #pragma unroll
            for (int k = 0; k < 5; k++) {
                float w = sw[co][ci * 5 + k];
                #pragma unroll
                for (int i = 0; i < 4; i++) acc[i] += w * v[ci][i + k];
            }
        float4 r;
        r.x = fmaxf(acc[0], 0.0f); r.y = fmaxf(acc[1], 0.0f);
        r.z = fmaxf(acc[2], 0.0f); r.w = fmaxf(acc[3], 0.0f);
        *(float4*)&g_h1[(b * 32 + co) * NFP + l0 + 4 * tid] = r;
    }

    if (blockIdx.x == 1 && tid == 0) {
        for (int co = 0; co < 32; co++) {
            float acc = sb[co];
            #pragma unroll
            for (int ci = 0; ci < 2; ci++)
                #pragma unroll
                for (int k = 0; k < 5; k++)
                    acc += sin_[ci][1024 + k] * sw[co][ci * 5 + k];
            g_h1[(b * 32 + co) * NFP + 2048] = fmaxf(acc, 0.0f);
        }
    }
}

// ---------------- 3) gate conv2 (32 -> 64, k5, p2) + mean pool -----------------
__global__ void __launch_bounds__(256, 2)
gconv2_pool_kernel(const float* __restrict__ w2, const float* __restrict__ b2) {
    __shared__ __align__(16) float sin_[16][264];
    __shared__ float sw[64][81];
    int b   = blockIdx.y;
    int l0  = blockIdx.x * 256;
    int tid = threadIdx.x;
    int lane = tid & 31;
    int wid  = tid >> 5;
    bool tail = (blockIdx.x == 7) && (tid < 64);

    float acc[8][8];
    #pragma unroll
    for (int j = 0; j < 8; j++)
        #pragma unroll
        for (int i = 0; i < 8; i++) acc[j][i] = 0.0f;
    float tacc = 0.0f;

    for (int cb = 0; cb < 2; cb++) {
        __syncthreads();
        for (int i = tid; i < 16 * 261; i += 256) {
            int ci = i / 261, j = i % 261;
            int g = l0 + j - 2;
            sin_[ci][j] = (g >= 0 && g < NF) ? g_h1[(b * 32 + cb * 16 + ci) * NFP + g] : 0.0f;
        }
        for (int i = tid; i < 64 * 80; i += 256) {
            int co = i / 80, r = i % 80;
            sw[co][r] = w2[co * 160 + cb * 80 + r];
        }
        __syncthreads();

        #pragma unroll 1
        for (int ci = 0; ci < 16; ci++) {
            float4 a = *(const float4*)&sin_[ci][8 * lane];
            float4 c = *(const float4*)&sin_[ci][8 * lane + 4];
            float4 d = *(const float4*)&sin_[ci][8 * lane + 8];
            float v[12] = {a.x,a.y,a.z,a.w, c.x,c.y,c.z,c.w, d.x,d.y,d.z,d.w};
            #pragma unroll
            for (int j = 0; j < 8; j++) {
                #pragma unroll
                for (int k = 0; k < 5; k++) {
                    float w = sw[wid * 8 + j][ci * 5 + k];
                    #pragma unroll
                    for (int i = 0; i < 8; i++)
                        acc[j][i] += w * v[i + k];
                }
            }
        }
        if (tail) {
            #pragma unroll 1
            for (int ci = 0; ci < 16; ci++)
                #pragma unroll
                for (int k = 0; k < 5; k++)
                    tacc += sin_[ci][256 + k] * sw[tid][ci * 5 + k];
        }
    }

    #pragma unroll
    for (int j = 0; j < 8; j++) {
        int co = wid * 8 + j;
        float bias = b2[co];
        float p = 0.0f;
        #pragma unroll
        for (int i = 0; i < 8; i++)
            p += fmaxf(acc[j][i] + bias, 0.0f);
        #pragma unroll
        for (int off = 16; off; off >>= 1)
            p += __shfl_down_sync(0xffffffffu, p, off, 32);
        if (lane == 0) atomicAdd(&g_pooled[b * 64 + co], p);
    }
    if (tail)
        atomicAdd(&g_pooled[b * 64 + tid], fmaxf(tacc + b2[tid], 0.0f));
}

// ---------------- 4) router MLP + softmax + top2 + aux accumulation ------------
// grid 128 (one block per batch row), 128 threads (one per hidden unit).
__global__ void gate_mlp_kernel(const float* __restrict__ w1, const float* __restrict__ b1,
                                const float* __restrict__ w2, const float* __restrict__ b2) {
    __shared__ float sp[64];
    __shared__ float sh[128];
    __shared__ float slg[8];
    int b = blockIdx.x;
    int j = threadIdx.x;

    if (j < 64) sp[j] = g_pooled[b * 64 + j] * (1.0f / 2049.0f);
    __syncthreads();

    // hidden unit j
    {
        const float* wr = w1 + j * 64;
        float h0 = 0.f, h1 = 0.f, h2 = 0.f, h3 = 0.f;
        #pragma unroll
        for (int i = 0; i < 64; i += 4) {
            h0 += sp[i + 0] * wr[i + 0];
            h1 += sp[i + 1] * wr[i + 1];
            h2 += sp[i + 2] * wr[i + 2];
            h3 += sp[i + 3] * wr[i + 3];
        }
        sh[j] = fmaxf((h0 + h1) + (h2 + h3) + b1[j], 0.0f);
    }
    __syncthreads();

    if (j < 8) {
        float acc = b2[j];
        const float* wr = w2 + j * 128;
        #pragma unroll 8
        for (int i = 0; i < 128; i++) acc += sh[i] * wr[i];
        slg[j] = acc;
    }
    __syncthreads();

    if (j == 0) {
        float lg[8];
        #pragma unroll
        for (int e = 0; e < 8; e++) lg[e] = slg[e];
        float m = lg[0];
        #pragma unroll
        for (int e = 1; e < 8; e++) m = fmaxf(m, lg[e]);
        float rw[8], s = 0.0f;
        #pragma unroll
        for (int e = 0; e < 8; e++) { rw[e] = expf(lg[e] - m); s += rw[e]; }
        float invs = 1.0f / s;
        #pragma unroll
        for (int e = 0; e < 8; e++) rw[e] *= invs;

        int i0 = 0;
        #pragma unroll
        for (int e = 1; e < 8; e++) if (rw[e] > rw[i0]) i0 = e;
        int i1 = (i0 == 0) ? 1 : 0;
        #pragma unroll
        for (int e = 0; e < 8; e++) if (e != i1 && e != i0 && rw[e] > rw[i1]) i1 = e;

        float t0 = rw[i0], t1 = rw[i1];
        float tn = 1.0f / (t0 + t1);
        g_ti[b * 2 + 0] = i0; g_ti[b * 2 + 1] = i1;
        g_tw[b * 2 + 0] = t0 * tn; g_tw[b * 2 + 1] = t1 * tn;

        #pragma unroll
        for (int e = 0; e < 8; e++) {
            atomicAdd(&g_srw[e], rw[e]);
            atomicAdd(&g_slg[e], lg[e]);
        }
    }
}

// ---------------- 5) expert conv1: (2 -> 64), k=7, s=2, p=3, relu --------------
__global__ void econv1_kernel(const float* __restrict__ ew1, const float* __restrict__ eb1) {
    __shared__ __align__(16) float sin_[2][2056];
    __shared__ float sw[64][16];
    __shared__ float sb[64];
    int t = blockIdx.x;
    int b = t >> 1;
    int e = g_ti[t];
    int tid = threadIdx.x;   // 256

    for (int i = tid; i < 2 * 2056; i += 256) {
        int ci = i / 2056, j = i % 2056;
        int g = j - 3;
        sin_[ci][j] = (g >= 0 && g < NF) ? g_fft[(b * 2 + ci) * NF + g] : 0.0f;
    }
    for (int i = tid; i < 64 * 14; i += 256) sw[i / 14][i % 14] = ew1[e * 896 + i];
    if (tid < 64) sb[tid] = eb1[e * 64 + tid];
    __syncthreads();

    float v[2][16];
    #pragma unroll
    for (int ci = 0; ci < 2; ci++) {
        float4 a = *(const float4*)&sin_[ci][8 * tid];
        float4 c = *(const float4*)&sin_[ci][8 * tid + 4];
        float4 d = *(const float4*)&sin_[ci][8 * tid + 8];
        float4 f = *(const float4*)&sin_[ci][8 * tid + 12];
        v[ci][0]=a.x;  v[ci][1]=a.y;  v[ci][2]=a.z;  v[ci][3]=a.w;
        v[ci][4]=c.x;  v[ci][5]=c.y;  v[ci][6]=c.z;  v[ci][7]=c.w;
        v[ci][8]=d.x;  v[ci][9]=d.y;  v[ci][10]=d.z; v[ci][11]=d.w;
        v[ci][12]=f.x; v[ci][13]=f.y; v[ci][14]=f.z; v[ci][15]=f.w;
    }

    #pragma unroll 2
    for (int co = 0; co < 64; co++) {
        float acc[4];
        #pragma unroll
        for (int i = 0; i < 4; i++) acc[i] = sb[co];
        #pragma unroll
        for (int ci = 0; ci < 2; ci++)
            #pragma unroll
            for (int k = 0; k < 7; k++) {
                float w = sw[co][ci * 7 + k];
                #pragma unroll
                for (int i = 0; i < 4; i++) acc[i] += w * v[ci][2 * i + k];
            }
        float4 r;
        r.x = fmaxf(acc[0], 0.0f); r.y = fmaxf(acc[1], 0.0f);
        r.z = fmaxf(acc[2], 0.0f); r.w = fmaxf(acc[3], 0.0f);
        *(float4*)&g_e1[((size_t)t * 64 + co) * L1P + 4 * tid] = r;
    }

    if (tid < 64) {
        int co = tid;
        float acc = sb[co];
        #pragma unroll
        for (int ci = 0; ci < 2; ci++)
            #pragma unroll
            for (int k = 0; k < 7; k++)
                acc += sin_[ci][2048 + k] * sw[co][ci * 7 + k];
        g_e1[((size_t)t * 64 + co) * L1P + 1024] = fmaxf(acc, 0.0f);
    }
}

// ---------------- 6) expert conv2: (64 -> 128), k=5, s=2, p=2, relu ------------
__global__ void __launch_bounds__(256, 2)
econv2_kernel(const float* __restrict__ ew2, const float* __restrict__ eb2) {
    __shared__ __align__(16) float sin_[8][520];
    __shared__ float sw[64][41];
    int t  = blockIdx.z;
    int e  = g_ti[t];
    int l0 = blockIdx.x * 256;
    int cgrp = blockIdx.y;             // co base = cgrp*64
    int tid = threadIdx.x;
    int lane = tid & 31;
    int wid  = tid >> 5;
    bool tail = (blockIdx.x == 1) && (tid < 64);

    float acc[8][8];
    #pragma unroll
    for (int j = 0; j < 8; j++)
        #pragma unroll
        for (int i = 0; i < 8; i++) acc[j][i] = 0.0f;
    float tacc = 0.0f;

    const float* e1base = g_e1 + (size_t)t * 64 * L1P;

    for (int cb = 0; cb < 8; cb++) {
        __syncthreads();
        for (int i = tid; i < 8 * 517; i += 256) {
            int ci = i / 517, j = i % 517;
            int g = 2 * l0 - 2 + j;
            sin_[ci][j] = (g >= 0 && g < L1E) ? e1base[(cb * 8 + ci) * L1P + g] : 0.0f;
        }
        for (int i = tid; i < 64 * 40; i += 256) {
            int co = i / 40, r = i % 40;
            sw[co][r] = ew2[((e * 128 + cgrp * 64 + co) * 64 + cb * 8) * 5 + r];
        }
        __syncthreads();

        #pragma unroll 1
        for (int ci = 0; ci < 8; ci++) {
            float4 a0 = *(const float4*)&sin_[ci][16 * lane];
            float4 a1 = *(const float4*)&sin_[ci][16 * lane + 4];
            float4 a2 = *(const float4*)&sin_[ci][16 * lane + 8];
            float4 a3 = *(const float4*)&sin_[ci][16 * lane + 12];
            float4 a4 = *(const float4*)&sin_[ci][16 * lane + 16];
            float v[20] = {a0.x,a0.y,a0.z,a0.w, a1.x,a1.y,a1.z,a1.w,
                           a2.x,a2.y,a2.z,a2.w, a3.x,a3.y,a3.z,a3.w,
                           a4.x,a4.y,a4.z,a4.w};
            #pragma unroll
            for (int j = 0; j < 8; j++) {
                #pragma unroll
                for (int k = 0; k < 5; k++) {
                    float w = sw[wid * 8 + j][ci * 5 + k];
                    #pragma unroll
                    for (int i = 0; i < 8; i++)
                        acc[j][i] += w * v[2 * i + k];
                }
            }
        }
        if (tail) {
            #pragma unroll 1
            for (int ci = 0; ci < 8; ci++)
                #pragma unroll
                for (int k = 0; k < 5; k++)
                    tacc += sin_[ci][512 + k] * sw[tid][ci * 5 + k];
        }
    }

    #pragma unroll
    for (int j = 0; j < 8; j++) {
        int co = cgrp * 64 + wid * 8 + j;
        float bias = eb2[e * 128 + co];
        int lbase = l0 + 8 * lane;
        float* dst = &g_e2[((size_t)t * 128 + co) * L2P + lbase];
        float4 r0, r1;
        r0.x = fmaxf(acc[j][0] + bias, 0.0f); r0.y = fmaxf(acc[j][1] + bias, 0.0f);
        r0.z = fmaxf(acc[j][2] + bias, 0.0f); r0.w = fmaxf(acc[j][3] + bias, 0.0f);
        r1.x = fmaxf(acc[j][4] + bias, 0.0f); r1.y = fmaxf(acc[j][5] + bias, 0.0f);
        r1.z = fmaxf(acc[j][6] + bias, 0.0f); r1.w = fmaxf(acc[j][7] + bias, 0.0f);
        *(float4*)dst = r0;
        *(float4*)(dst + 4) = r1;
    }
    if (tail) {
        int co = cgrp * 64 + tid;
        g_e2[((size_t)t * 128 + co) * L2P + 512] = fmaxf(tacc + eb2[e * 128 + co], 0.0f);
    }
}

// ---------------- 7) expert conv3: (128 -> 128), k=3, s=1, p=1, relu -----------
__global__ void __launch_bounds__(256, 2)
econv3_kernel(const float* __restrict__ ew3, const float* __restrict__ eb3) {
    __shared__ __align__(16) float sin_[16][260];
    __shared__ float sw[64][49];
    int t  = blockIdx.z;
    int e  = g_ti[t];
    int l0 = blockIdx.x * 256;
    int cgrp = blockIdx.y;
    int tid = threadIdx.x;
    int lane = tid & 31;
    int wid  = tid >> 5;
    bool tail = (blockIdx.x == 1) && (tid < 64);

    float acc[8][8];
    #pragma unroll
    for (int j = 0; j < 8; j++)
        #pragma unroll
        for (int i = 0; i < 8; i++) acc[j][i] = 0.0f;
    float tacc = 0.0f;

    const float* e2base = g_e2 + (size_t)t * 128 * L2P;

    for (int cb = 0; cb < 8; cb++) {
        __syncthreads();
        for (int i = tid; i < 16 * 259; i += 256) {
            int ci = i / 259, j = i % 259;
            int g = l0 - 1 + j;
            sin_[ci][j] = (g >= 0 && g < L2E) ? e2base[(cb * 16 + ci) * L2P + g] : 0.0f;
        }
        for (int i = tid; i < 64 * 48; i += 256) {
            int co = i / 48, r = i % 48;
            sw[co][r] = ew3[((e * 128 + cgrp * 64 + co) * 128 + cb * 16) * 3 + r];
        }
        __syncthreads();

        #pragma unroll 1
        for (int ci = 0; ci < 16; ci++) {
            float4 a0 = *(const float4*)&sin_[ci][8 * lane];
            float4 a1 = *(const float4*)&sin_[ci][8 * lane + 4];
            float4 a2 = *(const float4*)&sin_[ci][8 * lane + 8];
            float v[12] = {a0.x,a0.y,a0.z,a0.w, a1.x,a1.y,a1.z,a1.w,
                           a2.x,a2.y,a2.z,a2.w};
            #pragma unroll
            for (int j = 0; j < 8; j++) {
                #pragma unroll
                for (int k = 0; k < 3; k++) {
                    float w = sw[wid * 8 + j][ci * 3 + k];
                    #pragma unroll
                    for (int i = 0; i < 8; i++)
                        acc[j][i] += w * v[i + k];
                }
            }
        }
        if (tail) {
            #pragma unroll 1
            for (int ci = 0; ci < 16; ci++)
                #pragma unroll
                for (int k = 0; k < 3; k++)
                    tacc += sin_[ci][256 + k] * sw[tid][ci * 3 + k];
        }
    }

    #pragma unroll
    for (int j = 0; j < 8; j++) {
        int co = cgrp * 64 + wid * 8 + j;
        float bias = eb3[e * 128 + co];
        int lbase = l0 + 8 * lane;
        float* dst = &g_e3[((size_t)t * 128 + co) * L2P + lbase];
        float4 r0, r1;
        r0.x = fmaxf(acc[j][0] + bias, 0.0f); r0.y = fmaxf(acc[j][1] + bias, 0.0f);
        r0.z = fmaxf(acc[j][2] + bias, 0.0f); r0.w = fmaxf(acc[j][3] + bias, 0.0f);
        r1.x = fmaxf(acc[j][4] + bias, 0.0f); r1.y = fmaxf(acc[j][5] + bias, 0.0f);
        r1.z = fmaxf(acc[j][6] + bias, 0.0f); r1.w = fmaxf(acc[j][7] + bias, 0.0f);
        *(float4*)dst = r0;
        *(float4*)(dst + 4) = r1;
    }
    if (tail) {
        int co = cgrp * 64 + tid;
        g_e3[((size_t)t * 128 + co) * L2P + 512] = fmaxf(tacc + eb3[e * 128 + co], 0.0f);
    }
}

// ---------------- 8) top-2 combine + adaptive max-pool + aux finalize ----------
__global__ void pool_kernel(float* __restrict__ out, int out_size) {
    int idx = blockIdx.x * blockDim.x + threadIdx.x;
    if (idx == 0) {
        float aux = 0.0f;
        #pragma unroll
        for (int e = 0; e < 8; e++)
            aux += (g_srw[e] * (1.0f / 128.0f)) * (g_slg[e] * (1.0f / 128.0f));
        out[out_size - 1] = 0.01f * 8.0f * aux;
    }
    if (idx >= B * 128 * 256) return;
    int o  = idx & 255;
    int co = (idx >> 8) & 127;
    int b  = idx >> 15;
    float w0 = g_tw[b * 2 + 0];
    float w1 = g_tw[b * 2 + 1];
    const float* p0 = g_e3 + ((size_t)(b * 2 + 0) * 128 + co) * L2P;
    const float* p1 = g_e3 + ((size_t)(b * 2 + 1) * 128 + co) * L2P;
    int s  = (o * 513) >> 8;
    int en = (o * 513 + 513 + 255) >> 8;
    float m = -INFINITY;
    for (int l = s; l < en; l++)
        m = fmaxf(m, w0 * p0[l] + w1 * p1[l]);
    out[idx] = m;
}

// ---------------- launch --------------------------------------------------------
extern "C" void kernel_launch(void* const* d_in, const int* in_sizes, int n_in,
                              void* d_out, int out_size) {
    const float* x    = (const float*)d_in[0];
    const float* gw1  = (const float*)d_in[1];
    const float* gb1  = (const float*)d_in[2];
    const float* gw2  = (const float*)d_in[3];
    const float* gb2  = (const float*)d_in[4];
    const float* mw1  = (const float*)d_in[5];
    const float* mb1  = (const float*)d_in[6];
    const float* mw2  = (const float*)d_in[7];
    const float* mb2  = (const float*)d_in[8];
    const float* ew1  = (const float*)d_in[9];
    const float* eb1  = (const float*)d_in[10];
    const float* ew2  = (const float*)d_in[11];
    const float* eb2  = (const float*)d_in[12];
    const float* ew3  = (const float*)d_in[13];
    const float* eb3  = (const float*)d_in[14];
    float* out = (float*)d_out;

    fft_kernel<<<B, 512>>>(x);
    gconv1_kernel<<<dim3(2, B), 256>>>(gw1, gb1);
    gconv2_pool_kernel<<<dim3(8, B), 256>>>(gw2, gb2);
    gate_mlp_kernel<<<B, 128>>>(mw1, mb1, mw2, mb2);
    econv1_kernel<<<NTASK, 256>>>(ew1, eb1);
    econv2_kernel<<<dim3(2, 2, NTASK), 256>>>(ew2, eb2);
    econv3_kernel<<<dim3(2, 2, NTASK), 256>>>(ew3, eb3);
    pool_kernel<<<16384, 256>>>(out, out_size);
}

// round 8
// speedup vs baseline: 1.5818x; 1.0716x over previous
#include <cuda_runtime.h>
#include <math.h>
#include <stdint.h>

#define B 128
#define LSEQ 4096
#define NF 2049          // rfft bins
#define NFP 2052         // padded row stride for g_h1
#define L1E 1025         // expert conv1 out length
#define L1P 1028
#define L2E 513          // expert conv2/conv3 out length
#define L2P 516
#define NTASK 256        // B * TOP_K

// ---------------- cp.async helpers --------------------------------------------
__device__ __forceinline__ uint32_t s2u(const void* p) {
    return (uint32_t)__cvta_generic_to_shared(p);
}
__device__ __forceinline__ void cp4z(uint32_t saddr, const void* g, bool pred) {
    int sz = pred ? 4 : 0;
    asm volatile("cp.async.ca.shared.global [%0], [%1], 4, %2;"
                 :: "r"(saddr), "l"(g), "r"(sz));
}
__device__ __forceinline__ void cp_commit() {
    asm volatile("cp.async.commit_group;");
}
template <int N>
__device__ __forceinline__ void cp_wait() {
    asm volatile("cp.async.wait_group %0;" :: "n"(N));
}

// ---------------- scratch (device globals) -------------------------------------
__device__ float g_fft[B * 2 * NF];
__device__ float g_h1 [B * 32 * NFP];
__device__ float g_pooled[B * 64];
__device__ float g_tw[NTASK];
__device__ int   g_ti[NTASK];
__device__ float g_srw[8];
__device__ float g_slg[8];
__device__ float g_e1[NTASK * 64  * L1P];
__device__ float g_e2[NTASK * 128 * L2P];
__device__ float g_e3[NTASK * 128 * L2P];

// ---------------- 1) Hann window + 4096-pt radix-2 FFT + zero accumulators -----
__global__ void fft_kernel(const float* __restrict__ x) {
    __shared__ float re[4096];
    __shared__ float im[4096];
    __shared__ float twr[2048];
    __shared__ float twi[2048];
    int b = blockIdx.x;
    const float* xb = x + b * LSEQ;

    if (threadIdx.x < 64) g_pooled[b * 64 + threadIdx.x] = 0.0f;
    if (b == 0 && threadIdx.x >= 64 && threadIdx.x < 72) {
        g_srw[threadIdx.x - 64] = 0.0f;
        g_slg[threadIdx.x - 64] = 0.0f;
    }

    for (int i = threadIdx.x; i < 2048; i += blockDim.x) {
        float si, sr;
        sincospif(-(float)i * (1.0f / 2048.0f), &si, &sr);
        twr[i] = sr; twi[i] = si;
    }
    for (int i = threadIdx.x; i < 4096; i += blockDim.x) {
        float w = 0.5f * (1.0f - cospif((float)i * (1.0f / 2048.0f)));
        int j = __brev((unsigned)i) >> 20;
        re[j] = xb[i] * w;
        im[j] = 0.0f;
    }
    __syncthreads();

    for (int s = 1; s <= 12; s++) {
        int half = 1 << (s - 1);
        int len  = 1 << s;
        int shft = 12 - s;
        for (int t = threadIdx.x; t < 2048; t += blockDim.x) {
            int g   = t >> (s - 1);
            int pos = t & (half - 1);
            int i0  = g * len + pos;
            int i1  = i0 + half;
            int j   = pos << shft;
            float sr = twr[j], si = twi[j];
            float ar = re[i1], ai = im[i1];
            float tr = ar * sr - ai * si;
            float ti = ar * si + ai * sr;
            float br = re[i0], bi = im[i0];
            re[i1] = br - tr; im[i1] = bi - ti;
            re[i0] = br + tr; im[i0] = bi + ti;
        }
        __syncthreads();
    }
    const float sc = 1.0f / 64.0f;
    for (int f = threadIdx.x; f < NF; f += blockDim.x) {
        g_fft[(b * 2 + 0) * NF + f] = re[f] * sc;
        g_fft[(b * 2 + 1) * NF + f] = im[f] * sc;
    }
}

// ---------------- 2) gate conv1: (2 -> 32), k=5, s=1, p=2, relu ----------------
__global__ void gconv1_kernel(const float* __restrict__ w1, const float* __restrict__ b1) {
    __shared__ __align__(16) float sin_[2][1036];
    __shared__ float sw[32][11];
    __shared__ float sb[32];
    int b  = blockIdx.y;
    int l0 = blockIdx.x * 1024;
    int tid = threadIdx.x;   // 256

    for (int i = tid; i < 2 * 1032; i += 256) {
        int ci = i / 1032, j = i % 1032;
        int g = l0 + j - 2;
        sin_[ci][j] = (g >= 0 && g < NF) ? g_fft[(b * 2 + ci) * NF + g] : 0.0f;
    }
    for (int i = tid; i < 320; i += 256) sw[i / 10][i % 10] = w1[i];
    if (tid < 32) sb[tid] = b1[tid];
    __syncthreads();

    float v[2][8];
    #pragma unroll
    for (int ci = 0; ci < 2; ci++) {
        float4 a = *(const float4*)&sin_[ci][4 * tid];
        float4 c = *(const float4*)&sin_[ci][4 * tid + 4];
        v[ci][0] = a.x; v[ci][1] = a.y; v[ci][2] = a.z; v[ci][3] = a.w;
        v[ci][4] = c.x; v[ci][5] = c.y; v[ci][6] = c.z; v[ci][7] = c.w;
    }

    #pragma unroll 4
    for (int co = 0; co < 32; co++) {
        float acc[4];
        #pragma unroll
        for (int i = 0; i < 4; i++) acc[i] = sb[co];
        #pragma unroll
        for (int ci = 0; ci < 2; ci++)
            #pragma unroll
            for (int k = 0; k < 5; k++) {
                float w = sw[co][ci * 5 + k];
                #pragma unroll
                for (int i = 0; i < 4; i++) acc[i] += w * v[ci][i + k];
            }
        float4 r;
        r.x = fmaxf(acc[0], 0.0f); r.y = fmaxf(acc[1], 0.0f);
        r.z = fmaxf(acc[2], 0.0f); r.w = fmaxf(acc[3], 0.0f);
        *(float4*)&g_h1[(b * 32 + co) * NFP + l0 + 4 * tid] = r;
    }

    if (blockIdx.x == 1 && tid == 0) {
        for (int co = 0; co < 32; co++) {
            float acc = sb[co];
            #pragma unroll
            for (int ci = 0; ci < 2; ci++)
                #pragma unroll
                for (int k = 0; k < 5; k++)
                    acc += sin_[ci][1024 + k] * sw[co][ci * 5 + k];
            g_h1[(b * 32 + co) * NFP + 2048] = fmaxf(acc, 0.0f);
        }
    }
}

// ---------------- 3) gate conv2 (32 -> 64, k5, p2) + mean pool -----------------
__global__ void __launch_bounds__(256, 2)
gconv2_pool_kernel(const float* __restrict__ w2, const float* __restrict__ b2) {
    __shared__ __align__(16) float sin_[16][264];
    __shared__ float sw[64][81];
    int b   = blockIdx.y;
    int l0  = blockIdx.x * 256;
    int tid = threadIdx.x;
    int lane = tid & 31;
    int wid  = tid >> 5;
    bool tail = (blockIdx.x == 7) && (tid < 64);

    float acc[8][8];
    #pragma unroll
    for (int j = 0; j < 8; j++)
        #pragma unroll
        for (int i = 0; i < 8; i++) acc[j][i] = 0.0f;
    float tacc = 0.0f;

    for (int cb = 0; cb < 2; cb++) {
        __syncthreads();
        for (int i = tid; i < 16 * 261; i += 256) {
            int ci = i / 261, j = i % 261;
            int g = l0 + j - 2;
            sin_[ci][j] = (g >= 0 && g < NF) ? g_h1[(b * 32 + cb * 16 + ci) * NFP + g] : 0.0f;
        }
        for (int i = tid; i < 64 * 80; i += 256) {
            int co = i / 80, r = i % 80;
            sw[co][r] = w2[co * 160 + cb * 80 + r];
        }
        __syncthreads();

        #pragma unroll 1
        for (int ci = 0; ci < 16; ci++) {
            float4 a = *(const float4*)&sin_[ci][8 * lane];
            float4 c = *(const float4*)&sin_[ci][8 * lane + 4];
            float4 d = *(const float4*)&sin_[ci][8 * lane + 8];
            float v[12] = {a.x,a.y,a.z,a.w, c.x,c.y,c.z,c.w, d.x,d.y,d.z,d.w};
            #pragma unroll
            for (int j = 0; j < 8; j++) {
                #pragma unroll
                for (int k = 0; k < 5; k++) {
                    float w = sw[wid * 8 + j][ci * 5 + k];
                    #pragma unroll
                    for (int i = 0; i < 8; i++)
                        acc[j][i] += w * v[i + k];
                }
            }
        }
        if (tail) {
            #pragma unroll 1
            for (int ci = 0; ci < 16; ci++)
                #pragma unroll
                for (int k = 0; k < 5; k++)
                    tacc += sin_[ci][256 + k] * sw[tid][ci * 5 + k];
        }
    }

    #pragma unroll
    for (int j = 0; j < 8; j++) {
        int co = wid * 8 + j;
        float bias = b2[co];
        float p = 0.0f;
        #pragma unroll
        for (int i = 0; i < 8; i++)
            p += fmaxf(acc[j][i] + bias, 0.0f);
        #pragma unroll
        for (int off = 16; off; off >>= 1)
            p += __shfl_down_sync(0xffffffffu, p, off, 32);
        if (lane == 0) atomicAdd(&g_pooled[b * 64 + co], p);
    }
    if (tail)
        atomicAdd(&g_pooled[b * 64 + tid], fmaxf(tacc + b2[tid], 0.0f));
}

// ---------------- 4) router MLP + softmax + top2 + aux accumulation ------------
__global__ void gate_mlp_kernel(const float* __restrict__ w1, const float* __restrict__ b1,
                                const float* __restrict__ w2, const float* __restrict__ b2) {
    __shared__ float sp[64];
    __shared__ float sh[128];
    __shared__ float slg[8];
    int b = blockIdx.x;
    int j = threadIdx.x;

    if (j < 64) sp[j] = g_pooled[b * 64 + j] * (1.0f / 2049.0f);
    __syncthreads();

    {
        const float* wr = w1 + j * 64;
        float h0 = 0.f, h1 = 0.f, h2 = 0.f, h3 = 0.f;
        #pragma unroll
        for (int i = 0; i < 64; i += 4) {
            h0 += sp[i + 0] * wr[i + 0];
            h1 += sp[i + 1] * wr[i + 1];
            h2 += sp[i + 2] * wr[i + 2];
            h3 += sp[i + 3] * wr[i + 3];
        }
        sh[j] = fmaxf((h0 + h1) + (h2 + h3) + b1[j], 0.0f);
    }
    __syncthreads();

    if (j < 8) {
        float acc = b2[j];
        const float* wr = w2 + j * 128;
        #pragma unroll 8
        for (int i = 0; i < 128; i++) acc += sh[i] * wr[i];
        slg[j] = acc;
    }
    __syncthreads();

    if (j == 0) {
        float lg[8];
        #pragma unroll
        for (int e = 0; e < 8; e++) lg[e] = slg[e];
        float m = lg[0];
        #pragma unroll
        for (int e = 1; e < 8; e++) m = fmaxf(m, lg[e]);
        float rw[8], s = 0.0f;
        #pragma unroll
        for (int e = 0; e < 8; e++) { rw[e] = expf(lg[e] - m); s += rw[e]; }
        float invs = 1.0f / s;
        #pragma unroll
        for (int e = 0; e < 8; e++) rw[e] *= invs;

        int i0 = 0;
        #pragma unroll
        for (int e = 1; e < 8; e++) if (rw[e] > rw[i0]) i0 = e;
        int i1 = (i0 == 0) ? 1 : 0;
        #pragma unroll
        for (int e = 0; e < 8; e++) if (e != i1 && e != i0 && rw[e] > rw[i1]) i1 = e;

        float t0 = rw[i0], t1 = rw[i1];
        float tn = 1.0f / (t0 + t1);
        g_ti[b * 2 + 0] = i0; g_ti[b * 2 + 1] = i1;
        g_tw[b * 2 + 0] = t0 * tn; g_tw[b * 2 + 1] = t1 * tn;

        #pragma unroll
        for (int e = 0; e < 8; e++) {
            atomicAdd(&g_srw[e], rw[e]);
            atomicAdd(&g_slg[e], lg[e]);
        }
    }
}

// ---------------- 5) expert conv1: (2 -> 64), k=7, s=2, p=3, relu --------------
__global__ void econv1_kernel(const float* __restrict__ ew1, const float* __restrict__ eb1) {
    __shared__ __align__(16) float sin_[2][2056];
    __shared__ float sw[64][16];
    __shared__ float sb[64];
    int t = blockIdx.x;
    int b = t >> 1;
    int e = g_ti[t];
    int tid = threadIdx.x;   // 256

    for (int i = tid; i < 2 * 2056; i += 256) {
        int ci = i / 2056, j = i % 2056;
        int g = j - 3;
        sin_[ci][j] = (g >= 0 && g < NF) ? g_fft[(b * 2 + ci) * NF + g] : 0.0f;
    }
    for (int i = tid; i < 64 * 14; i += 256) sw[i / 14][i % 14] = ew1[e * 896 + i];
    if (tid < 64) sb[tid] = eb1[e * 64 + tid];
    __syncthreads();

    float v[2][16];
    #pragma unroll
    for (int ci = 0; ci < 2; ci++) {
        float4 a = *(const float4*)&sin_[ci][8 * tid];
        float4 c = *(const float4*)&sin_[ci][8 * tid + 4];
        float4 d = *(const float4*)&sin_[ci][8 * tid + 8];
        float4 f = *(const float4*)&sin_[ci][8 * tid + 12];
        v[ci][0]=a.x;  v[ci][1]=a.y;  v[ci][2]=a.z;  v[ci][3]=a.w;
        v[ci][4]=c.x;  v[ci][5]=c.y;  v[ci][6]=c.z;  v[ci][7]=c.w;
        v[ci][8]=d.x;  v[ci][9]=d.y;  v[ci][10]=d.z; v[ci][11]=d.w;
        v[ci][12]=f.x; v[ci][13]=f.y; v[ci][14]=f.z; v[ci][15]=f.w;
    }

    #pragma unroll 2
    for (int co = 0; co < 64; co++) {
        float acc[4];
        #pragma unroll
        for (int i = 0; i < 4; i++) acc[i] = sb[co];
        #pragma unroll
        for (int ci = 0; ci < 2; ci++)
            #pragma unroll
            for (int k = 0; k < 7; k++) {
                float w = sw[co][ci * 7 + k];
                #pragma unroll
                for (int i = 0; i < 4; i++) acc[i] += w * v[ci][2 * i + k];
            }
        float4 r;
        r.x = fmaxf(acc[0], 0.0f); r.y = fmaxf(acc[1], 0.0f);
        r.z = fmaxf(acc[2], 0.0f); r.w = fmaxf(acc[3], 0.0f);
        *(float4*)&g_e1[((size_t)t * 64 + co) * L1P + 4 * tid] = r;
    }

    if (tid < 64) {
        int co = tid;
        float acc = sb[co];
        #pragma unroll
        for (int ci = 0; ci < 2; ci++)
            #pragma unroll
            for (int k = 0; k < 7; k++)
                acc += sin_[ci][2048 + k] * sw[co][ci * 7 + k];
        g_e1[((size_t)t * 64 + co) * L1P + 1024] = fmaxf(acc, 0.0f);
    }
}

// ---------------- 6) expert conv2: (64 -> 128), k=5, s=2, p=2, relu ------------
// cp.async double-buffered over 8 ci-chunks. Dynamic smem:
//   sin: 2 x [8][520], sw: 2 x [64][40]  -> 53760 bytes
#define E2_SIN_STRIDE (8 * 520)
#define E2_SW_STRIDE  (64 * 40)
#define E2_SMEM ((2 * E2_SIN_STRIDE + 2 * E2_SW_STRIDE) * 4)
__global__ void __launch_bounds__(256, 2)
econv2_kernel(const float* __restrict__ ew2, const float* __restrict__ eb2) {
    extern __shared__ __align__(16) float dyn2[];
    float* sinb = dyn2;                        // 2 buffers of [8][520]
    float* swb  = dyn2 + 2 * E2_SIN_STRIDE;    // 2 buffers of [64][40]
    int t  = blockIdx.z;
    int e  = g_ti[t];
    int l0 = blockIdx.x * 256;
    int cgrp = blockIdx.y;             // co base = cgrp*64
    int tid = threadIdx.x;
    int lane = tid & 31;
    int wid  = tid >> 5;
    bool tail = (blockIdx.x == 1) && (tid < 64);

    const float* e1base = g_e1 + (size_t)t * 64 * L1P;
    const float* wbase  = ew2 + (size_t)(e * 128 + cgrp * 64) * 320;

    auto prefetch = [&](int p, int cb) {
        float* s = sinb + p * E2_SIN_STRIDE;
        for (int i = tid; i < 8 * 517; i += 256) {
            int ci = i / 517, j = i % 517;
            int g = 2 * l0 - 2 + j;
            bool ok = (g >= 0 && g < L1E);
            cp4z(s2u(&s[ci * 520 + j]),
                 e1base + (size_t)(cb * 8 + ci) * L1P + (ok ? g : 0), ok);
        }
        float* w = swb + p * E2_SW_STRIDE;
        for (int i = tid; i < 64 * 40; i += 256) {
            int co = i / 40, r = i % 40;
            cp4z(s2u(&w[co * 40 + r]), wbase + (size_t)co * 320 + cb * 40 + r, true);
        }
    };

    float acc[8][8];
    #pragma unroll
    for (int j = 0; j < 8; j++)
        #pragma unroll
        for (int i = 0; i < 8; i++) acc[j][i] = 0.0f;
    float tacc = 0.0f;

    prefetch(0, 0); cp_commit();
    prefetch(1, 1); cp_commit();

    for (int cb = 0; cb < 8; cb++) {
        int p = cb & 1;
        cp_wait<1>();
        __syncthreads();
        const float* s = sinb + p * E2_SIN_STRIDE;
        const float* w = swb + p * E2_SW_STRIDE;

        #pragma unroll 1
        for (int ci = 0; ci < 8; ci++) {
            const float* row = s + ci * 520 + 16 * lane;
            float4 a0 = *(const float4*)(row);
            float4 a1 = *(const float4*)(row + 4);
            float4 a2 = *(const float4*)(row + 8);
            float4 a3 = *(const float4*)(row + 12);
            float4 a4 = *(const float4*)(row + 16);
            float v[20] = {a0.x,a0.y,a0.z,a0.w, a1.x,a1.y,a1.z,a1.w,
                           a2.x,a2.y,a2.z,a2.w, a3.x,a3.y,a3.z,a3.w,
                           a4.x,a4.y,a4.z,a4.w};
            #pragma unroll
            for (int j = 0; j < 8; j++) {
                #pragma unroll
                for (int k = 0; k < 5; k++) {
                    float wv = w[(wid * 8 + j) * 40 + ci * 5 + k];
                    #pragma unroll
                    for (int i = 0; i < 8; i++)
                        acc[j][i] += wv * v[2 * i + k];
                }
            }
        }
        if (tail) {
            #pragma unroll 1
            for (int ci = 0; ci < 8; ci++)
                #pragma unroll
                for (int k = 0; k < 5; k++)
                    tacc += s[ci * 520 + 512 + k] * w[tid * 40 + ci * 5 + k];
        }
        __syncthreads();
        if (cb + 2 < 8) prefetch(p, cb + 2);
        cp_commit();
    }

    #pragma unroll
    for (int j = 0; j < 8; j++) {
        int co = cgrp * 64 + wid * 8 + j;
        float bias = eb2[e * 128 + co];
        int lbase = l0 + 8 * lane;
        float* dst = &g_e2[((size_t)t * 128 + co) * L2P + lbase];
        float4 r0, r1;
        r0.x = fmaxf(acc[j][0] + bias, 0.0f); r0.y = fmaxf(acc[j][1] + bias, 0.0f);
        r0.z = fmaxf(acc[j][2] + bias, 0.0f); r0.w = fmaxf(acc[j][3] + bias, 0.0f);
        r1.x = fmaxf(acc[j][4] + bias, 0.0f); r1.y = fmaxf(acc[j][5] + bias, 0.0f);
        r1.z = fmaxf(acc[j][6] + bias, 0.0f); r1.w = fmaxf(acc[j][7] + bias, 0.0f);
        *(float4*)dst = r0;
        *(float4*)(dst + 4) = r1;
    }
    if (tail) {
        int co = cgrp * 64 + tid;
        g_e2[((size_t)t * 128 + co) * L2P + 512] = fmaxf(tacc + eb2[e * 128 + co], 0.0f);
    }
}

// ---------------- 7) expert conv3: (128 -> 128), k=3, s=1, p=1, relu -----------
// cp.async double-buffered over 8 ci-chunks. Dynamic smem:
//   sin: 2 x [16][260], sw: 2 x [64][48]  -> 57856 bytes
#define E3_SIN_STRIDE (16 * 260)
#define E3_SW_STRIDE  (64 * 48)
#define E3_SMEM ((2 * E3_SIN_STRIDE + 2 * E3_SW_STRIDE) * 4)
__global__ void __launch_bounds__(256, 2)
econv3_kernel(const float* __restrict__ ew3, const float* __restrict__ eb3) {
    extern __shared__ __align__(16) float dyn3[];
    float* sinb = dyn3;
    float* swb  = dyn3 + 2 * E3_SIN_STRIDE;
    int t  = blockIdx.z;
    int e  = g_ti[t];
    int l0 = blockIdx.x * 256;
    int cgrp = blockIdx.y;
    int tid = threadIdx.x;
    int lane = tid & 31;
    int wid  = tid >> 5;
    bool tail = (blockIdx.x == 1) && (tid < 64);

    const float* e2base = g_e2 + (size_t)t * 128 * L2P;
    const float* wbase  = ew3 + (size_t)(e * 128 + cgrp * 64) * 384;

    auto prefetch = [&](int p, int cb) {
        float* s = sinb + p * E3_SIN_STRIDE;
        for (int i = tid; i < 16 * 259; i += 256) {
            int ci = i / 259, j = i % 259;
            int g = l0 - 1 + j;
            bool ok = (g >= 0 && g < L2E);
            cp4z(s2u(&s[ci * 260 + j]),
                 e2base + (size_t)(cb * 16 + ci) * L2P + (ok ? g : 0), ok);
        }
        float* w = swb + p * E3_SW_STRIDE;
        for (int i = tid; i < 64 * 48; i += 256) {
            int co = i / 48, r = i % 48;
            cp4z(s2u(&w[co * 48 + r]), wbase + (size_t)co * 384 + cb * 48 + r, true);
        }
    };

    float acc[8][8];
    #pragma unroll
    for (int j = 0; j < 8; j++)
        #pragma unroll
        for (int i = 0; i < 8; i++) acc[j][i] = 0.0f;
    float tacc = 0.0f;

    prefetch(0, 0); cp_commit();
    prefetch(1, 1); cp_commit();

    for (int cb = 0; cb < 8; cb++) {
        int p = cb & 1;
        cp_wait<1>();
        __syncthreads();
        const float* s = sinb + p * E3_SIN_STRIDE;
        const float* w = swb + p * E3_SW_STRIDE;

        #pragma unroll 1
        for (int ci = 0; ci < 16; ci++) {
            const float* row = s + ci * 260 + 8 * lane;
            float4 a0 = *(const float4*)(row);
            float4 a1 = *(const float4*)(row + 4);
            float4 a2 = *(const float4*)(row + 8);
            float v[12] = {a0.x,a0.y,a0.z,a0.w, a1.x,a1.y,a1.z,a1.w,
                           a2.x,a2.y,a2.z,a2.w};
            #pragma unroll
            for (int j = 0; j < 8; j++) {
                #pragma unroll
                for (int k = 0; k < 3; k++) {
                    float wv = w[(wid * 8 + j) * 48 + ci * 3 + k];
                    #pragma unroll
                    for (int i = 0; i < 8; i++)
                        acc[j][i] += wv * v[i + k];
                }
            }
        }
        if (tail) {
            #pragma unroll 1
            for (int ci = 0; ci < 16; ci++)
                #pragma unroll
                for (int k = 0; k < 3; k++)
                    tacc += s[ci * 260 + 256 + k] * w[tid * 48 + ci * 3 + k];
        }
        __syncthreads();
        if (cb + 2 < 8) prefetch(p, cb + 2);
        cp_commit();
    }

    #pragma unroll
    for (int j = 0; j < 8; j++) {
        int co = cgrp * 64 + wid * 8 + j;
        float bias = eb3[e * 128 + co];
        int lbase = l0 + 8 * lane;
        float* dst = &g_e3[((size_t)t * 128 + co) * L2P + lbase];
        float4 r0, r1;
        r0.x = fmaxf(acc[j][0] + bias, 0.0f); r0.y = fmaxf(acc[j][1] + bias, 0.0f);
        r0.z = fmaxf(acc[j][2] + bias, 0.0f); r0.w = fmaxf(acc[j][3] + bias, 0.0f);
        r1.x = fmaxf(acc[j][4] + bias, 0.0f); r1.y = fmaxf(acc[j][5] + bias, 0.0f);
        r1.z = fmaxf(acc[j][6] + bias, 0.0f); r1.w = fmaxf(acc[j][7] + bias, 0.0f);
        *(float4*)dst = r0;
        *(float4*)(dst + 4) = r1;
    }
    if (tail) {
        int co = cgrp * 64 + tid;
        g_e3[((size_t)t * 128 + co) * L2P + 512] = fmaxf(tacc + eb3[e * 128 + co], 0.0f);
    }
}

// ---------------- 8) top-2 combine + adaptive max-pool + aux finalize ----------
__global__ void pool_kernel(float* __restrict__ out, int out_size) {
    int idx = blockIdx.x * blockDim.x + threadIdx.x;
    if (idx == 0) {
        float aux = 0.0f;
        #pragma unroll
        for (int e = 0; e < 8; e++)
            aux += (g_srw[e] * (1.0f / 128.0f)) * (g_slg[e] * (1.0f / 128.0f));
        out[out_size - 1] = 0.01f * 8.0f * aux;
    }
    if (idx >= B * 128 * 256) return;
    int o  = idx & 255;
    int co = (idx >> 8) & 127;
    int b  = idx >> 15;
    float w0 = g_tw[b * 2 + 0];
    float w1 = g_tw[b * 2 + 1];
    const float* p0 = g_e3 + ((size_t)(b * 2 + 0) * 128 + co) * L2P;
    const float* p1 = g_e3 + ((size_t)(b * 2 + 1) * 128 + co) * L2P;
    int s  = (o * 513) >> 8;
    int en = (o * 513 + 513 + 255) >> 8;
    float m = -INFINITY;
    for (int l = s; l < en; l++)
        m = fmaxf(m, w0 * p0[l] + w1 * p1[l]);
    out[idx] = m;
}

// ---------------- launch --------------------------------------------------------
extern "C" void kernel_launch(void* const* d_in, const int* in_sizes, int n_in,
                              void* d_out, int out_size) {
    const float* x    = (const float*)d_in[0];
    const float* gw1  = (const float*)d_in[1];
    const float* gb1  = (const float*)d_in[2];
    const float* gw2  = (const float*)d_in[3];
    const float* gb2  = (const float*)d_in[4];
    const float* mw1  = (const float*)d_in[5];
    const float* mb1  = (const float*)d_in[6];
    const float* mw2  = (const float*)d_in[7];
    const float* mb2  = (const float*)d_in[8];
    const float* ew1  = (const float*)d_in[9];
    const float* eb1  = (const float*)d_in[10];
    const float* ew2  = (const float*)d_in[11];
    const float* eb2  = (const float*)d_in[12];
    const float* ew3  = (const float*)d_in[13];
    const float* eb3  = (const float*)d_in[14];
    float* out = (float*)d_out;

    static int attr_done = 0;
    if (!attr_done) {
        cudaFuncSetAttribute(econv2_kernel, cudaFuncAttributeMaxDynamicSharedMemorySize, E2_SMEM);
        cudaFuncSetAttribute(econv3_kernel, cudaFuncAttributeMaxDynamicSharedMemorySize, E3_SMEM);
        attr_done = 1;
    }

    fft_kernel<<<B, 512>>>(x);
    gconv1_kernel<<<dim3(2, B), 256>>>(gw1, gb1);
    gconv2_pool_kernel<<<dim3(8, B), 256>>>(gw2, gb2);
    gate_mlp_kernel<<<B, 128>>>(mw1, mb1, mw2, mb2);
    econv1_kernel<<<NTASK, 256>>>(ew1, eb1);
    econv2_kernel<<<dim3(2, 2, NTASK), 256, E2_SMEM>>>(ew2, eb2);
    econv3_kernel<<<dim3(2, 2, NTASK), 256, E3_SMEM>>>(ew3, eb3);
    pool_kernel<<<16384, 256>>>(out, out_size);
}

// round 9
// speedup vs baseline: 1.5909x; 1.0057x over previous
#include <cuda_runtime.h>
#include <math.h>
#include <stdint.h>

#define B 128
#define LSEQ 4096
#define NF 2049          // rfft bins
#define NFP 2052         // padded row stride for g_h1
#define L1E 1025         // expert conv1 out length
#define L1P 1028
#define L2E 513          // expert conv2/conv3 out length
#define L2P 516
#define NTASK 256        // B * TOP_K

// ---------------- cp.async helpers --------------------------------------------
__device__ __forceinline__ uint32_t s2u(const void* p) {
    return (uint32_t)__cvta_generic_to_shared(p);
}
__device__ __forceinline__ void cp4z(uint32_t saddr, const void* g, bool pred) {
    int sz = pred ? 4 : 0;
    asm volatile("cp.async.ca.shared.global [%0], [%1], 4, %2;"
                 :: "r"(saddr), "l"(g), "r"(sz));
}
__device__ __forceinline__ void cp_commit() {
    asm volatile("cp.async.commit_group;");
}
template <int N>
__device__ __forceinline__ void cp_wait() {
    asm volatile("cp.async.wait_group %0;" :: "n"(N));
}
// round fp32 -> tf32 (rna), returned as fp32 bit pattern
__device__ __forceinline__ float tf32r(float x) {
    uint32_t u;
    asm("cvt.rna.tf32.f32 %0, %1;" : "=r"(u) : "f"(x));
    return __uint_as_float(u);
}

// ---------------- scratch (device globals) -------------------------------------
__device__ float g_fft[B * 2 * NF];
__device__ float g_h1 [B * 32 * NFP];
__device__ float g_pooled[B * 64];
__device__ float g_tw[NTASK];
__device__ int   g_ti[NTASK];
__device__ float g_srw[8];
__device__ float g_slg[8];
__device__ float g_e1[NTASK * 64  * L1P];
__device__ float g_e2[NTASK * 128 * L2P];
__device__ float g_e3[NTASK * 128 * L2P];

// ---------------- 1) Hann window + 4096-pt radix-2 FFT + zero accumulators -----
__global__ void fft_kernel(const float* __restrict__ x) {
    __shared__ float re[4096];
    __shared__ float im[4096];
    __shared__ float twr[2048];
    __shared__ float twi[2048];
    int b = blockIdx.x;
    const float* xb = x + b * LSEQ;

    if (threadIdx.x < 64) g_pooled[b * 64 + threadIdx.x] = 0.0f;
    if (b == 0 && threadIdx.x >= 64 && threadIdx.x < 72) {
        g_srw[threadIdx.x - 64] = 0.0f;
        g_slg[threadIdx.x - 64] = 0.0f;
    }

    for (int i = threadIdx.x; i < 2048; i += blockDim.x) {
        float si, sr;
        sincospif(-(float)i * (1.0f / 2048.0f), &si, &sr);
        twr[i] = sr; twi[i] = si;
    }
    for (int i = threadIdx.x; i < 4096; i += blockDim.x) {
        float w = 0.5f * (1.0f - cospif((float)i * (1.0f / 2048.0f)));
        int j = __brev((unsigned)i) >> 20;
        re[j] = xb[i] * w;
        im[j] = 0.0f;
    }
    __syncthreads();

    for (int s = 1; s <= 12; s++) {
        int half = 1 << (s - 1);
        int len  = 1 << s;
        int shft = 12 - s;
        for (int t = threadIdx.x; t < 2048; t += blockDim.x) {
            int g   = t >> (s - 1);
            int pos = t & (half - 1);
            int i0  = g * len + pos;
            int i1  = i0 + half;
            int j   = pos << shft;
            float sr = twr[j], si = twi[j];
            float ar = re[i1], ai = im[i1];
            float tr = ar * sr - ai * si;
            float ti = ar * si + ai * sr;
            float br = re[i0], bi = im[i0];
            re[i1] = br - tr; im[i1] = bi - ti;
            re[i0] = br + tr; im[i0] = bi + ti;
        }
        __syncthreads();
    }
    const float sc = 1.0f / 64.0f;
    for (int f = threadIdx.x; f < NF; f += blockDim.x) {
        g_fft[(b * 2 + 0) * NF + f] = re[f] * sc;
        g_fft[(b * 2 + 1) * NF + f] = im[f] * sc;
    }
}

// ---------------- 2) gate conv1: (2 -> 32), k=5, s=1, p=2, relu ----------------
__global__ void gconv1_kernel(const float* __restrict__ w1, const float* __restrict__ b1) {
    __shared__ __align__(16) float sin_[2][1036];
    __shared__ float sw[32][11];
    __shared__ float sb[32];
    int b  = blockIdx.y;
    int l0 = blockIdx.x * 1024;
    int tid = threadIdx.x;   // 256

    for (int i = tid; i < 2 * 1032; i += 256) {
        int ci = i / 1032, j = i % 1032;
        int g = l0 + j - 2;
        sin_[ci][j] = (g >= 0 && g < NF) ? g_fft[(b * 2 + ci) * NF + g] : 0.0f;
    }
    for (int i = tid; i < 320; i += 256) sw[i / 10][i % 10] = w1[i];
    if (tid < 32) sb[tid] = b1[tid];
    __syncthreads();

    float v[2][8];
    #pragma unroll
    for (int ci = 0; ci < 2; ci++) {
        float4 a = *(const float4*)&sin_[ci][4 * tid];
        float4 c = *(const float4*)&sin_[ci][4 * tid + 4];
        v[ci][0] = a.x; v[ci][1] = a.y; v[ci][2] = a.z; v[ci][3] = a.w;
        v[ci][4] = c.x; v[ci][5] = c.y; v[ci][6] = c.z; v[ci][7] = c.w;
    }

    #pragma unroll 4
    for (int co = 0; co < 32; co++) {
        float acc[4];
        #pragma unroll
        for (int i = 0; i < 4; i++) acc[i] = sb[co];
        #pragma unroll
        for (int ci = 0; ci < 2; ci++)
            #pragma unroll
            for (int k = 0; k < 5; k++) {
                float w = sw[co][ci * 5 + k];
                #pragma unroll
                for (int i = 0; i < 4; i++) acc[i] += w * v[ci][i + k];
            }
        float4 r;
        r.x = fmaxf(acc[0], 0.0f); r.y = fmaxf(acc[1], 0.0f);
        r.z = fmaxf(acc[2], 0.0f); r.w = fmaxf(acc[3], 0.0f);
        *(float4*)&g_h1[(b * 32 + co) * NFP + l0 + 4 * tid] = r;
    }

    if (blockIdx.x == 1 && tid == 0) {
        for (int co = 0; co < 32; co++) {
            float acc = sb[co];
            #pragma unroll
            for (int ci = 0; ci < 2; ci++)
                #pragma unroll
                for (int k = 0; k < 5; k++)
                    acc += sin_[ci][1024 + k] * sw[co][ci * 5 + k];
            g_h1[(b * 32 + co) * NFP + 2048] = fmaxf(acc, 0.0f);
        }
    }
}

// ---------------- 3) gate conv2 (32 -> 64, k5, p2) + mean pool -----------------
__global__ void __launch_bounds__(256, 2)
gconv2_pool_kernel(const float* __restrict__ w2, const float* __restrict__ b2) {
    __shared__ __align__(16) float sin_[16][264];
    __shared__ float sw[64][81];
    int b   = blockIdx.y;
    int l0  = blockIdx.x * 256;
    int tid = threadIdx.x;
    int lane = tid & 31;
    int wid  = tid >> 5;
    bool tail = (blockIdx.x == 7) && (tid < 64);

    float acc[8][8];
    #pragma unroll
    for (int j = 0; j < 8; j++)
        #pragma unroll
        for (int i = 0; i < 8; i++) acc[j][i] = 0.0f;
    float tacc = 0.0f;

    for (int cb = 0; cb < 2; cb++) {
        __syncthreads();
        for (int i = tid; i < 16 * 261; i += 256) {
            int ci = i / 261, j = i % 261;
            int g = l0 + j - 2;
            sin_[ci][j] = (g >= 0 && g < NF) ? g_h1[(b * 32 + cb * 16 + ci) * NFP + g] : 0.0f;
        }
        for (int i = tid; i < 64 * 80; i += 256) {
            int co = i / 80, r = i % 80;
            sw[co][r] = w2[co * 160 + cb * 80 + r];
        }
        __syncthreads();

        #pragma unroll 1
        for (int ci = 0; ci < 16; ci++) {
            float4 a = *(const float4*)&sin_[ci][8 * lane];
            float4 c = *(const float4*)&sin_[ci][8 * lane + 4];
            float4 d = *(const float4*)&sin_[ci][8 * lane + 8];
            float v[12] = {a.x,a.y,a.z,a.w, c.x,c.y,c.z,c.w, d.x,d.y,d.z,d.w};
            #pragma unroll
            for (int j = 0; j < 8; j++) {
                #pragma unroll
                for (int k = 0; k < 5; k++) {
                    float w = sw[wid * 8 + j][ci * 5 + k];
                    #pragma unroll
                    for (int i = 0; i < 8; i++)
                        acc[j][i] += w * v[i + k];
                }
            }
        }
        if (tail) {
            #pragma unroll 1
            for (int ci = 0; ci < 16; ci++)
                #pragma unroll
                for (int k = 0; k < 5; k++)
                    tacc += sin_[ci][256 + k] * sw[tid][ci * 5 + k];
        }
    }

    #pragma unroll
    for (int j = 0; j < 8; j++) {
        int co = wid * 8 + j;
        float bias = b2[co];
        float p = 0.0f;
        #pragma unroll
        for (int i = 0; i < 8; i++)
            p += fmaxf(acc[j][i] + bias, 0.0f);
        #pragma unroll
        for (int off = 16; off; off >>= 1)
            p += __shfl_down_sync(0xffffffffu, p, off, 32);
        if (lane == 0) atomicAdd(&g_pooled[b * 64 + co], p);
    }
    if (tail)
        atomicAdd(&g_pooled[b * 64 + tid], fmaxf(tacc + b2[tid], 0.0f));
}

// ---------------- 4) router MLP + softmax + top2 + aux accumulation ------------
__global__ void gate_mlp_kernel(const float* __restrict__ w1, const float* __restrict__ b1,
                                const float* __restrict__ w2, const float* __restrict__ b2) {
    __shared__ float sp[64];
    __shared__ float sh[128];
    __shared__ float slg[8];
    int b = blockIdx.x;
    int j = threadIdx.x;

    if (j < 64) sp[j] = g_pooled[b * 64 + j] * (1.0f / 2049.0f);
    __syncthreads();

    {
        const float* wr = w1 + j * 64;
        float h0 = 0.f, h1 = 0.f, h2 = 0.f, h3 = 0.f;
        #pragma unroll
        for (int i = 0; i < 64; i += 4) {
            h0 += sp[i + 0] * wr[i + 0];
            h1 += sp[i + 1] * wr[i + 1];
            h2 += sp[i + 2] * wr[i + 2];
            h3 += sp[i + 3] * wr[i + 3];
        }
        sh[j] = fmaxf((h0 + h1) + (h2 + h3) + b1[j], 0.0f);
    }
    __syncthreads();

    if (j < 8) {
        float acc = b2[j];
        const float* wr = w2 + j * 128;
        #pragma unroll 8
        for (int i = 0; i < 128; i++) acc += sh[i] * wr[i];
        slg[j] = acc;
    }
    __syncthreads();

    if (j == 0) {
        float lg[8];
        #pragma unroll
        for (int e = 0; e < 8; e++) lg[e] = slg[e];
        float m = lg[0];
        #pragma unroll
        for (int e = 1; e < 8; e++) m = fmaxf(m, lg[e]);
        float rw[8], s = 0.0f;
        #pragma unroll
        for (int e = 0; e < 8; e++) { rw[e] = expf(lg[e] - m); s += rw[e]; }
        float invs = 1.0f / s;
        #pragma unroll
        for (int e = 0; e < 8; e++) rw[e] *= invs;

        int i0 = 0;
        #pragma unroll
        for (int e = 1; e < 8; e++) if (rw[e] > rw[i0]) i0 = e;
        int i1 = (i0 == 0) ? 1 : 0;
        #pragma unroll
        for (int e = 0; e < 8; e++) if (e != i1 && e != i0 && rw[e] > rw[i1]) i1 = e;

        float t0 = rw[i0], t1 = rw[i1];
        float tn = 1.0f / (t0 + t1);
        g_ti[b * 2 + 0] = i0; g_ti[b * 2 + 1] = i1;
        g_tw[b * 2 + 0] = t0 * tn; g_tw[b * 2 + 1] = t1 * tn;

        #pragma unroll
        for (int e = 0; e < 8; e++) {
            atomicAdd(&g_srw[e], rw[e]);
            atomicAdd(&g_slg[e], lg[e]);
        }
    }
}

// ---------------- 5) expert conv1: (2 -> 64), k=7, s=2, p=3, relu --------------
__global__ void econv1_kernel(const float* __restrict__ ew1, const float* __restrict__ eb1) {
    __shared__ __align__(16) float sin_[2][2056];
    __shared__ float sw[64][16];
    __shared__ float sb[64];
    int t = blockIdx.x;
    int b = t >> 1;
    int e = g_ti[t];
    int tid = threadIdx.x;   // 256

    for (int i = tid; i < 2 * 2056; i += 256) {
        int ci = i / 2056, j = i % 2056;
        int g = j - 3;
        sin_[ci][j] = (g >= 0 && g < NF) ? g_fft[(b * 2 + ci) * NF + g] : 0.0f;
    }
    for (int i = tid; i < 64 * 14; i += 256) sw[i / 14][i % 14] = ew1[e * 896 + i];
    if (tid < 64) sb[tid] = eb1[e * 64 + tid];
    __syncthreads();

    float v[2][16];
    #pragma unroll
    for (int ci = 0; ci < 2; ci++) {
        float4 a = *(const float4*)&sin_[ci][8 * tid];
        float4 c = *(const float4*)&sin_[ci][8 * tid + 4];
        float4 d = *(const float4*)&sin_[ci][8 * tid + 8];
        float4 f = *(const float4*)&sin_[ci][8 * tid + 12];
        v[ci][0]=a.x;  v[ci][1]=a.y;  v[ci][2]=a.z;  v[ci][3]=a.w;
        v[ci][4]=c.x;  v[ci][5]=c.y;  v[ci][6]=c.z;  v[ci][7]=c.w;
        v[ci][8]=d.x;  v[ci][9]=d.y;  v[ci][10]=d.z; v[ci][11]=d.w;
        v[ci][12]=f.x; v[ci][13]=f.y; v[ci][14]=f.z; v[ci][15]=f.w;
    }

    #pragma unroll 2
    for (int co = 0; co < 64; co++) {
        float acc[4];
        #pragma unroll
        for (int i = 0; i < 4; i++) acc[i] = sb[co];
        #pragma unroll
        for (int ci = 0; ci < 2; ci++)
            #pragma unroll
            for (int k = 0; k < 7; k++) {
                float w = sw[co][ci * 7 + k];
                #pragma unroll
                for (int i = 0; i < 4; i++) acc[i] += w * v[ci][2 * i + k];
            }
        float4 r;
        r.x = fmaxf(acc[0], 0.0f); r.y = fmaxf(acc[1], 0.0f);
        r.z = fmaxf(acc[2], 0.0f); r.w = fmaxf(acc[3], 0.0f);
        *(float4*)&g_e1[((size_t)t * 64 + co) * L1P + 4 * tid] = r;
    }

    if (tid < 64) {
        int co = tid;
        float acc = sb[co];
        #pragma unroll
        for (int ci = 0; ci < 2; ci++)
            #pragma unroll
            for (int k = 0; k < 7; k++)
                acc += sin_[ci][2048 + k] * sw[co][ci * 7 + k];
        g_e1[((size_t)t * 64 + co) * L1P + 1024] = fmaxf(acc, 0.0f);
    }
}

// ---------------- 6) expert conv2: (64 -> 128), k=5, s=2, p=2, relu ------------
// cp.async double-buffered. Outputs rounded to tf32 (consumed by tf32 econv3).
#define E2_SIN_STRIDE (8 * 520)
#define E2_SW_STRIDE  (64 * 40)
#define E2_SMEM ((2 * E2_SIN_STRIDE + 2 * E2_SW_STRIDE) * 4)
__global__ void __launch_bounds__(256, 2)
econv2_kernel(const float* __restrict__ ew2, const float* __restrict__ eb2) {
    extern __shared__ __align__(16) float dyn2[];
    float* sinb = dyn2;
    float* swb  = dyn2 + 2 * E2_SIN_STRIDE;
    int t  = blockIdx.z;
    int e  = g_ti[t];
    int l0 = blockIdx.x * 256;
    int cgrp = blockIdx.y;
    int tid = threadIdx.x;
    int lane = tid & 31;
    int wid  = tid >> 5;
    bool tail = (blockIdx.x == 1) && (tid < 64);

    const float* e1base = g_e1 + (size_t)t * 64 * L1P;
    const float* wbase  = ew2 + (size_t)(e * 128 + cgrp * 64) * 320;

    auto prefetch = [&](int p, int cb) {
        float* s = sinb + p * E2_SIN_STRIDE;
        for (int i = tid; i < 8 * 517; i += 256) {
            int ci = i / 517, j = i % 517;
            int g = 2 * l0 - 2 + j;
            bool ok = (g >= 0 && g < L1E);
            cp4z(s2u(&s[ci * 520 + j]),
                 e1base + (size_t)(cb * 8 + ci) * L1P + (ok ? g : 0), ok);
        }
        float* w = swb + p * E2_SW_STRIDE;
        for (int i = tid; i < 64 * 40; i += 256) {
            int co = i / 40, r = i % 40;
            cp4z(s2u(&w[co * 40 + r]), wbase + (size_t)co * 320 + cb * 40 + r, true);
        }
    };

    float acc[8][8];
    #pragma unroll
    for (int j = 0; j < 8; j++)
        #pragma unroll
        for (int i = 0; i < 8; i++) acc[j][i] = 0.0f;
    float tacc = 0.0f;

    prefetch(0, 0); cp_commit();
    prefetch(1, 1); cp_commit();

    for (int cb = 0; cb < 8; cb++) {
        int p = cb & 1;
        cp_wait<1>();
        __syncthreads();
        const float* s = sinb + p * E2_SIN_STRIDE;
        const float* w = swb + p * E2_SW_STRIDE;

        #pragma unroll 1
        for (int ci = 0; ci < 8; ci++) {
            const float* row = s + ci * 520 + 16 * lane;
            float4 a0 = *(const float4*)(row);
            float4 a1 = *(const float4*)(row + 4);
            float4 a2 = *(const float4*)(row + 8);
            float4 a3 = *(const float4*)(row + 12);
            float4 a4 = *(const float4*)(row + 16);
            float v[20] = {a0.x,a0.y,a0.z,a0.w, a1.x,a1.y,a1.z,a1.w,
                           a2.x,a2.y,a2.z,a2.w, a3.x,a3.y,a3.z,a3.w,
                           a4.x,a4.y,a4.z,a4.w};
            #pragma unroll
            for (int j = 0; j < 8; j++) {
                #pragma unroll
                for (int k = 0; k < 5; k++) {
                    float wv = w[(wid * 8 + j) * 40 + ci * 5 + k];
                    #pragma unroll
                    for (int i = 0; i < 8; i++)
                        acc[j][i] += wv * v[2 * i + k];
                }
            }
        }
        if (tail) {
            #pragma unroll 1
            for (int ci = 0; ci < 8; ci++)
                #pragma unroll
                for (int k = 0; k < 5; k++)
                    tacc += s[ci * 520 + 512 + k] * w[tid * 40 + ci * 5 + k];
        }
        __syncthreads();
        if (cb + 2 < 8) prefetch(p, cb + 2);
        cp_commit();
    }

    #pragma unroll
    for (int j = 0; j < 8; j++) {
        int co = cgrp * 64 + wid * 8 + j;
        float bias = eb2[e * 128 + co];
        int lbase = l0 + 8 * lane;
        float* dst = &g_e2[((size_t)t * 128 + co) * L2P + lbase];
        float4 r0, r1;
        r0.x = tf32r(fmaxf(acc[j][0] + bias, 0.0f)); r0.y = tf32r(fmaxf(acc[j][1] + bias, 0.0f));
        r0.z = tf32r(fmaxf(acc[j][2] + bias, 0.0f)); r0.w = tf32r(fmaxf(acc[j][3] + bias, 0.0f));
        r1.x = tf32r(fmaxf(acc[j][4] + bias, 0.0f)); r1.y = tf32r(fmaxf(acc[j][5] + bias, 0.0f));
        r1.z = tf32r(fmaxf(acc[j][6] + bias, 0.0f)); r1.w = tf32r(fmaxf(acc[j][7] + bias, 0.0f));
        *(float4*)dst = r0;
        *(float4*)(dst + 4) = r1;
    }
    if (tail) {
        int co = cgrp * 64 + tid;
        g_e2[((size_t)t * 128 + co) * L2P + 512] = tf32r(fmaxf(tacc + eb2[e * 128 + co], 0.0f));
    }
}

// ---------------- 7) expert conv3 via TF32 mma.sync ----------------------------
// D[co, l] = relu(sum_{K} W[co,K] * X[ci(K), l+shift(K)-1]) + bias, K = shift*128+ci
// Block: 8 warps = 4 co-subtiles(16) x 2 n-halves(64); tile co64 x l128.
// 4 ci-chunks of 32 (K-chunk 96 = 12 k-steps of 8, shift-major so shift const per step).
// Input staged via cp.async (values pre-rounded to tf32 by econv2);
// weights staged via register prefetch + cvt.rna + STS.
#define E3T_SX_STRIDE (32 * 136)
#define E3T_SW_STRIDE (96 * 72)
#define E3T_SMEM ((2 * E3T_SX_STRIDE + 2 * E3T_SW_STRIDE) * 4)
__global__ void __launch_bounds__(256, 2)
econv3_tf32_kernel(const float* __restrict__ ew3, const float* __restrict__ eb3) {
    extern __shared__ __align__(16) float dyn3[];
    float* sxb = dyn3;                         // 2 x [32][136], col j <-> l = l0-1+j
    float* swb = dyn3 + 2 * E3T_SX_STRIDE;     // 2 x [96][72], rows K'=shift*32+ci, cols co
    int t  = blockIdx.z;
    int e  = g_ti[t];
    int l0 = blockIdx.x * 128;
    int cgrp = blockIdx.y;                     // co base = cgrp*64
    int tid = threadIdx.x;
    int lane = tid & 31;
    int w    = tid >> 5;
    int wc   = w & 3;                          // co subtile (16 rows)
    int wn   = w >> 2;                         // n half (64 cols)
    int g    = lane >> 2;                      // fragment group row
    int tg   = lane & 3;                       // fragment thread-in-group
    bool tail = (blockIdx.x == 3) && (tid < 64);

    const float* e2base = g_e2 + (size_t)t * 128 * L2P;
    const float* wbase  = ew3 + (size_t)(e * 128 + cgrp * 64) * 384;

    auto prefetchX = [&](int p, int cb) {
        float* s = sxb + p * E3T_SX_STRIDE;
        for (int i = tid; i < 32 * 131; i += 256) {
            int ci = i / 131, j = i % 131;
            int l = l0 - 1 + j;
            bool ok = (l >= 0 && l < L2E);
            cp4z(s2u(&s[ci * 136 + j]),
                 e2base + (size_t)(cb * 32 + ci) * L2P + (ok ? l : 0), ok);
        }
    };

    float wreg[24];
    auto loadW = [&](int cb) {
        #pragma unroll
        for (int n = 0; n < 24; n++) {
            int i = n * 256 + tid;
            int Kp = i >> 6, co = i & 63;
            int shift = Kp >> 5, cil = Kp & 31;
            wreg[n] = __ldg(wbase + (size_t)co * 384 + (cb * 32 + cil) * 3 + shift);
        }
    };
    auto storeW = [&](int p) {
        float* d = swb + p * E3T_SW_STRIDE;
        #pragma unroll
        for (int n = 0; n < 24; n++) {
            int i = n * 256 + tid;
            int Kp = i >> 6, co = i & 63;
            d[Kp * 72 + co] = tf32r(wreg[n]);
        }
    };

    float acc[8][4];
    #pragma unroll
    for (int nt = 0; nt < 8; nt++)
        #pragma unroll
        for (int i = 0; i < 4; i++) acc[nt][i] = 0.0f;
    float tacc = 0.0f;

    loadW(0);
    prefetchX(0, 0); cp_commit();
    prefetchX(1, 1); cp_commit();
    storeW(0);
    loadW(1);

    for (int cb = 0; cb < 4; cb++) {
        int p = cb & 1;
        cp_wait<1>();
        __syncthreads();
        const float* X = sxb + p * E3T_SX_STRIDE;
        const float* W = swb + p * E3T_SW_STRIDE;

        #pragma unroll 1
        for (int ks = 0; ks < 12; ks++) {
            int shift = ks >> 2;
            int cik   = (ks & 3) * 8;
            const float* wr = W + (ks * 8 + tg) * 72 + wc * 16 + g;
            uint32_t a0 = __float_as_uint(wr[0]);
            uint32_t a1 = __float_as_uint(wr[8]);
            uint32_t a2 = __float_as_uint(wr[4 * 72]);
            uint32_t a3 = __float_as_uint(wr[4 * 72 + 8]);
            const float* x0 = X + (cik + tg) * 136 + wn * 64 + g + shift;
            const float* x1 = x0 + 4 * 136;
            #pragma unroll
            for (int nt = 0; nt < 8; nt++) {
                uint32_t b0 = __float_as_uint(x0[nt * 8]);
                uint32_t b1 = __float_as_uint(x1[nt * 8]);
                asm volatile(
                    "mma.sync.aligned.m16n8k8.row.col.f32.tf32.tf32.f32 "
                    "{%0,%1,%2,%3}, {%4,%5,%6,%7}, {%8,%9}, {%0,%1,%2,%3};"
                    : "+f"(acc[nt][0]), "+f"(acc[nt][1]),
                      "+f"(acc[nt][2]), "+f"(acc[nt][3])
                    : "r"(a0), "r"(a1), "r"(a2), "r"(a3), "r"(b0), "r"(b1));
            }
        }
        if (tail) {
            // l = 512: j = 512 - l0 + shift = 128 + shift
            #pragma unroll 1
            for (int ci = 0; ci < 32; ci++)
                #pragma unroll
                for (int sh = 0; sh < 3; sh++)
                    tacc += X[ci * 136 + 128 + sh] * W[(sh * 32 + ci) * 72 + tid];
        }
        __syncthreads();
        if (cb + 2 < 4) prefetchX(p, cb + 2);
        cp_commit();
        if (cb + 1 < 4) storeW((cb + 1) & 1);
        if (cb + 2 < 4) loadW(cb + 2);
    }

    // epilogue: c0/c1 -> (co_a, l..l+1), c2/c3 -> (co_a+8, l..l+1)
    int co_a = cgrp * 64 + wc * 16 + g;
    int co_b = co_a + 8;
    float bias_a = eb3[e * 128 + co_a];
    float bias_b = eb3[e * 128 + co_b];
    float* outa = &g_e3[((size_t)t * 128 + co_a) * L2P];
    float* outb = &g_e3[((size_t)t * 128 + co_b) * L2P];
    #pragma unroll
    for (int nt = 0; nt < 8; nt++) {
        int l = l0 + wn * 64 + nt * 8 + 2 * tg;
        float2 ra, rb;
        ra.x = fmaxf(acc[nt][0] + bias_a, 0.0f);
        ra.y = fmaxf(acc[nt][1] + bias_a, 0.0f);
        rb.x = fmaxf(acc[nt][2] + bias_b, 0.0f);
        rb.y = fmaxf(acc[nt][3] + bias_b, 0.0f);
        *(float2*)(outa + l) = ra;
        *(float2*)(outb + l) = rb;
    }
    if (tail) {
        int co = cgrp * 64 + tid;
        g_e3[((size_t)t * 128 + co) * L2P + 512] = fmaxf(tacc + eb3[e * 128 + co], 0.0f);
    }
}

// ---------------- 8) top-2 combine + adaptive max-pool + aux finalize ----------
__global__ void pool_kernel(float* __restrict__ out, int out_size) {
    int idx = blockIdx.x * blockDim.x + threadIdx.x;
    if (idx == 0) {
        float aux = 0.0f;
        #pragma unroll
        for (int e = 0; e < 8; e++)
            aux += (g_srw[e] * (1.0f / 128.0f)) * (g_slg[e] * (1.0f / 128.0f));
        out[out_size - 1] = 0.01f * 8.0f * aux;
    }
    if (idx >= B * 128 * 256) return;
    int o  = idx & 255;
    int co = (idx >> 8) & 127;
    int b  = idx >> 15;
    float w0 = g_tw[b * 2 + 0];
    float w1 = g_tw[b * 2 + 1];
    const float* p0 = g_e3 + ((size_t)(b * 2 + 0) * 128 + co) * L2P;
    const float* p1 = g_e3 + ((size_t)(b * 2 + 1) * 128 + co) * L2P;
    int s  = (o * 513) >> 8;
    int en = (o * 513 + 513 + 255) >> 8;
    float m = -INFINITY;
    for (int l = s; l < en; l++)
        m = fmaxf(m, w0 * p0[l] + w1 * p1[l]);
    out[idx] = m;
}

// ---------------- launch --------------------------------------------------------
extern "C" void kernel_launch(void* const* d_in, const int* in_sizes, int n_in,
                              void* d_out, int out_size) {
    const float* x    = (const float*)d_in[0];
    const float* gw1  = (const float*)d_in[1];
    const float* gb1  = (const float*)d_in[2];
    const float* gw2  = (const float*)d_in[3];
    const float* gb2  = (const float*)d_in[4];
    const float* mw1  = (const float*)d_in[5];
    const float* mb1  = (const float*)d_in[6];
    const float* mw2  = (const float*)d_in[7];
    const float* mb2  = (const float*)d_in[8];
    const float* ew1  = (const float*)d_in[9];
    const float* eb1  = (const float*)d_in[10];
    const float* ew2  = (const float*)d_in[11];
    const float* eb2  = (const float*)d_in[12];
    const float* ew3  = (const float*)d_in[13];
    const float* eb3  = (const float*)d_in[14];
    float* out = (float*)d_out;

    static int attr_done = 0;
    if (!attr_done) {
        cudaFuncSetAttribute(econv2_kernel, cudaFuncAttributeMaxDynamicSharedMemorySize, E2_SMEM);
        cudaFuncSetAttribute(econv3_tf32_kernel, cudaFuncAttributeMaxDynamicSharedMemorySize, E3T_SMEM);
        attr_done = 1;
    }

    fft_kernel<<<B, 512>>>(x);
    gconv1_kernel<<<dim3(2, B), 256>>>(gw1, gb1);
    gconv2_pool_kernel<<<dim3(8, B), 256>>>(gw2, gb2);
    gate_mlp_kernel<<<B, 128>>>(mw1, mb1, mw2, mb2);
    econv1_kernel<<<NTASK, 256>>>(ew1, eb1);
    econv2_kernel<<<dim3(2, 2, NTASK), 256, E2_SMEM>>>(ew2, eb2);
    econv3_tf32_kernel<<<dim3(4, 2, NTASK), 256, E3T_SMEM>>>(ew3, eb3);
    pool_kernel<<<16384, 256>>>(out, out_size);
}

// round 10
// speedup vs baseline: 2.3727x; 1.4915x over previous
#include <cuda_runtime.h>
#include <math.h>
#include <stdint.h>

#define B 128
#define LSEQ 4096
#define NF 2049          // rfft bins
#define NFP 2052         // padded row stride for g_h1
#define L1E 1025         // expert conv1 out length
#define L1P 1028
#define L2E 513          // expert conv2/conv3 out length
#define L2P 516
#define NTASK 256        // B * TOP_K

// ---------------- cp.async helpers --------------------------------------------
__device__ __forceinline__ uint32_t s2u(const void* p) {
    return (uint32_t)__cvta_generic_to_shared(p);
}
__device__ __forceinline__ void cp4z(uint32_t saddr, const void* g, bool pred) {
    int sz = pred ? 4 : 0;
    asm volatile("cp.async.ca.shared.global [%0], [%1], 4, %2;"
                 :: "r"(saddr), "l"(g), "r"(sz));
}
__device__ __forceinline__ void cp_commit() {
    asm volatile("cp.async.commit_group;");
}
template <int N>
__device__ __forceinline__ void cp_wait() {
    asm volatile("cp.async.wait_group %0;" :: "n"(N));
}
// round fp32 -> tf32 (rna), returned as fp32 bit pattern
__device__ __forceinline__ float tf32r(float x) {
    uint32_t u;
    asm("cvt.rna.tf32.f32 %0, %1;" : "=r"(u) : "f"(x));
    return __uint_as_float(u);
}

// ---------------- scratch (device globals) -------------------------------------
__device__ float g_fft[B * 2 * NF];
__device__ float g_h1 [B * 32 * NFP];
__device__ float g_pooled[B * 64];
__device__ float g_tw[NTASK];
__device__ int   g_ti[NTASK];
__device__ float g_srw[8];
__device__ float g_slg[8];
__device__ float g_e1[NTASK * 64  * L1P];
__device__ float g_e2[NTASK * 128 * L2P];
__device__ float g_e3[NTASK * 128 * L2P];

// ---------------- 1) Hann window + 4096-pt radix-2 FFT + zero accumulators -----
__global__ void fft_kernel(const float* __restrict__ x) {
    __shared__ float re[4096];
    __shared__ float im[4096];
    __shared__ float twr[2048];
    __shared__ float twi[2048];
    int b = blockIdx.x;
    const float* xb = x + b * LSEQ;

    if (threadIdx.x < 64) g_pooled[b * 64 + threadIdx.x] = 0.0f;
    if (b == 0 && threadIdx.x >= 64 && threadIdx.x < 72) {
        g_srw[threadIdx.x - 64] = 0.0f;
        g_slg[threadIdx.x - 64] = 0.0f;
    }

    for (int i = threadIdx.x; i < 2048; i += blockDim.x) {
        float si, sr;
        sincospif(-(float)i * (1.0f / 2048.0f), &si, &sr);
        twr[i] = sr; twi[i] = si;
    }
    for (int i = threadIdx.x; i < 4096; i += blockDim.x) {
        float w = 0.5f * (1.0f - cospif((float)i * (1.0f / 2048.0f)));
        int j = __brev((unsigned)i) >> 20;
        re[j] = xb[i] * w;
        im[j] = 0.0f;
    }
    __syncthreads();

    for (int s = 1; s <= 12; s++) {
        int half = 1 << (s - 1);
        int len  = 1 << s;
        int shft = 12 - s;
        for (int t = threadIdx.x; t < 2048; t += blockDim.x) {
            int g   = t >> (s - 1);
            int pos = t & (half - 1);
            int i0  = g * len + pos;
            int i1  = i0 + half;
            int j   = pos << shft;
            float sr = twr[j], si = twi[j];
            float ar = re[i1], ai = im[i1];
            float tr = ar * sr - ai * si;
            float ti = ar * si + ai * sr;
            float br = re[i0], bi = im[i0];
            re[i1] = br - tr; im[i1] = bi - ti;
            re[i0] = br + tr; im[i0] = bi + ti;
        }
        __syncthreads();
    }
    const float sc = 1.0f / 64.0f;
    for (int f = threadIdx.x; f < NF; f += blockDim.x) {
        g_fft[(b * 2 + 0) * NF + f] = re[f] * sc;
        g_fft[(b * 2 + 1) * NF + f] = im[f] * sc;
    }
}

// ---------------- 2) gate conv1: (2 -> 32), k=5, s=1, p=2, relu ----------------
__global__ void gconv1_kernel(const float* __restrict__ w1, const float* __restrict__ b1) {
    __shared__ __align__(16) float sin_[2][1036];
    __shared__ float sw[32][11];
    __shared__ float sb[32];
    int b  = blockIdx.y;
    int l0 = blockIdx.x * 1024;
    int tid = threadIdx.x;   // 256

    for (int i = tid; i < 2 * 1032; i += 256) {
        int ci = i / 1032, j = i % 1032;
        int g = l0 + j - 2;
        sin_[ci][j] = (g >= 0 && g < NF) ? g_fft[(b * 2 + ci) * NF + g] : 0.0f;
    }
    for (int i = tid; i < 320; i += 256) sw[i / 10][i % 10] = w1[i];
    if (tid < 32) sb[tid] = b1[tid];
    __syncthreads();

    float v[2][8];
    #pragma unroll
    for (int ci = 0; ci < 2; ci++) {
        float4 a = *(const float4*)&sin_[ci][4 * tid];
        float4 c = *(const float4*)&sin_[ci][4 * tid + 4];
        v[ci][0] = a.x; v[ci][1] = a.y; v[ci][2] = a.z; v[ci][3] = a.w;
        v[ci][4] = c.x; v[ci][5] = c.y; v[ci][6] = c.z; v[ci][7] = c.w;
    }

    #pragma unroll 4
    for (int co = 0; co < 32; co++) {
        float acc[4];
        #pragma unroll
        for (int i = 0; i < 4; i++) acc[i] = sb[co];
        #pragma unroll
        for (int ci = 0; ci < 2; ci++)
            #pragma unroll
            for (int k = 0; k < 5; k++) {
                float w = sw[co][ci * 5 + k];
                #pragma unroll
                for (int i = 0; i < 4; i++) acc[i] += w * v[ci][i + k];
            }
        float4 r;
        r.x = fmaxf(acc[0], 0.0f); r.y = fmaxf(acc[1], 0.0f);
        r.z = fmaxf(acc[2], 0.0f); r.w = fmaxf(acc[3], 0.0f);
        *(float4*)&g_h1[(b * 32 + co) * NFP + l0 + 4 * tid] = r;
    }

    if (blockIdx.x == 1 && tid == 0) {
        for (int co = 0; co < 32; co++) {
            float acc = sb[co];
            #pragma unroll
            for (int ci = 0; ci < 2; ci++)
                #pragma unroll
                for (int k = 0; k < 5; k++)
                    acc += sin_[ci][1024 + k] * sw[co][ci * 5 + k];
            g_h1[(b * 32 + co) * NFP + 2048] = fmaxf(acc, 0.0f);
        }
    }
}

// ---------------- 3) gate conv2 (32 -> 64, k5, p2) + mean pool -----------------
__global__ void __launch_bounds__(256, 2)
gconv2_pool_kernel(const float* __restrict__ w2, const float* __restrict__ b2) {
    __shared__ __align__(16) float sin_[16][264];
    __shared__ float sw[64][81];
    int b   = blockIdx.y;
    int l0  = blockIdx.x * 256;
    int tid = threadIdx.x;
    int lane = tid & 31;
    int wid  = tid >> 5;
    bool tail = (blockIdx.x == 7) && (tid < 64);

    float acc[8][8];
    #pragma unroll
    for (int j = 0; j < 8; j++)
        #pragma unroll
        for (int i = 0; i < 8; i++) acc[j][i] = 0.0f;
    float tacc = 0.0f;

    for (int cb = 0; cb < 2; cb++) {
        __syncthreads();
        for (int i = tid; i < 16 * 261; i += 256) {
            int ci = i / 261, j = i % 261;
            int g = l0 + j - 2;
            sin_[ci][j] = (g >= 0 && g < NF) ? g_h1[(b * 32 + cb * 16 + ci) * NFP + g] : 0.0f;
        }
        for (int i = tid; i < 64 * 80; i += 256) {
            int co = i / 80, r = i % 80;
            sw[co][r] = w2[co * 160 + cb * 80 + r];
        }
        __syncthreads();

        #pragma unroll 1
        for (int ci = 0; ci < 16; ci++) {
            float4 a = *(const float4*)&sin_[ci][8 * lane];
            float4 c = *(const float4*)&sin_[ci][8 * lane + 4];
            float4 d = *(const float4*)&sin_[ci][8 * lane + 8];
            float v[12] = {a.x,a.y,a.z,a.w, c.x,c.y,c.z,c.w, d.x,d.y,d.z,d.w};
            #pragma unroll
            for (int j = 0; j < 8; j++) {
                #pragma unroll
                for (int k = 0; k < 5; k++) {
                    float w = sw[wid * 8 + j][ci * 5 + k];
                    #pragma unroll
                    for (int i = 0; i < 8; i++)
                        acc[j][i] += w * v[i + k];
                }
            }
        }
        if (tail) {
            #pragma unroll 1
            for (int ci = 0; ci < 16; ci++)
                #pragma unroll
                for (int k = 0; k < 5; k++)
                    tacc += sin_[ci][256 + k] * sw[tid][ci * 5 + k];
        }
    }

    #pragma unroll
    for (int j = 0; j < 8; j++) {
        int co = wid * 8 + j;
        float bias = b2[co];
        float p = 0.0f;
        #pragma unroll
        for (int i = 0; i < 8; i++)
            p += fmaxf(acc[j][i] + bias, 0.0f);
        #pragma unroll
        for (int off = 16; off; off >>= 1)
            p += __shfl_down_sync(0xffffffffu, p, off, 32);
        if (lane == 0) atomicAdd(&g_pooled[b * 64 + co], p);
    }
    if (tail)
        atomicAdd(&g_pooled[b * 64 + tid], fmaxf(tacc + b2[tid], 0.0f));
}

// ---------------- 4) router MLP + softmax + top2 + aux accumulation ------------
__global__ void gate_mlp_kernel(const float* __restrict__ w1, const float* __restrict__ b1,
                                const float* __restrict__ w2, const float* __restrict__ b2) {
    __shared__ float sp[64];
    __shared__ float sh[128];
    __shared__ float slg[8];
    int b = blockIdx.x;
    int j = threadIdx.x;

    if (j < 64) sp[j] = g_pooled[b * 64 + j] * (1.0f / 2049.0f);
    __syncthreads();

    {
        const float* wr = w1 + j * 64;
        float h0 = 0.f, h1 = 0.f, h2 = 0.f, h3 = 0.f;
        #pragma unroll
        for (int i = 0; i < 64; i += 4) {
            h0 += sp[i + 0] * wr[i + 0];
            h1 += sp[i + 1] * wr[i + 1];
            h2 += sp[i + 2] * wr[i + 2];
            h3 += sp[i + 3] * wr[i + 3];
        }
        sh[j] = fmaxf((h0 + h1) + (h2 + h3) + b1[j], 0.0f);
    }
    __syncthreads();

    if (j < 8) {
        float acc = b2[j];
        const float* wr = w2 + j * 128;
        #pragma unroll 8
        for (int i = 0; i < 128; i++) acc += sh[i] * wr[i];
        slg[j] = acc;
    }
    __syncthreads();

    if (j == 0) {
        float lg[8];
        #pragma unroll
        for (int e = 0; e < 8; e++) lg[e] = slg[e];
        float m = lg[0];
        #pragma unroll
        for (int e = 1; e < 8; e++) m = fmaxf(m, lg[e]);
        float rw[8], s = 0.0f;
        #pragma unroll
        for (int e = 0; e < 8; e++) { rw[e] = expf(lg[e] - m); s += rw[e]; }
        float invs = 1.0f / s;
        #pragma unroll
        for (int e = 0; e < 8; e++) rw[e] *= invs;

        int i0 = 0;
        #pragma unroll
        for (int e = 1; e < 8; e++) if (rw[e] > rw[i0]) i0 = e;
        int i1 = (i0 == 0) ? 1 : 0;
        #pragma unroll
        for (int e = 0; e < 8; e++) if (e != i1 && e != i0 && rw[e] > rw[i1]) i1 = e;

        float t0 = rw[i0], t1 = rw[i1];
        float tn = 1.0f / (t0 + t1);
        g_ti[b * 2 + 0] = i0; g_ti[b * 2 + 1] = i1;
        g_tw[b * 2 + 0] = t0 * tn; g_tw[b * 2 + 1] = t1 * tn;

        #pragma unroll
        for (int e = 0; e < 8; e++) {
            atomicAdd(&g_srw[e], rw[e]);
            atomicAdd(&g_slg[e], lg[e]);
        }
    }
}

// ---------------- 5) expert conv1: (2 -> 64), k=7, s=2, p=3, relu --------------
// Outputs rounded to tf32 (rna) so econv2's tf32 MMA sees exactly-rounded B.
__global__ void econv1_kernel(const float* __restrict__ ew1, const float* __restrict__ eb1) {
    __shared__ __align__(16) float sin_[2][2056];
    __shared__ float sw[64][16];
    __shared__ float sb[64];
    int t = blockIdx.x;
    int b = t >> 1;
    int e = g_ti[t];
    int tid = threadIdx.x;   // 256

    for (int i = tid; i < 2 * 2056; i += 256) {
        int ci = i / 2056, j = i % 2056;
        int g = j - 3;
        sin_[ci][j] = (g >= 0 && g < NF) ? g_fft[(b * 2 + ci) * NF + g] : 0.0f;
    }
    for (int i = tid; i < 64 * 14; i += 256) sw[i / 14][i % 14] = ew1[e * 896 + i];
    if (tid < 64) sb[tid] = eb1[e * 64 + tid];
    __syncthreads();

    float v[2][16];
    #pragma unroll
    for (int ci = 0; ci < 2; ci++) {
        float4 a = *(const float4*)&sin_[ci][8 * tid];
        float4 c = *(const float4*)&sin_[ci][8 * tid + 4];
        float4 d = *(const float4*)&sin_[ci][8 * tid + 8];
        float4 f = *(const float4*)&sin_[ci][8 * tid + 12];
        v[ci][0]=a.x;  v[ci][1]=a.y;  v[ci][2]=a.z;  v[ci][3]=a.w;
        v[ci][4]=c.x;  v[ci][5]=c.y;  v[ci][6]=c.z;  v[ci][7]=c.w;
        v[ci][8]=d.x;  v[ci][9]=d.y;  v[ci][10]=d.z; v[ci][11]=d.w;
        v[ci][12]=f.x; v[ci][13]=f.y; v[ci][14]=f.z; v[ci][15]=f.w;
    }

    #pragma unroll 2
    for (int co = 0; co < 64; co++) {
        float acc[4];
        #pragma unroll
        for (int i = 0; i < 4; i++) acc[i] = sb[co];
        #pragma unroll
        for (int ci = 0; ci < 2; ci++)
            #pragma unroll
            for (int k = 0; k < 7; k++) {
                float w = sw[co][ci * 7 + k];
                #pragma unroll
                for (int i = 0; i < 4; i++) acc[i] += w * v[ci][2 * i + k];
            }
        float4 r;
        r.x = tf32r(fmaxf(acc[0], 0.0f)); r.y = tf32r(fmaxf(acc[1], 0.0f));
        r.z = tf32r(fmaxf(acc[2], 0.0f)); r.w = tf32r(fmaxf(acc[3], 0.0f));
        *(float4*)&g_e1[((size_t)t * 64 + co) * L1P + 4 * tid] = r;
    }

    if (tid < 64) {
        int co = tid;
        float acc = sb[co];
        #pragma unroll
        for (int ci = 0; ci < 2; ci++)
            #pragma unroll
            for (int k = 0; k < 7; k++)
                acc += sin_[ci][2048 + k] * sw[co][ci * 7 + k];
        g_e1[((size_t)t * 64 + co) * L1P + 1024] = tf32r(fmaxf(acc, 0.0f));
    }
}

// ---------------- 6) expert conv2 via TF32 mma.sync ----------------------------
// D[co,l] = relu(sum_{ci,k} W[co,ci,k] * X[ci, 2l+k-2]) ; M=co64/block, N=l128, K=320.
// 4 ci-chunks of 16 (K-chunk 80 = 10 k-steps of 8, shift-major).
// X via cp.async ([16][264] pitch, col j <-> pos 2*l0-2+j); W via cp.async in
// native [co][80] layout ([64][81] pitch) + in-smem rna conversion pass.
#define E2T_SX_STRIDE (16 * 264)
#define E2T_SW_STRIDE (64 * 81)
#define E2T_SMEM ((2 * E2T_SX_STRIDE + 2 * E2T_SW_STRIDE) * 4)
__global__ void __launch_bounds__(256, 2)
econv2_tf32_kernel(const float* __restrict__ ew2, const float* __restrict__ eb2) {
    extern __shared__ __align__(16) float dyn2[];
    float* sxb = dyn2;                         // 2 x [16][264]
    float* swb = dyn2 + 2 * E2T_SX_STRIDE;     // 2 x [64][81]
    int t  = blockIdx.z;
    int e  = g_ti[t];
    int l0 = blockIdx.x * 128;
    int cgrp = blockIdx.y;                     // co base = cgrp*64
    int tid = threadIdx.x;
    int lane = tid & 31;
    int w    = tid >> 5;
    int wc   = w & 3;                          // co subtile (16 rows)
    int wn   = w >> 2;                         // n half (64 cols)
    int g    = lane >> 2;
    int tg   = lane & 3;
    bool tail = (blockIdx.x == 3) && (tid < 64);

    const float* e1base = g_e1 + (size_t)t * 64 * L1P;
    const float* wbase  = ew2 + (size_t)(e * 128 + cgrp * 64) * 320;

    auto prefetch = [&](int p, int cb) {
        float* sx = sxb + p * E2T_SX_STRIDE;
        for (int i = tid; i < 16 * 261; i += 256) {
            int ci = i / 261, j = i % 261;
            int pos = 2 * l0 - 2 + j;
            bool ok = (pos >= 0 && pos < L1E);
            cp4z(s2u(&sx[ci * 264 + j]),
                 e1base + (size_t)(cb * 16 + ci) * L1P + (ok ? pos : 0), ok);
        }
        float* sw = swb + p * E2T_SW_STRIDE;
        for (int i = tid; i < 64 * 80; i += 256) {
            int co = i / 80, r = i % 80;
            cp4z(s2u(&sw[co * 81 + r]), wbase + (size_t)co * 320 + cb * 80 + r, true);
        }
    };
    auto convW = [&](int p) {
        float* sw = swb + p * E2T_SW_STRIDE;
        #pragma unroll
        for (int n = 0; n < 20; n++) {
            int i = n * 256 + tid;
            int co = i / 80, r = i % 80;
            sw[co * 81 + r] = tf32r(sw[co * 81 + r]);
        }
    };

    float acc[8][4];
    #pragma unroll
    for (int nt = 0; nt < 8; nt++)
        #pragma unroll
        for (int i = 0; i < 4; i++) acc[nt][i] = 0.0f;
    float tacc = 0.0f;

    prefetch(0, 0); cp_commit();
    prefetch(1, 1); cp_commit();

    for (int cb = 0; cb < 4; cb++) {
        int p = cb & 1;
        cp_wait<1>();
        __syncthreads();
        convW(p);
        __syncthreads();
        const float* X = sxb + p * E2T_SX_STRIDE;
        const float* W = swb + p * E2T_SW_STRIDE;

        #pragma unroll 1
        for (int ks = 0; ks < 10; ks++) {
            int shift = ks >> 1;
            int cik   = (ks & 1) * 8;
            const float* wr = W + (wc * 16 + g) * 81 + (cik + tg) * 5 + shift;
            uint32_t a0 = __float_as_uint(wr[0]);
            uint32_t a1 = __float_as_uint(wr[8 * 81]);
            uint32_t a2 = __float_as_uint(wr[20]);
            uint32_t a3 = __float_as_uint(wr[8 * 81 + 20]);
            const float* x0 = X + (cik + tg) * 264 + 2 * (wn * 64 + g) + shift;
            const float* x1 = x0 + 4 * 264;
            #pragma unroll
            for (int nt = 0; nt < 8; nt++) {
                uint32_t b0 = __float_as_uint(x0[nt * 16]);
                uint32_t b1 = __float_as_uint(x1[nt * 16]);
                asm volatile(
                    "mma.sync.aligned.m16n8k8.row.col.f32.tf32.tf32.f32 "
                    "{%0,%1,%2,%3}, {%4,%5,%6,%7}, {%8,%9}, {%0,%1,%2,%3};"
                    : "+f"(acc[nt][0]), "+f"(acc[nt][1]),
                      "+f"(acc[nt][2]), "+f"(acc[nt][3])
                    : "r"(a0), "r"(a1), "r"(a2), "r"(a3), "r"(b0), "r"(b1));
            }
        }
        if (tail) {
            // l = 512: pos = 1022+k -> j = 256+k (l0 = 384)
            #pragma unroll 1
            for (int ci = 0; ci < 16; ci++)
                #pragma unroll
                for (int k = 0; k < 5; k++)
                    tacc += X[ci * 264 + 256 + k] * W[tid * 81 + ci * 5 + k];
        }
        __syncthreads();
        if (cb + 2 < 4) prefetch(p, cb + 2);
        cp_commit();
    }

    int co_a = cgrp * 64 + wc * 16 + g;
    int co_b = co_a + 8;
    float bias_a = eb2[e * 128 + co_a];
    float bias_b = eb2[e * 128 + co_b];
    float* outa = &g_e2[((size_t)t * 128 + co_a) * L2P];
    float* outb = &g_e2[((size_t)t * 128 + co_b) * L2P];
    #pragma unroll
    for (int nt = 0; nt < 8; nt++) {
        int l = l0 + wn * 64 + nt * 8 + 2 * tg;
        float2 ra, rb;
        ra.x = tf32r(fmaxf(acc[nt][0] + bias_a, 0.0f));
        ra.y = tf32r(fmaxf(acc[nt][1] + bias_a, 0.0f));
        rb.x = tf32r(fmaxf(acc[nt][2] + bias_b, 0.0f));
        rb.y = tf32r(fmaxf(acc[nt][3] + bias_b, 0.0f));
        *(float2*)(outa + l) = ra;
        *(float2*)(outb + l) = rb;
    }
    if (tail) {
        int co = cgrp * 64 + tid;
        g_e2[((size_t)t * 128 + co) * L2P + 512] = tf32r(fmaxf(tacc + eb2[e * 128 + co], 0.0f));
    }
}

// ---------------- 7) expert conv3 via TF32 mma.sync ----------------------------
// Weights now cp.async'd coalesced in native [co][96] layout ([64][97] pitch);
// transpose absorbed into A-fragment index math; in-smem rna conversion pass.
#define E3T_SX_STRIDE (32 * 136)
#define E3T_SW_STRIDE (64 * 97)
#define E3T_SMEM ((2 * E3T_SX_STRIDE + 2 * E3T_SW_STRIDE) * 4)
__global__ void __launch_bounds__(256, 2)
econv3_tf32_kernel(const float* __restrict__ ew3, const float* __restrict__ eb3) {
    extern __shared__ __align__(16) float dyn3[];
    float* sxb = dyn3;                         // 2 x [32][136], col j <-> l = l0-1+j
    float* swb = dyn3 + 2 * E3T_SX_STRIDE;     // 2 x [64][97], row co, col ci*3+shift
    int t  = blockIdx.z;
    int e  = g_ti[t];
    int l0 = blockIdx.x * 128;
    int cgrp = blockIdx.y;
    int tid = threadIdx.x;
    int lane = tid & 31;
    int w    = tid >> 5;
    int wc   = w & 3;
    int wn   = w >> 2;
    int g    = lane >> 2;
    int tg   = lane & 3;
    bool tail = (blockIdx.x == 3) && (tid < 64);

    const float* e2base = g_e2 + (size_t)t * 128 * L2P;
    const float* wbase  = ew3 + (size_t)(e * 128 + cgrp * 64) * 384;

    auto prefetch = [&](int p, int cb) {
        float* sx = sxb + p * E3T_SX_STRIDE;
        for (int i = tid; i < 32 * 131; i += 256) {
            int ci = i / 131, j = i % 131;
            int l = l0 - 1 + j;
            bool ok = (l >= 0 && l < L2E);
            cp4z(s2u(&sx[ci * 136 + j]),
                 e2base + (size_t)(cb * 32 + ci) * L2P + (ok ? l : 0), ok);
        }
        float* sw = swb + p * E3T_SW_STRIDE;
        for (int i = tid; i < 64 * 96; i += 256) {
            int co = i / 96, r = i % 96;
            cp4z(s2u(&sw[co * 97 + r]), wbase + (size_t)co * 384 + cb * 96 + r, true);
        }
    };
    auto convW = [&](int p) {
        float* sw = swb + p * E3T_SW_STRIDE;
        #pragma unroll
        for (int n = 0; n < 24; n++) {
            int i = n * 256 + tid;
            int co = i / 96, r = i % 96;
            sw[co * 97 + r] = tf32r(sw[co * 97 + r]);
        }
    };

    float acc[8][4];
    #pragma unroll
    for (int nt = 0; nt < 8; nt++)
        #pragma unroll
        for (int i = 0; i < 4; i++) acc[nt][i] = 0.0f;
    float tacc = 0.0f;

    prefetch(0, 0); cp_commit();
    prefetch(1, 1); cp_commit();

    for (int cb = 0; cb < 4; cb++) {
        int p = cb & 1;
        cp_wait<1>();
        __syncthreads();
        convW(p);
        __syncthreads();
        const float* X = sxb + p * E3T_SX_STRIDE;
        const float* W = swb + p * E3T_SW_STRIDE;

        #pragma unroll 1
        for (int ks = 0; ks < 12; ks++) {
            int shift = ks >> 2;
            int cik   = (ks & 3) * 8;
            const float* wr = W + (wc * 16 + g) * 97 + (cik + tg) * 3 + shift;
            uint32_t a0 = __float_as_uint(wr[0]);
            uint32_t a1 = __float_as_uint(wr[8 * 97]);
            uint32_t a2 = __float_as_uint(wr[12]);
            uint32_t a3 = __float_as_uint(wr[8 * 97 + 12]);
            const float* x0 = X + (cik + tg) * 136 + wn * 64 + g + shift;
            const float* x1 = x0 + 4 * 136;
            #pragma unroll
            for (int nt = 0; nt < 8; nt++) {
                uint32_t b0 = __float_as_uint(x0[nt * 8]);
                uint32_t b1 = __float_as_uint(x1[nt * 8]);
                asm volatile(
                    "mma.sync.aligned.m16n8k8.row.col.f32.tf32.tf32.f32 "
                    "{%0,%1,%2,%3}, {%4,%5,%6,%7}, {%8,%9}, {%0,%1,%2,%3};"
                    : "+f"(acc[nt][0]), "+f"(acc[nt][1]),
                      "+f"(acc[nt][2]), "+f"(acc[nt][3])
                    : "r"(a0), "r"(a1), "r"(a2), "r"(a3), "r"(b0), "r"(b1));
            }
        }
        if (tail) {
            // l = 512: j = 128 + sh (l0 = 384)
            #pragma unroll 1
            for (int ci = 0; ci < 32; ci++)
                #pragma unroll
                for (int sh = 0; sh < 3; sh++)
                    tacc += X[ci * 136 + 128 + sh] * W[tid * 97 + ci * 3 + sh];
        }
        __syncthreads();
        if (cb + 2 < 4) prefetch(p, cb + 2);
        cp_commit();
    }

    int co_a = cgrp * 64 + wc * 16 + g;
    int co_b = co_a + 8;
    float bias_a = eb3[e * 128 + co_a];
    float bias_b = eb3[e * 128 + co_b];
    float* outa = &g_e3[((size_t)t * 128 + co_a) * L2P];
    float* outb = &g_e3[((size_t)t * 128 + co_b) * L2P];
    #pragma unroll
    for (int nt = 0; nt < 8; nt++) {
        int l = l0 + wn * 64 + nt * 8 + 2 * tg;
        float2 ra, rb;
        ra.x = fmaxf(acc[nt][0] + bias_a, 0.0f);
        ra.y = fmaxf(acc[nt][1] + bias_a, 0.0f);
        rb.x = fmaxf(acc[nt][2] + bias_b, 0.0f);
        rb.y = fmaxf(acc[nt][3] + bias_b, 0.0f);
        *(float2*)(outa + l) = ra;
        *(float2*)(outb + l) = rb;
    }
    if (tail) {
        int co = cgrp * 64 + tid;
        g_e3[((size_t)t * 128 + co) * L2P + 512] = fmaxf(tacc + eb3[e * 128 + co], 0.0f);
    }
}

// ---------------- 8) top-2 combine + adaptive max-pool + aux finalize ----------
__global__ void pool_kernel(float* __restrict__ out, int out_size) {
    int idx = blockIdx.x * blockDim.x + threadIdx.x;
    if (idx == 0) {
        float aux = 0.0f;
        #pragma unroll
        for (int e = 0; e < 8; e++)
            aux += (g_srw[e] * (1.0f / 128.0f)) * (g_slg[e] * (1.0f / 128.0f));
        out[out_size - 1] = 0.01f * 8.0f * aux;
    }
    if (idx >= B * 128 * 256) return;
    int o  = idx & 255;
    int co = (idx >> 8) & 127;
    int b  = idx >> 15;
    float w0 = g_tw[b * 2 + 0];
    float w1 = g_tw[b * 2 + 1];
    const float* p0 = g_e3 + ((size_t)(b * 2 + 0) * 128 + co) * L2P;
    const float* p1 = g_e3 + ((size_t)(b * 2 + 1) * 128 + co) * L2P;
    int s  = (o * 513) >> 8;
    int en = (o * 513 + 513 + 255) >> 8;
    float m = -INFINITY;
    for (int l = s; l < en; l++)
        m = fmaxf(m, w0 * p0[l] + w1 * p1[l]);
    out[idx] = m;
}

// ---------------- launch --------------------------------------------------------
extern "C" void kernel_launch(void* const* d_in, const int* in_sizes, int n_in,
                              void* d_out, int out_size) {
    const float* x    = (const float*)d_in[0];
    const float* gw1  = (const float*)d_in[1];
    const float* gb1  = (const float*)d_in[2];
    const float* gw2  = (const float*)d_in[3];
    const float* gb2  = (const float*)d_in[4];
    const float* mw1  = (const float*)d_in[5];
    const float* mb1  = (const float*)d_in[6];
    const float* mw2  = (const float*)d_in[7];
    const float* mb2  = (const float*)d_in[8];
    const float* ew1  = (const float*)d_in[9];
    const float* eb1  = (const float*)d_in[10];
    const float* ew2  = (const float*)d_in[11];
    const float* eb2  = (const float*)d_in[12];
    const float* ew3  = (const float*)d_in[13];
    const float* eb3  = (const float*)d_in[14];
    float* out = (float*)d_out;

    static int attr_done = 0;
    if (!attr_done) {
        cudaFuncSetAttribute(econv2_tf32_kernel, cudaFuncAttributeMaxDynamicSharedMemorySize, E2T_SMEM);
        cudaFuncSetAttribute(econv3_tf32_kernel, cudaFuncAttributeMaxDynamicSharedMemorySize, E3T_SMEM);
        attr_done = 1;
    }

    fft_kernel<<<B, 512>>>(x);
    gconv1_kernel<<<dim3(2, B), 256>>>(gw1, gb1);
    gconv2_pool_kernel<<<dim3(8, B), 256>>>(gw2, gb2);
    gate_mlp_kernel<<<B, 128>>>(mw1, mb1, mw2, mb2);
    econv1_kernel<<<NTASK, 256>>>(ew1, eb1);
    econv2_tf32_kernel<<<dim3(4, 2, NTASK), 256, E2T_SMEM>>>(ew2, eb2);
    econv3_tf32_kernel<<<dim3(4, 2, NTASK), 256, E3T_SMEM>>>(ew3, eb3);
    pool_kernel<<<16384, 256>>>(out, out_size);
}

// round 13
// speedup vs baseline: 2.8173x; 1.1874x over previous
#include <cuda_runtime.h>
#include <math.h>
#include <stdint.h>

#define B 128
#define LSEQ 4096
#define NF 2049          // rfft bins
#define NFP 2052         // padded row stride for g_h1
#define L1E 1025         // expert conv1 out length
#define L1P 1028
#define L2E 513          // expert conv2/conv3 out length
#define L2P 516
#define NTASK 256        // B * TOP_K

// ---------------- cp.async helpers --------------------------------------------
__device__ __forceinline__ uint32_t s2u(const void* p) {
    return (uint32_t)__cvta_generic_to_shared(p);
}
// 16B cp.async with variable valid-prefix (zero-fills the rest)
__device__ __forceinline__ void cp16z(uint32_t saddr, const void* g, int src_bytes) {
    asm volatile("cp.async.ca.shared.global [%0], [%1], 16, %2;"
                 :: "r"(saddr), "l"(g), "r"(src_bytes));
}
__device__ __forceinline__ void cp_commit() {
    asm volatile("cp.async.commit_group;");
}
template <int N>
__device__ __forceinline__ void cp_wait() {
    asm volatile("cp.async.wait_group %0;" :: "n"(N));
}
// round fp32 -> tf32 (rna), returned as fp32 bit pattern
__device__ __forceinline__ float tf32r(float x) {
    uint32_t u;
    asm("cvt.rna.tf32.f32 %0, %1;" : "=r"(u) : "f"(x));
    return __uint_as_float(u);
}

// ---------------- scratch (device globals) -------------------------------------
__device__ float g_fft[B * 2 * NF];
__device__ float g_h1 [B * 32 * NFP];
__device__ float g_pooled[B * 64];
__device__ float g_tw[NTASK];
__device__ int   g_ti[NTASK];
__device__ float g_srw[8];
__device__ float g_slg[8];
__device__ float g_e1[NTASK * 64  * L1P];
__device__ float g_e2[NTASK * 128 * L2P];
__device__ float g_e3[NTASK * 128 * L2P];

// ---------------- 1) Hann window + 4096-pt radix-2 FFT + zero accumulators -----
__global__ void fft_kernel(const float* __restrict__ x) {
    __shared__ float re[4096];
    __shared__ float im[4096];
    __shared__ float twr[2048];
    __shared__ float twi[2048];
    int b = blockIdx.x;
    const float* xb = x + b * LSEQ;

    if (threadIdx.x < 64) g_pooled[b * 64 + threadIdx.x] = 0.0f;
    if (b == 0 && threadIdx.x >= 64 && threadIdx.x < 72) {
        g_srw[threadIdx.x - 64] = 0.0f;
        g_slg[threadIdx.x - 64] = 0.0f;
    }

    for (int i = threadIdx.x; i < 2048; i += blockDim.x) {
        float si, sr;
        sincospif(-(float)i * (1.0f / 2048.0f), &si, &sr);
        twr[i] = sr; twi[i] = si;
    }
    for (int i = threadIdx.x; i < 4096; i += blockDim.x) {
        float w = 0.5f * (1.0f - cospif((float)i * (1.0f / 2048.0f)));
        int j = __brev((unsigned)i) >> 20;
        re[j] = xb[i] * w;
        im[j] = 0.0f;
    }
    __syncthreads();

    for (int s = 1; s <= 12; s++) {
        int half = 1 << (s - 1);
        int len  = 1 << s;
        int shft = 12 - s;
        for (int t = threadIdx.x; t < 2048; t += blockDim.x) {
            int g   = t >> (s - 1);
            int pos = t & (half - 1);
            int i0  = g * len + pos;
            int i1  = i0 + half;
            int j   = pos << shft;
            float sr = twr[j], si = twi[j];
            float ar = re[i1], ai = im[i1];
            float tr = ar * sr - ai * si;
            float ti = ar * si + ai * sr;
            float br = re[i0], bi = im[i0];
            re[i1] = br - tr; im[i1] = bi - ti;
            re[i0] = br + tr; im[i0] = bi + ti;
        }
        __syncthreads();
    }
    const float sc = 1.0f / 64.0f;
    for (int f = threadIdx.x; f < NF; f += blockDim.x) {
        g_fft[(b * 2 + 0) * NF + f] = re[f] * sc;
        g_fft[(b * 2 + 1) * NF + f] = im[f] * sc;
    }
}

// ---------------- 2) gate conv1: (2 -> 32), k=5, s=1, p=2, relu ----------------
__global__ void gconv1_kernel(const float* __restrict__ w1, const float* __restrict__ b1) {
    __shared__ __align__(16) float sin_[2][1036];
    __shared__ float sw[32][11];
    __shared__ float sb[32];
    int b  = blockIdx.y;
    int l0 = blockIdx.x * 1024;
    int tid = threadIdx.x;   // 256

    for (int i = tid; i < 2 * 1032; i += 256) {
        int ci = i / 1032, j = i % 1032;
        int g = l0 + j - 2;
        sin_[ci][j] = (g >= 0 && g < NF) ? g_fft[(b * 2 + ci) * NF + g] : 0.0f;
    }
    for (int i = tid; i < 320; i += 256) sw[i / 10][i % 10] = w1[i];
    if (tid < 32) sb[tid] = b1[tid];
    __syncthreads();

    float v[2][8];
    #pragma unroll
    for (int ci = 0; ci < 2; ci++) {
        float4 a = *(const float4*)&sin_[ci][4 * tid];
        float4 c = *(const float4*)&sin_[ci][4 * tid + 4];
        v[ci][0] = a.x; v[ci][1] = a.y; v[ci][2] = a.z; v[ci][3] = a.w;
        v[ci][4] = c.x; v[ci][5] = c.y; v[ci][6] = c.z; v[ci][7] = c.w;
    }

    #pragma unroll 4
    for (int co = 0; co < 32; co++) {
        float acc[4];
        #pragma unroll
        for (int i = 0; i < 4; i++) acc[i] = sb[co];
        #pragma unroll
        for (int ci = 0; ci < 2; ci++)
            #pragma unroll
            for (int k = 0; k < 5; k++) {
                float w = sw[co][ci * 5 + k];
                #pragma unroll
                for (int i = 0; i < 4; i++) acc[i] += w * v[ci][i + k];
            }
        float4 r;
        r.x = fmaxf(acc[0], 0.0f); r.y = fmaxf(acc[1], 0.0f);
        r.z = fmaxf(acc[2], 0.0f); r.w = fmaxf(acc[3], 0.0f);
        *(float4*)&g_h1[(b * 32 + co) * NFP + l0 + 4 * tid] = r;
    }

    if (blockIdx.x == 1 && tid == 0) {
        for (int co = 0; co < 32; co++) {
            float acc = sb[co];
            #pragma unroll
            for (int ci = 0; ci < 2; ci++)
                #pragma unroll
                for (int k = 0; k < 5; k++)
                    acc += sin_[ci][1024 + k] * sw[co][ci * 5 + k];
            g_h1[(b * 32 + co) * NFP + 2048] = fmaxf(acc, 0.0f);
        }
    }
}

// ---------------- 3) gate conv2 (32 -> 64, k5, p2) + mean pool -----------------
__global__ void __launch_bounds__(256, 2)
gconv2_pool_kernel(const float* __restrict__ w2, const float* __restrict__ b2) {
    __shared__ __align__(16) float sin_[16][264];
    __shared__ float sw[64][81];
    int b   = blockIdx.y;
    int l0  = blockIdx.x * 256;
    int tid = threadIdx.x;
    int lane = tid & 31;
    int wid  = tid >> 5;
    bool tail = (blockIdx.x == 7) && (tid < 64);

    float acc[8][8];
    #pragma unroll
    for (int j = 0; j < 8; j++)
        #pragma unroll
        for (int i = 0; i < 8; i++) acc[j][i] = 0.0f;
    float tacc = 0.0f;

    for (int cb = 0; cb < 2; cb++) {
        __syncthreads();
        for (int i = tid; i < 16 * 261; i += 256) {
            int ci = i / 261, j = i % 261;
            int g = l0 + j - 2;
            sin_[ci][j] = (g >= 0 && g < NF) ? g_h1[(b * 32 + cb * 16 + ci) * NFP + g] : 0.0f;
        }
        for (int i = tid; i < 64 * 80; i += 256) {
            int co = i / 80, r = i % 80;
            sw[co][r] = w2[co * 160 + cb * 80 + r];
        }
        __syncthreads();

        #pragma unroll 1
        for (int ci = 0; ci < 16; ci++) {
            float4 a = *(const float4*)&sin_[ci][8 * lane];
            float4 c = *(const float4*)&sin_[ci][8 * lane + 4];
            float4 d = *(const float4*)&sin_[ci][8 * lane + 8];
            float v[12] = {a.x,a.y,a.z,a.w, c.x,c.y,c.z,c.w, d.x,d.y,d.z,d.w};
            #pragma unroll
            for (int j = 0; j < 8; j++) {
                #pragma unroll
                for (int k = 0; k < 5; k++) {
                    float w = sw[wid * 8 + j][ci * 5 + k];
                    #pragma unroll
                    for (int i = 0; i < 8; i++)
                        acc[j][i] += w * v[i + k];
                }
            }
        }
        if (tail) {
            #pragma unroll 1
            for (int ci = 0; ci < 16; ci++)
                #pragma unroll
                for (int k = 0; k < 5; k++)
                    tacc += sin_[ci][256 + k] * sw[tid][ci * 5 + k];
        }
    }

    #pragma unroll
    for (int j = 0; j < 8; j++) {
        int co = wid * 8 + j;
        float bias = b2[co];
        float p = 0.0f;
        #pragma unroll
        for (int i = 0; i < 8; i++)
            p += fmaxf(acc[j][i] + bias, 0.0f);
        #pragma unroll
        for (int off = 16; off; off >>= 1)
            p += __shfl_down_sync(0xffffffffu, p, off, 32);
        if (lane == 0) atomicAdd(&g_pooled[b * 64 + co], p);
    }
    if (tail)
        atomicAdd(&g_pooled[b * 64 + tid], fmaxf(tacc + b2[tid], 0.0f));
}

// ---------------- 4) router MLP + softmax + top2 + aux accumulation ------------
__global__ void gate_mlp_kernel(const float* __restrict__ w1, const float* __restrict__ b1,
                                const float* __restrict__ w2, const float* __restrict__ b2) {
    __shared__ __align__(16) float sp[64];
    __shared__ __align__(16) float sh[128];
    __shared__ float slg[8];
    int b = blockIdx.x;
    int j = threadIdx.x;

    if (j < 64) sp[j] = g_pooled[b * 64 + j] * (1.0f / 2049.0f);
    __syncthreads();

    {
        const float4* wr = (const float4*)(w1 + j * 64);
        float h0 = 0.f, h1 = 0.f, h2 = 0.f, h3 = 0.f;
        #pragma unroll
        for (int i = 0; i < 16; i++) {
            float4 wv = wr[i];
            float4 pv = *(const float4*)&sp[4 * i];
            h0 += pv.x * wv.x;
            h1 += pv.y * wv.y;
            h2 += pv.z * wv.z;
            h3 += pv.w * wv.w;
        }
        sh[j] = fmaxf((h0 + h1) + (h2 + h3) + b1[j], 0.0f);
    }
    __syncthreads();

    if (j < 8) {
        float acc = b2[j];
        const float4* wr = (const float4*)(w2 + j * 128);
        #pragma unroll
        for (int i = 0; i < 32; i++) {
            float4 wv = wr[i];
            float4 hv = *(const float4*)&sh[4 * i];
            acc += hv.x * wv.x + hv.y * wv.y + hv.z * wv.z + hv.w * wv.w;
        }
        slg[j] = acc;
    }
    __syncthreads();

    if (j == 0) {
        float lg[8];
        #pragma unroll
        for (int e = 0; e < 8; e++) lg[e] = slg[e];
        float m = lg[0];
        #pragma unroll
        for (int e = 1; e < 8; e++) m = fmaxf(m, lg[e]);
        float rw[8], s = 0.0f;
        #pragma unroll
        for (int e = 0; e < 8; e++) { rw[e] = expf(lg[e] - m); s += rw[e]; }
        float invs = 1.0f / s;
        #pragma unroll
        for (int e = 0; e < 8; e++) rw[e] *= invs;

        int i0 = 0;
        #pragma unroll
        for (int e = 1; e < 8; e++) if (rw[e] > rw[i0]) i0 = e;
        int i1 = (i0 == 0) ? 1 : 0;
        #pragma unroll
        for (int e = 0; e < 8; e++) if (e != i1 && e != i0 && rw[e] > rw[i1]) i1 = e;

        float t0 = rw[i0], t1 = rw[i1];
        float tn = 1.0f / (t0 + t1);
        g_ti[b * 2 + 0] = i0; g_ti[b * 2 + 1] = i1;
        g_tw[b * 2 + 0] = t0 * tn; g_tw[b * 2 + 1] = t1 * tn;

        #pragma unroll
        for (int e = 0; e < 8; e++) {
            atomicAdd(&g_srw[e], rw[e]);
            atomicAdd(&g_slg[e], lg[e]);
        }
    }
}

// ---------------- 5) expert conv1: (2 -> 64), k=7, s=2, p=3, relu --------------
// Outputs rounded to tf32 (rna) so econv2's tf32 MMA sees exactly-rounded B.
__global__ void econv1_kernel(const float* __restrict__ ew1, const float* __restrict__ eb1) {
    __shared__ __align__(16) float sin_[2][2056];
    __shared__ float sw[64][16];
    __shared__ float sb[64];
    int t = blockIdx.x;
    int b = t >> 1;
    int e = g_ti[t];
    int tid = threadIdx.x;   // 256

    for (int i = tid; i < 2 * 2056; i += 256) {
        int ci = i / 2056, j = i % 2056;
        int g = j - 3;
        sin_[ci][j] = (g >= 0 && g < NF) ? g_fft[(b * 2 + ci) * NF + g] : 0.0f;
    }
    for (int i = tid; i < 64 * 14; i += 256) sw[i / 14][i % 14] = ew1[e * 896 + i];
    if (tid < 64) sb[tid] = eb1[e * 64 + tid];
    __syncthreads();

    float v[2][16];
    #pragma unroll
    for (int ci = 0; ci < 2; ci++) {
        float4 a = *(const float4*)&sin_[ci][8 * tid];
        float4 c = *(const float4*)&sin_[ci][8 * tid + 4];
        float4 d = *(const float4*)&sin_[ci][8 * tid + 8];
        float4 f = *(const float4*)&sin_[ci][8 * tid + 12];
        v[ci][0]=a.x;  v[ci][1]=a.y;  v[ci][2]=a.z;  v[ci][3]=a.w;
        v[ci][4]=c.x;  v[ci][5]=c.y;  v[ci][6]=c.z;  v[ci][7]=c.w;
        v[ci][8]=d.x;  v[ci][9]=d.y;  v[ci][10]=d.z; v[ci][11]=d.w;
        v[ci][12]=f.x; v[ci][13]=f.y; v[ci][14]=f.z; v[ci][15]=f.w;
    }

    #pragma unroll 2
    for (int co = 0; co < 64; co++) {
        float acc[4];
        #pragma unroll
        for (int i = 0; i < 4; i++) acc[i] = sb[co];
        #pragma unroll
        for (int ci = 0; ci < 2; ci++)
            #pragma unroll
            for (int k = 0; k < 7; k++) {
                float w = sw[co][ci * 7 + k];
                #pragma unroll
                for (int i = 0; i < 4; i++) acc[i] += w * v[ci][2 * i + k];
            }
        float4 r;
        r.x = tf32r(fmaxf(acc[0], 0.0f)); r.y = tf32r(fmaxf(acc[1], 0.0f));
        r.z = tf32r(fmaxf(acc[2], 0.0f)); r.w = tf32r(fmaxf(acc[3], 0.0f));
        *(float4*)&g_e1[((size_t)t * 64 + co) * L1P + 4 * tid] = r;
    }

    if (tid < 64) {
        int co = tid;
        float acc = sb[co];
        #pragma unroll
        for (int ci = 0; ci < 2; ci++)
            #pragma unroll
            for (int k = 0; k < 7; k++)
                acc += sin_[ci][2048 + k] * sw[co][ci * 7 + k];
        g_e1[((size_t)t * 64 + co) * L1P + 1024] = tf32r(fmaxf(acc, 0.0f));
    }
}

// ---------------- 6) expert conv2 via TF32 mma.sync ----------------------------
// X smem: [16][264], col j <-> pos = 2*l0-4+j (16B-granule aligned loads).
// W smem: [64][84] pitch; both staged with 16B cp.async.
#define E2T_SX_STRIDE (16 * 264)
#define E2T_SW_STRIDE (64 * 84)
#define E2T_SMEM ((2 * E2T_SX_STRIDE + 2 * E2T_SW_STRIDE) * 4)
__global__ void __launch_bounds__(256, 2)
econv2_tf32_kernel(const float* __restrict__ ew2, const float* __restrict__ eb2) {
    extern __shared__ __align__(16) float dyn2[];
    float* sxb = dyn2;
    float* swb = dyn2 + 2 * E2T_SX_STRIDE;
    int t  = blockIdx.z;
    int e  = g_ti[t];
    int l0 = blockIdx.x * 128;
    int cgrp = blockIdx.y;
    int tid = threadIdx.x;
    int lane = tid & 31;
    int w    = tid >> 5;
    int wc   = w & 3;
    int wn   = w >> 2;
    int g    = lane >> 2;
    int tg   = lane & 3;
    bool tail = (blockIdx.x == 3) && (tid < 64);

    const float* e1base = g_e1 + (size_t)t * 64 * L1P;
    const float* wbase  = ew2 + (size_t)(e * 128 + cgrp * 64) * 320;

    auto prefetch = [&](int p, int cb) {
        float* sx = sxb + p * E2T_SX_STRIDE;
        // X: 16 rows x 66 granules; pos_start = 2*l0-4+4*jj
        for (int i = tid; i < 16 * 66; i += 256) {
            int ci = i / 66, jj = i % 66;
            int ps = 2 * l0 - 4 + 4 * jj;
            int nf = (ps < 0) ? 0 : min(4, max(0, L1E - ps));
            cp16z(s2u(&sx[ci * 264 + 4 * jj]),
                  e1base + (size_t)(cb * 16 + ci) * L1P + max(ps, 0), 4 * nf);
        }
        float* sw = swb + p * E2T_SW_STRIDE;
        // W: 64 co x 20 granules of chunk cb (80 floats)
        for (int i = tid; i < 64 * 20; i += 256) {
            int co = i / 20, kk = i % 20;
            cp16z(s2u(&sw[co * 84 + 4 * kk]),
                  wbase + (size_t)co * 320 + cb * 80 + 4 * kk, 16);
        }
    };
    auto convW = [&](int p) {
        float* sw = swb + p * E2T_SW_STRIDE;
        #pragma unroll
        for (int n = 0; n < 20; n++) {
            int i = n * 256 + tid;
            int co = i / 80, r = i % 80;
            sw[co * 84 + r] = tf32r(sw[co * 84 + r]);
        }
    };

    float acc[8][4];
    #pragma unroll
    for (int nt = 0; nt < 8; nt++)
        #pragma unroll
        for (int i = 0; i < 4; i++) acc[nt][i] = 0.0f;
    float tacc = 0.0f;

    prefetch(0, 0); cp_commit();
    prefetch(1, 1); cp_commit();

    for (int cb = 0; cb < 4; cb++) {
        int p = cb & 1;
        cp_wait<1>();
        __syncthreads();
        convW(p);
        __syncthreads();
        const float* X = sxb + p * E2T_SX_STRIDE;
        const float* W = swb + p * E2T_SW_STRIDE;

        #pragma unroll 1
        for (int ks = 0; ks < 10; ks++) {
            int shift = ks >> 1;
            int cik   = (ks & 1) * 8;
            const float* wr = W + (wc * 16 + g) * 84 + (cik + tg) * 5 + shift;
            uint32_t a0 = __float_as_uint(wr[0]);
            uint32_t a1 = __float_as_uint(wr[8 * 84]);
            uint32_t a2 = __float_as_uint(wr[20]);
            uint32_t a3 = __float_as_uint(wr[8 * 84 + 20]);
            // j = 2*(l - l0) + shift + 2
            const float* x0 = X + (cik + tg) * 264 + 2 * (wn * 64 + g) + shift + 2;
            const float* x1 = x0 + 4 * 264;
            #pragma unroll
            for (int nt = 0; nt < 8; nt++) {
                uint32_t b0 = __float_as_uint(x0[nt * 16]);
                uint32_t b1 = __float_as_uint(x1[nt * 16]);
                asm volatile(
                    "mma.sync.aligned.m16n8k8.row.col.f32.tf32.tf32.f32 "
                    "{%0,%1,%2,%3}, {%4,%5,%6,%7}, {%8,%9}, {%0,%1,%2,%3};"
                    : "+f"(acc[nt][0]), "+f"(acc[nt][1]),
                      "+f"(acc[nt][2]), "+f"(acc[nt][3])
                    : "r"(a0), "r"(a1), "r"(a2), "r"(a3), "r"(b0), "r"(b1));
            }
        }
        if (tail) {
            // l = 512: pos = 1022+k -> j = 1022 - (2*384-4) + k = 258+k
            #pragma unroll 1
            for (int ci = 0; ci < 16; ci++)
                #pragma unroll
                for (int k = 0; k < 5; k++)
                    tacc += X[ci * 264 + 258 + k] * W[tid * 84 + ci * 5 + k];
        }
        __syncthreads();
        if (cb + 2 < 4) prefetch(p, cb + 2);
        cp_commit();
    }

    int co_a = cgrp * 64 + wc * 16 + g;
    int co_b = co_a + 8;
    float bias_a = eb2[e * 128 + co_a];
    float bias_b = eb2[e * 128 + co_b];
    float* outa = &g_e2[((size_t)t * 128 + co_a) * L2P];
    float* outb = &g_e2[((size_t)t * 128 + co_b) * L2P];
    #pragma unroll
    for (int nt = 0; nt < 8; nt++) {
        int l = l0 + wn * 64 + nt * 8 + 2 * tg;
        float2 ra, rb;
        ra.x = tf32r(fmaxf(acc[nt][0] + bias_a, 0.0f));
        ra.y = tf32r(fmaxf(acc[nt][1] + bias_a, 0.0f));
        rb.x = tf32r(fmaxf(acc[nt][2] + bias_b, 0.0f));
        rb.y = tf32r(fmaxf(acc[nt][3] + bias_b, 0.0f));
        *(float2*)(outa + l) = ra;
        *(float2*)(outb + l) = rb;
    }
    if (tail) {
        int co = cgrp * 64 + tid;
        g_e2[((size_t)t * 128 + co) * L2P + 512] = tf32r(fmaxf(tacc + eb2[e * 128 + co], 0.0f));
    }
}

// ---------------- 7) expert conv3 via TF32 mma.sync ----------------------------
// X smem: [32][136], col j <-> l = l0-4+j (16B-granule aligned loads).
// W smem: [64][100] pitch; both staged with 16B cp.async.
#define E3T_SX_STRIDE (32 * 136)
#define E3T_SW_STRIDE (64 * 100)
#define E3T_SMEM ((2 * E3T_SX_STRIDE + 2 * E3T_SW_STRIDE) * 4)
__global__ void __launch_bounds__(256, 2)
econv3_tf32_kernel(const float* __restrict__ ew3, const float* __restrict__ eb3) {
    extern __shared__ __align__(16) float dyn3[];
    float* sxb = dyn3;
    float* swb = dyn3 + 2 * E3T_SX_STRIDE;
    int t  = blockIdx.z;
    int e  = g_ti[t];
    int l0 = blockIdx.x * 128;
    int cgrp = blockIdx.y;
    int tid = threadIdx.x;
    int lane = tid & 31;
    int w    = tid >> 5;
    int wc   = w & 3;
    int wn   = w >> 2;
    int g    = lane >> 2;
    int tg   = lane & 3;
    bool tail = (blockIdx.x == 3) && (tid < 64);

    const float* e2base = g_e2 + (size_t)t * 128 * L2P;
    const float* wbase  = ew3 + (size_t)(e * 128 + cgrp * 64) * 384;

    auto prefetch = [&](int p, int cb) {
        float* sx = sxb + p * E3T_SX_STRIDE;
        // X: 32 rows x 34 granules; l_start = l0-4+4*jj
        for (int i = tid; i < 32 * 34; i += 256) {
            int ci = i / 34, jj = i % 34;
            int ls = l0 - 4 + 4 * jj;
            int nf = (ls < 0) ? 0 : min(4, max(0, L2E - ls));
            cp16z(s2u(&sx[ci * 136 + 4 * jj]),
                  e2base + (size_t)(cb * 32 + ci) * L2P + max(ls, 0), 4 * nf);
        }
        float* sw = swb + p * E3T_SW_STRIDE;
        // W: 64 co x 24 granules of chunk cb (96 floats)
        for (int i = tid; i < 64 * 24; i += 256) {
            int co = i / 24, kk = i % 24;
            cp16z(s2u(&sw[co * 100 + 4 * kk]),
                  wbase + (size_t)co * 384 + cb * 96 + 4 * kk, 16);
        }
    };
    auto convW = [&](int p) {
        float* sw = swb + p * E3T_SW_STRIDE;
        #pragma unroll
        for (int n = 0; n < 24; n++) {
            int i = n * 256 + tid;
            int co = i / 96, r = i % 96;
            sw[co * 100 + r] = tf32r(sw[co * 100 + r]);
        }
    };

    float acc[8][4];
    #pragma unroll
    for (int nt = 0; nt < 8; nt++)
        #pragma unroll
        for (int i = 0; i < 4; i++) acc[nt][i] = 0.0f;
    float tacc = 0.0f;

    prefetch(0, 0); cp_commit();
    prefetch(1, 1); cp_commit();

    for (int cb = 0; cb < 4; cb++) {
        int p = cb & 1;
        cp_wait<1>();
        __syncthreads();
        convW(p);
        __syncthreads();
        const float* X = sxb + p * E3T_SX_STRIDE;
        const float* W = swb + p * E3T_SW_STRIDE;

        #pragma unroll 1
        for (int ks = 0; ks < 12; ks++) {
            int shift = ks >> 2;
            int cik   = (ks & 3) * 8;
            const float* wr = W + (wc * 16 + g) * 100 + (cik + tg) * 3 + shift;
            uint32_t a0 = __float_as_uint(wr[0]);
            uint32_t a1 = __float_as_uint(wr[8 * 100]);
            uint32_t a2 = __float_as_uint(wr[12]);
            uint32_t a3 = __float_as_uint(wr[8 * 100 + 12]);
            // j = (l - l0) + shift + 3
            const float* x0 = X + (cik + tg) * 136 + wn * 64 + g + shift + 3;
            const float* x1 = x0 + 4 * 136;
            #pragma unroll
            for (int nt = 0; nt < 8; nt++) {
                uint32_t b0 = __float_as_uint(x0[nt * 8]);
                uint32_t b1 = __float_as_uint(x1[nt * 8]);
                asm volatile(
                    "mma.sync.aligned.m16n8k8.row.col.f32.tf32.tf32.f32 "
                    "{%0,%1,%2,%3}, {%4,%5,%6,%7}, {%8,%9}, {%0,%1,%2,%3};"
                    : "+f"(acc[nt][0]), "+f"(acc[nt][1]),
                      "+f"(acc[nt][2]), "+f"(acc[nt][3])
                    : "r"(a0), "r"(a1), "r"(a2), "r"(a3), "r"(b0), "r"(b1));
            }
        }
        if (tail) {
            // l = 512: input l' = 511+sh -> j = 511+sh - (384-4) = 131+sh
            #pragma unroll 1
            for (int ci = 0; ci < 32; ci++)
                #pragma unroll
                for (int sh = 0; sh < 3; sh++)
                    tacc += X[ci * 136 + 131 + sh] * W[tid * 100 + ci * 3 + sh];
        }
        __syncthreads();
        if (cb + 2 < 4) prefetch(p, cb + 2);
        cp_commit();
    }

    int co_a = cgrp * 64 + wc * 16 + g;
    int co_b = co_a + 8;
    float bias_a = eb3[e * 128 + co_a];
    float bias_b = eb3[e * 128 + co_b];
    float* outa = &g_e3[((size_t)t * 128 + co_a) * L2P];
    float* outb = &g_e3[((size_t)t * 128 + co_b) * L2P];
    #pragma unroll
    for (int nt = 0; nt < 8; nt++) {
        int l = l0 + wn * 64 + nt * 8 + 2 * tg;
        float2 ra, rb;
        ra.x = fmaxf(acc[nt][0] + bias_a, 0.0f);
        ra.y = fmaxf(acc[nt][1] + bias_a, 0.0f);
        rb.x = fmaxf(acc[nt][2] + bias_b, 0.0f);
        rb.y = fmaxf(acc[nt][3] + bias_b, 0.0f);
        *(float2*)(outa + l) = ra;
        *(float2*)(outb + l) = rb;
    }
    if (tail) {
        int co = cgrp * 64 + tid;
        g_e3[((size_t)t * 128 + co) * L2P + 512] = fmaxf(tacc + eb3[e * 128 + co], 0.0f);
    }
}

// ---------------- 8) top-2 combine + adaptive max-pool + aux finalize ----------
__global__ void pool_kernel(float* __restrict__ out, int out_size) {
    int idx = blockIdx.x * blockDim.x + threadIdx.x;
    if (idx == 0) {
        float aux = 0.0f;
        #pragma unroll
        for (int e = 0; e < 8; e++)
            aux += (g_srw[e] * (1.0f / 128.0f)) * (g_slg[e] * (1.0f / 128.0f));
        out[out_size - 1] = 0.01f * 8.0f * aux;
    }
    if (idx >= B * 128 * 256) return;
    int o  = idx & 255;
    int co = (idx >> 8) & 127;
    int b  = idx >> 15;
    float w0 = g_tw[b * 2 + 0];
    float w1 = g_tw[b * 2 + 1];
    const float* p0 = g_e3 + ((size_t)(b * 2 + 0) * 128 + co) * L2P;
    const float* p1 = g_e3 + ((size_t)(b * 2 + 1) * 128 + co) * L2P;
    int s  = (o * 513) >> 8;
    int en = (o * 513 + 513 + 255) >> 8;
    float m = -INFINITY;
    for (int l = s; l < en; l++)
        m = fmaxf(m, w0 * p0[l] + w1 * p1[l]);
    out[idx] = m;
}

// ---------------- launch --------------------------------------------------------
extern "C" void kernel_launch(void* const* d_in, const int* in_sizes, int n_in,
                              void* d_out, int out_size) {
    const float* x    = (const float*)d_in[0];
    const float* gw1  = (const float*)d_in[1];
    const float* gb1  = (const float*)d_in[2];
    const float* gw2  = (const float*)d_in[3];
    const float* gb2  = (const float*)d_in[4];
    const float* mw1  = (const float*)d_in[5];
    const float* mb1  = (const float*)d_in[6];
    const float* mw2  = (const float*)d_in[7];
    const float* mb2  = (const float*)d_in[8];
    const float* ew1  = (const float*)d_in[9];
    const float* eb1  = (const float*)d_in[10];
    const float* ew2  = (const float*)d_in[11];
    const float* eb2  = (const float*)d_in[12];
    const float* ew3  = (const float*)d_in[13];
    const float* eb3  = (const float*)d_in[14];
    float* out = (float*)d_out;

    static int attr_done = 0;
    if (!attr_done) {
        cudaFuncSetAttribute(econv2_tf32_kernel, cudaFuncAttributeMaxDynamicSharedMemorySize, E2T_SMEM);
        cudaFuncSetAttribute(econv3_tf32_kernel, cudaFuncAttributeMaxDynamicSharedMemorySize, E3T_SMEM);
        attr_done = 1;
    }

    fft_kernel<<<B, 512>>>(x);
    gconv1_kernel<<<dim3(2, B), 256>>>(gw1, gb1);
    gconv2_pool_kernel<<<dim3(8, B), 256>>>(gw2, gb2);
    gate_mlp_kernel<<<B, 128>>>(mw1, mb1, mw2, mb2);
    econv1_kernel<<<NTASK, 256>>>(ew1, eb1);
    econv2_tf32_kernel<<<dim3(4, 2, NTASK), 256, E2T_SMEM>>>(ew2, eb2);
    econv3_tf32_kernel<<<dim3(4, 2, NTASK), 256, E3T_SMEM>>>(ew3, eb3);
    pool_kernel<<<16384, 256>>>(out, out_size);
}

// round 14
// speedup vs baseline: 3.2605x; 1.1573x over previous
#include <cuda_runtime.h>
#include <math.h>
#include <stdint.h>

#define B 128
#define LSEQ 4096
#define NF 2049          // rfft bins
#define NFP 2052         // padded row stride for g_h1
#define L1E 1025         // expert conv1 out length
#define L1P 1028
#define L2E 513          // expert conv2/conv3 out length
#define L2P 516
#define NTASK 256        // B * TOP_K

// ---------------- cp.async helpers --------------------------------------------
__device__ __forceinline__ uint32_t s2u(const void* p) {
    return (uint32_t)__cvta_generic_to_shared(p);
}
// 16B cp.async with variable valid-prefix (zero-fills the rest)
__device__ __forceinline__ void cp16z(uint32_t saddr, const void* g, int src_bytes) {
    asm volatile("cp.async.ca.shared.global [%0], [%1], 16, %2;"
                 :: "r"(saddr), "l"(g), "r"(src_bytes));
}
__device__ __forceinline__ void cp_commit() {
    asm volatile("cp.async.commit_group;");
}
template <int N>
__device__ __forceinline__ void cp_wait() {
    asm volatile("cp.async.wait_group %0;" :: "n"(N));
}
// round fp32 -> tf32 (rna), returned as fp32 bit pattern
__device__ __forceinline__ float tf32r(float x) {
    uint32_t u;
    asm("cvt.rna.tf32.f32 %0, %1;" : "=r"(u) : "f"(x));
    return __uint_as_float(u);
}

// ---------------- scratch (device globals) -------------------------------------
__device__ float g_fft[B * 2 * NF];
__device__ float g_h1 [B * 32 * NFP];
__device__ float g_pooled[B * 64];
__device__ float g_tw[NTASK];
__device__ int   g_ti[NTASK];
__device__ float g_srw[8];
__device__ float g_slg[8];
__device__ float g_e1[NTASK * 64  * L1P];
__device__ float g_e2[NTASK * 128 * L2P];
__device__ float g_e3[NTASK * 128 * L2P];

// ---------------- 1) Hann window + 4096-pt radix-2 FFT + zero accumulators -----
__global__ void fft_kernel(const float* __restrict__ x) {
    __shared__ float re[4096];
    __shared__ float im[4096];
    __shared__ float twr[2048];
    __shared__ float twi[2048];
    int b = blockIdx.x;
    const float* xb = x + b * LSEQ;

    if (threadIdx.x < 64) g_pooled[b * 64 + threadIdx.x] = 0.0f;
    if (b == 0 && threadIdx.x >= 64 && threadIdx.x < 72) {
        g_srw[threadIdx.x - 64] = 0.0f;
        g_slg[threadIdx.x - 64] = 0.0f;
    }

    for (int i = threadIdx.x; i < 2048; i += blockDim.x) {
        float si, sr;
        sincospif(-(float)i * (1.0f / 2048.0f), &si, &sr);
        twr[i] = sr; twi[i] = si;
    }
    for (int i = threadIdx.x; i < 4096; i += blockDim.x) {
        float w = 0.5f * (1.0f - cospif((float)i * (1.0f / 2048.0f)));
        int j = __brev((unsigned)i) >> 20;
        re[j] = xb[i] * w;
        im[j] = 0.0f;
    }
    __syncthreads();

    for (int s = 1; s <= 12; s++) {
        int half = 1 << (s - 1);
        int len  = 1 << s;
        int shft = 12 - s;
        for (int t = threadIdx.x; t < 2048; t += blockDim.x) {
            int g   = t >> (s - 1);
            int pos = t & (half - 1);
            int i0  = g * len + pos;
            int i1  = i0 + half;
            int j   = pos << shft;
            float sr = twr[j], si = twi[j];
            float ar = re[i1], ai = im[i1];
            float tr = ar * sr - ai * si;
            float ti = ar * si + ai * sr;
            float br = re[i0], bi = im[i0];
            re[i1] = br - tr; im[i1] = bi - ti;
            re[i0] = br + tr; im[i0] = bi + ti;
        }
        __syncthreads();
    }
    const float sc = 1.0f / 64.0f;
    for (int f = threadIdx.x; f < NF; f += blockDim.x) {
        g_fft[(b * 2 + 0) * NF + f] = re[f] * sc;
        g_fft[(b * 2 + 1) * NF + f] = im[f] * sc;
    }
}

// ---------------- 2) gate conv1: (2 -> 32), k=5, s=1, p=2, relu ----------------
// Outputs rounded to tf32 (rna): g_h1 feeds only the tf32 gconv2.
__global__ void gconv1_kernel(const float* __restrict__ w1, const float* __restrict__ b1) {
    __shared__ __align__(16) float sin_[2][1036];
    __shared__ float sw[32][11];
    __shared__ float sb[32];
    int b  = blockIdx.y;
    int l0 = blockIdx.x * 1024;
    int tid = threadIdx.x;   // 256

    for (int i = tid; i < 2 * 1032; i += 256) {
        int ci = i / 1032, j = i % 1032;
        int g = l0 + j - 2;
        sin_[ci][j] = (g >= 0 && g < NF) ? g_fft[(b * 2 + ci) * NF + g] : 0.0f;
    }
    for (int i = tid; i < 320; i += 256) sw[i / 10][i % 10] = w1[i];
    if (tid < 32) sb[tid] = b1[tid];
    __syncthreads();

    float v[2][8];
    #pragma unroll
    for (int ci = 0; ci < 2; ci++) {
        float4 a = *(const float4*)&sin_[ci][4 * tid];
        float4 c = *(const float4*)&sin_[ci][4 * tid + 4];
        v[ci][0] = a.x; v[ci][1] = a.y; v[ci][2] = a.z; v[ci][3] = a.w;
        v[ci][4] = c.x; v[ci][5] = c.y; v[ci][6] = c.z; v[ci][7] = c.w;
    }

    #pragma unroll 4
    for (int co = 0; co < 32; co++) {
        float acc[4];
        #pragma unroll
        for (int i = 0; i < 4; i++) acc[i] = sb[co];
        #pragma unroll
        for (int ci = 0; ci < 2; ci++)
            #pragma unroll
            for (int k = 0; k < 5; k++) {
                float w = sw[co][ci * 5 + k];
                #pragma unroll
                for (int i = 0; i < 4; i++) acc[i] += w * v[ci][i + k];
            }
        float4 r;
        r.x = tf32r(fmaxf(acc[0], 0.0f)); r.y = tf32r(fmaxf(acc[1], 0.0f));
        r.z = tf32r(fmaxf(acc[2], 0.0f)); r.w = tf32r(fmaxf(acc[3], 0.0f));
        *(float4*)&g_h1[(b * 32 + co) * NFP + l0 + 4 * tid] = r;
    }

    if (blockIdx.x == 1 && tid == 0) {
        for (int co = 0; co < 32; co++) {
            float acc = sb[co];
            #pragma unroll
            for (int ci = 0; ci < 2; ci++)
                #pragma unroll
                for (int k = 0; k < 5; k++)
                    acc += sin_[ci][1024 + k] * sw[co][ci * 5 + k];
            g_h1[(b * 32 + co) * NFP + 2048] = tf32r(fmaxf(acc, 0.0f));
        }
    }
}

// ---------------- 3) gate conv2 via TF32 mma + fused mean pool ----------------
// D[co,l] = relu(sum_{ci,k} W[co,ci,k] * X[ci, l+k-2]) ; M=64, N=2049, K=160.
// Grid (16, B); block tile N=128; tail l=2048 by tid<64 of block x=15.
// 2 ci-chunks of 16 (K-chunk 80 = 10 k-steps, shift-major).
// X smem [16][136], col j <-> l = l0-4+j ; W smem [64][84] (same as econv2).
#define G2T_SX_STRIDE (16 * 136)
#define G2T_SW_STRIDE (64 * 84)
#define G2T_SMEM ((2 * G2T_SX_STRIDE + 2 * G2T_SW_STRIDE) * 4)
__global__ void __launch_bounds__(256, 2)
gconv2_tf32_pool_kernel(const float* __restrict__ w2, const float* __restrict__ b2) {
    extern __shared__ __align__(16) float dyng[];
    float* sxb = dyng;
    float* swb = dyng + 2 * G2T_SX_STRIDE;
    int b  = blockIdx.y;
    int l0 = blockIdx.x * 128;
    int tid = threadIdx.x;
    int lane = tid & 31;
    int w    = tid >> 5;
    int wc   = w & 3;
    int wn   = w >> 2;
    int g    = lane >> 2;
    int tg   = lane & 3;
    bool tail = (blockIdx.x == 15) && (tid < 64);

    const float* h1base = g_h1 + (size_t)b * 32 * NFP;

    auto prefetch = [&](int p, int cb) {
        float* sx = sxb + p * G2T_SX_STRIDE;
        // X: 16 rows x 34 granules; l_start = l0-4+4*jj
        for (int i = tid; i < 16 * 34; i += 256) {
            int ci = i / 34, jj = i % 34;
            int ls = l0 - 4 + 4 * jj;
            int nf = (ls < 0) ? 0 : min(4, max(0, NF - ls));
            cp16z(s2u(&sx[ci * 136 + 4 * jj]),
                  h1base + (size_t)(cb * 16 + ci) * NFP + max(ls, 0), 4 * nf);
        }
        float* sw = swb + p * G2T_SW_STRIDE;
        // W: 64 co x 20 granules of chunk cb (80 floats)
        for (int i = tid; i < 64 * 20; i += 256) {
            int co = i / 20, kk = i % 20;
            cp16z(s2u(&sw[co * 84 + 4 * kk]),
                  w2 + (size_t)co * 160 + cb * 80 + 4 * kk, 16);
        }
    };
    auto convW = [&](int p) {
        float* sw = swb + p * G2T_SW_STRIDE;
        #pragma unroll
        for (int n = 0; n < 20; n++) {
            int i = n * 256 + tid;
            int co = i / 80, r = i % 80;
            sw[co * 84 + r] = tf32r(sw[co * 84 + r]);
        }
    };

    float acc[8][4];
    #pragma unroll
    for (int nt = 0; nt < 8; nt++)
        #pragma unroll
        for (int i = 0; i < 4; i++) acc[nt][i] = 0.0f;
    float tacc = 0.0f;

    prefetch(0, 0); cp_commit();
    prefetch(1, 1); cp_commit();

    for (int cb = 0; cb < 2; cb++) {
        int p = cb & 1;
        cp_wait<1>();
        __syncthreads();
        convW(p);
        __syncthreads();
        const float* X = sxb + p * G2T_SX_STRIDE;
        const float* W = swb + p * G2T_SW_STRIDE;

        #pragma unroll 1
        for (int ks = 0; ks < 10; ks++) {
            int shift = ks >> 1;
            int cik   = (ks & 1) * 8;
            const float* wr = W + (wc * 16 + g) * 84 + (cik + tg) * 5 + shift;
            uint32_t a0 = __float_as_uint(wr[0]);
            uint32_t a1 = __float_as_uint(wr[8 * 84]);
            uint32_t a2 = __float_as_uint(wr[20]);
            uint32_t a3 = __float_as_uint(wr[8 * 84 + 20]);
            // j = (l - l0) + shift + 2  (X col j <-> l = l0-4+j, l' = l+shift-2)
            const float* x0 = X + (cik + tg) * 136 + wn * 64 + g + shift + 2;
            const float* x1 = x0 + 4 * 136;
            #pragma unroll
            for (int nt = 0; nt < 8; nt++) {
                uint32_t b0 = __float_as_uint(x0[nt * 8]);
                uint32_t b1 = __float_as_uint(x1[nt * 8]);
                asm volatile(
                    "mma.sync.aligned.m16n8k8.row.col.f32.tf32.tf32.f32 "
                    "{%0,%1,%2,%3}, {%4,%5,%6,%7}, {%8,%9}, {%0,%1,%2,%3};"
                    : "+f"(acc[nt][0]), "+f"(acc[nt][1]),
                      "+f"(acc[nt][2]), "+f"(acc[nt][3])
                    : "r"(a0), "r"(a1), "r"(a2), "r"(a3), "r"(b0), "r"(b1));
            }
        }
        if (tail) {
            // l = 2048: input l' = 2046+k -> j = 2046+k - (1920-4) = 130+k
            #pragma unroll 1
            for (int ci = 0; ci < 16; ci++)
                #pragma unroll
                for (int k = 0; k < 5; k++)
                    tacc += X[ci * 136 + 130 + k] * W[tid * 84 + ci * 5 + k];
        }
        __syncthreads();
        // keep the commit-group cadence (empty commit on last iters)
        cp_commit();
    }

    // fused mean-pool epilogue: relu + sum over this thread's l-values,
    // reduce over tg within the quad, atomicAdd per (b, co).
    int co_a = wc * 16 + g;
    int co_b = co_a + 8;
    float bias_a = b2[co_a];
    float bias_b = b2[co_b];
    float pa = 0.0f, pb = 0.0f;
    #pragma unroll
    for (int nt = 0; nt < 8; nt++) {
        pa += fmaxf(acc[nt][0] + bias_a, 0.0f) + fmaxf(acc[nt][1] + bias_a, 0.0f);
        pb += fmaxf(acc[nt][2] + bias_b, 0.0f) + fmaxf(acc[nt][3] + bias_b, 0.0f);
    }
    pa += __shfl_xor_sync(0xffffffffu, pa, 1, 32);
    pa += __shfl_xor_sync(0xffffffffu, pa, 2, 32);
    pb += __shfl_xor_sync(0xffffffffu, pb, 1, 32);
    pb += __shfl_xor_sync(0xffffffffu, pb, 2, 32);
    if (tg == 0) {
        atomicAdd(&g_pooled[b * 64 + co_a], pa);
        atomicAdd(&g_pooled[b * 64 + co_b], pb);
    }
    if (tail)
        atomicAdd(&g_pooled[b * 64 + tid], fmaxf(tacc + b2[tid], 0.0f));
}

// ---------------- 4) router MLP + softmax + top2 + aux accumulation ------------
__global__ void gate_mlp_kernel(const float* __restrict__ w1, const float* __restrict__ b1,
                                const float* __restrict__ w2, const float* __restrict__ b2) {
    __shared__ __align__(16) float sp[64];
    __shared__ __align__(16) float sh[128];
    __shared__ float slg[8];
    int b = blockIdx.x;
    int j = threadIdx.x;

    if (j < 64) sp[j] = g_pooled[b * 64 + j] * (1.0f / 2049.0f);
    __syncthreads();

    {
        const float4* wr = (const float4*)(w1 + j * 64);
        float h0 = 0.f, h1 = 0.f, h2 = 0.f, h3 = 0.f;
        #pragma unroll
        for (int i = 0; i < 16; i++) {
            float4 wv = wr[i];
            float4 pv = *(const float4*)&sp[4 * i];
            h0 += pv.x * wv.x;
            h1 += pv.y * wv.y;
            h2 += pv.z * wv.z;
            h3 += pv.w * wv.w;
        }
        sh[j] = fmaxf((h0 + h1) + (h2 + h3) + b1[j], 0.0f);
    }
    __syncthreads();

    if (j < 8) {
        float acc = b2[j];
        const float4* wr = (const float4*)(w2 + j * 128);
        #pragma unroll
        for (int i = 0; i < 32; i++) {
            float4 wv = wr[i];
            float4 hv = *(const float4*)&sh[4 * i];
            acc += hv.x * wv.x + hv.y * wv.y + hv.z * wv.z + hv.w * wv.w;
        }
        slg[j] = acc;
    }
    __syncthreads();

    if (j == 0) {
        float lg[8];
        #pragma unroll
        for (int e = 0; e < 8; e++) lg[e] = slg[e];
        float m = lg[0];
        #pragma unroll
        for (int e = 1; e < 8; e++) m = fmaxf(m, lg[e]);
        float rw[8], s = 0.0f;
        #pragma unroll
        for (int e = 0; e < 8; e++) { rw[e] = expf(lg[e] - m); s += rw[e]; }
        float invs = 1.0f / s;
        #pragma unroll
        for (int e = 0; e < 8; e++) rw[e] *= invs;

        int i0 = 0;
        #pragma unroll
        for (int e = 1; e < 8; e++) if (rw[e] > rw[i0]) i0 = e;
        int i1 = (i0 == 0) ? 1 : 0;
        #pragma unroll
        for (int e = 0; e < 8; e++) if (e != i1 && e != i0 && rw[e] > rw[i1]) i1 = e;

        float t0 = rw[i0], t1 = rw[i1];
        float tn = 1.0f / (t0 + t1);
        g_ti[b * 2 + 0] = i0; g_ti[b * 2 + 1] = i1;
        g_tw[b * 2 + 0] = t0 * tn; g_tw[b * 2 + 1] = t1 * tn;

        #pragma unroll
        for (int e = 0; e < 8; e++) {
            atomicAdd(&g_srw[e], rw[e]);
            atomicAdd(&g_slg[e], lg[e]);
        }
    }
}

// ---------------- 5) expert conv1: (2 -> 64), k=7, s=2, p=3, relu --------------
// Outputs rounded to tf32 (rna) so econv2's tf32 MMA sees exactly-rounded B.
__global__ void econv1_kernel(const float* __restrict__ ew1, const float* __restrict__ eb1) {
    __shared__ __align__(16) float sin_[2][2056];
    __shared__ float sw[64][16];
    __shared__ float sb[64];
    int t = blockIdx.x;
    int b = t >> 1;
    int e = g_ti[t];
    int tid = threadIdx.x;   // 256

    for (int i = tid; i < 2 * 2056; i += 256) {
        int ci = i / 2056, j = i % 2056;
        int g = j - 3;
        sin_[ci][j] = (g >= 0 && g < NF) ? g_fft[(b * 2 + ci) * NF + g] : 0.0f;
    }
    for (int i = tid; i < 64 * 14; i += 256) sw[i / 14][i % 14] = ew1[e * 896 + i];
    if (tid < 64) sb[tid] = eb1[e * 64 + tid];
    __syncthreads();

    float v[2][16];
    #pragma unroll
    for (int ci = 0; ci < 2; ci++) {
        float4 a = *(const float4*)&sin_[ci][8 * tid];
        float4 c = *(const float4*)&sin_[ci][8 * tid + 4];
        float4 d = *(const float4*)&sin_[ci][8 * tid + 8];
        float4 f = *(const float4*)&sin_[ci][8 * tid + 12];
        v[ci][0]=a.x;  v[ci][1]=a.y;  v[ci][2]=a.z;  v[ci][3]=a.w;
        v[ci][4]=c.x;  v[ci][5]=c.y;  v[ci][6]=c.z;  v[ci][7]=c.w;
        v[ci][8]=d.x;  v[ci][9]=d.y;  v[ci][10]=d.z; v[ci][11]=d.w;
        v[ci][12]=f.x; v[ci][13]=f.y; v[ci][14]=f.z; v[ci][15]=f.w;
    }

    #pragma unroll 2
    for (int co = 0; co < 64; co++) {
        float acc[4];
        #pragma unroll
        for (int i = 0; i < 4; i++) acc[i] = sb[co];
        #pragma unroll
        for (int ci = 0; ci < 2; ci++)
            #pragma unroll
            for (int k = 0; k < 7; k++) {
                float w = sw[co][ci * 7 + k];
                #pragma unroll
                for (int i = 0; i < 4; i++) acc[i] += w * v[ci][2 * i + k];
            }
        float4 r;
        r.x = tf32r(fmaxf(acc[0], 0.0f)); r.y = tf32r(fmaxf(acc[1], 0.0f));
        r.z = tf32r(fmaxf(acc[2], 0.0f)); r.w = tf32r(fmaxf(acc[3], 0.0f));
        *(float4*)&g_e1[((size_t)t * 64 + co) * L1P + 4 * tid] = r;
    }

    if (tid < 64) {
        int co = tid;
        float acc = sb[co];
        #pragma unroll
        for (int ci = 0; ci < 2; ci++)
            #pragma unroll
            for (int k = 0; k < 7; k++)
                acc += sin_[ci][2048 + k] * sw[co][ci * 7 + k];
        g_e1[((size_t)t * 64 + co) * L1P + 1024] = tf32r(fmaxf(acc, 0.0f));
    }
}

// ---------------- 6) expert conv2 via TF32 mma.sync ----------------------------
#define E2T_SX_STRIDE (16 * 264)
#define E2T_SW_STRIDE (64 * 84)
#define E2T_SMEM ((2 * E2T_SX_STRIDE + 2 * E2T_SW_STRIDE) * 4)
__global__ void __launch_bounds__(256, 2)
econv2_tf32_kernel(const float* __restrict__ ew2, const float* __restrict__ eb2) {
    extern __shared__ __align__(16) float dyn2[];
    float* sxb = dyn2;
    float* swb = dyn2 + 2 * E2T_SX_STRIDE;
    int t  = blockIdx.z;
    int e  = g_ti[t];
    int l0 = blockIdx.x * 128;
    int cgrp = blockIdx.y;
    int tid = threadIdx.x;
    int lane = tid & 31;
    int w    = tid >> 5;
    int wc   = w & 3;
    int wn   = w >> 2;
    int g    = lane >> 2;
    int tg   = lane & 3;
    bool tail = (blockIdx.x == 3) && (tid < 64);

    const float* e1base = g_e1 + (size_t)t * 64 * L1P;
    const float* wbase  = ew2 + (size_t)(e * 128 + cgrp * 64) * 320;

    auto prefetch = [&](int p, int cb) {
        float* sx = sxb + p * E2T_SX_STRIDE;
        for (int i = tid; i < 16 * 66; i += 256) {
            int ci = i / 66, jj = i % 66;
            int ps = 2 * l0 - 4 + 4 * jj;
            int nf = (ps < 0) ? 0 : min(4, max(0, L1E - ps));
            cp16z(s2u(&sx[ci * 264 + 4 * jj]),
                  e1base + (size_t)(cb * 16 + ci) * L1P + max(ps, 0), 4 * nf);
        }
        float* sw = swb + p * E2T_SW_STRIDE;
        for (int i = tid; i < 64 * 20; i += 256) {
            int co = i / 20, kk = i % 20;
            cp16z(s2u(&sw[co * 84 + 4 * kk]),
                  wbase + (size_t)co * 320 + cb * 80 + 4 * kk, 16);
        }
    };
    auto convW = [&](int p) {
        float* sw = swb + p * E2T_SW_STRIDE;
        #pragma unroll
        for (int n = 0; n < 20; n++) {
            int i = n * 256 + tid;
            int co = i / 80, r = i % 80;
            sw[co * 84 + r] = tf32r(sw[co * 84 + r]);
        }
    };

    float acc[8][4];
    #pragma unroll
    for (int nt = 0; nt < 8; nt++)
        #pragma unroll
        for (int i = 0; i < 4; i++) acc[nt][i] = 0.0f;
    float tacc = 0.0f;

    prefetch(0, 0); cp_commit();
    prefetch(1, 1); cp_commit();

    for (int cb = 0; cb < 4; cb++) {
        int p = cb & 1;
        cp_wait<1>();
        __syncthreads();
        convW(p);
        __syncthreads();
        const float* X = sxb + p * E2T_SX_STRIDE;
        const float* W = swb + p * E2T_SW_STRIDE;

        #pragma unroll 1
        for (int ks = 0; ks < 10; ks++) {
            int shift = ks >> 1;
            int cik   = (ks & 1) * 8;
            const float* wr = W + (wc * 16 + g) * 84 + (cik + tg) * 5 + shift;
            uint32_t a0 = __float_as_uint(wr[0]);
            uint32_t a1 = __float_as_uint(wr[8 * 84]);
            uint32_t a2 = __float_as_uint(wr[20]);
            uint32_t a3 = __float_as_uint(wr[8 * 84 + 20]);
            const float* x0 = X + (cik + tg) * 264 + 2 * (wn * 64 + g) + shift + 2;
            const float* x1 = x0 + 4 * 264;
            #pragma unroll
            for (int nt = 0; nt < 8; nt++) {
                uint32_t b0 = __float_as_uint(x0[nt * 16]);
                uint32_t b1 = __float_as_uint(x1[nt * 16]);
                asm volatile(
                    "mma.sync.aligned.m16n8k8.row.col.f32.tf32.tf32.f32 "
                    "{%0,%1,%2,%3}, {%4,%5,%6,%7}, {%8,%9}, {%0,%1,%2,%3};"
                    : "+f"(acc[nt][0]), "+f"(acc[nt][1]),
                      "+f"(acc[nt][2]), "+f"(acc[nt][3])
                    : "r"(a0), "r"(a1), "r"(a2), "r"(a3), "r"(b0), "r"(b1));
            }
        }
        if (tail) {
            #pragma unroll 1
            for (int ci = 0; ci < 16; ci++)
                #pragma unroll
                for (int k = 0; k < 5; k++)
                    tacc += X[ci * 264 + 258 + k] * W[tid * 84 + ci * 5 + k];
        }
        __syncthreads();
        if (cb + 2 < 4) prefetch(p, cb + 2);
        cp_commit();
    }

    int co_a = cgrp * 64 + wc * 16 + g;
    int co_b = co_a + 8;
    float bias_a = eb2[e * 128 + co_a];
    float bias_b = eb2[e * 128 + co_b];
    float* outa = &g_e2[((size_t)t * 128 + co_a) * L2P];
    float* outb = &g_e2[((size_t)t * 128 + co_b) * L2P];
    #pragma unroll
    for (int nt = 0; nt < 8; nt++) {
        int l = l0 + wn * 64 + nt * 8 + 2 * tg;
        float2 ra, rb;
        ra.x = tf32r(fmaxf(acc[nt][0] + bias_a, 0.0f));
        ra.y = tf32r(fmaxf(acc[nt][1] + bias_a, 0.0f));
        rb.x = tf32r(fmaxf(acc[nt][2] + bias_b, 0.0f));
        rb.y = tf32r(fmaxf(acc[nt][3] + bias_b, 0.0f));
        *(float2*)(outa + l) = ra;
        *(float2*)(outb + l) = rb;
    }
    if (tail) {
        int co = cgrp * 64 + tid;
        g_e2[((size_t)t * 128 + co) * L2P + 512] = tf32r(fmaxf(tacc + eb2[e * 128 + co], 0.0f));
    }
}

// ---------------- 7) expert conv3 via TF32 mma.sync ----------------------------
#define E3T_SX_STRIDE (32 * 136)
#define E3T_SW_STRIDE (64 * 100)
#define E3T_SMEM ((2 * E3T_SX_STRIDE + 2 * E3T_SW_STRIDE) * 4)
__global__ void __launch_bounds__(256, 2)
econv3_tf32_kernel(const float* __restrict__ ew3, const float* __restrict__ eb3) {
    extern __shared__ __align__(16) float dyn3[];
    float* sxb = dyn3;
    float* swb = dyn3 + 2 * E3T_SX_STRIDE;
    int t  = blockIdx.z;
    int e  = g_ti[t];
    int l0 = blockIdx.x * 128;
    int cgrp = blockIdx.y;
    int tid = threadIdx.x;
    int lane = tid & 31;
    int w    = tid >> 5;
    int wc   = w & 3;
    int wn   = w >> 2;
    int g    = lane >> 2;
    int tg   = lane & 3;
    bool tail = (blockIdx.x == 3) && (tid < 64);

    const float* e2base = g_e2 + (size_t)t * 128 * L2P;
    const float* wbase  = ew3 + (size_t)(e * 128 + cgrp * 64) * 384;

    auto prefetch = [&](int p, int cb) {
        float* sx = sxb + p * E3T_SX_STRIDE;
        for (int i = tid; i < 32 * 34; i += 256) {
            int ci = i / 34, jj = i % 34;
            int ls = l0 - 4 + 4 * jj;
            int nf = (ls < 0) ? 0 : min(4, max(0, L2E - ls));
            cp16z(s2u(&sx[ci * 136 + 4 * jj]),
                  e2base + (size_t)(cb * 32 + ci) * L2P + max(ls, 0), 4 * nf);
        }
        float* sw = swb + p * E3T_SW_STRIDE;
        for (int i = tid; i < 64 * 24; i += 256) {
            int co = i / 24, kk = i % 24;
            cp16z(s2u(&sw[co * 100 + 4 * kk]),
                  wbase + (size_t)co * 384 + cb * 96 + 4 * kk, 16);
        }
    };
    auto convW = [&](int p) {
        float* sw = swb + p * E3T_SW_STRIDE;
        #pragma unroll
        for (int n = 0; n < 24; n++) {
            int i = n * 256 + tid;
            int co = i / 96, r = i % 96;
            sw[co * 100 + r] = tf32r(sw[co * 100 + r]);
        }
    };

    float acc[8][4];
    #pragma unroll
    for (int nt = 0; nt < 8; nt++)
        #pragma unroll
        for (int i = 0; i < 4; i++) acc[nt][i] = 0.0f;
    float tacc = 0.0f;

    prefetch(0, 0); cp_commit();
    prefetch(1, 1); cp_commit();

    for (int cb = 0; cb < 4; cb++) {
        int p = cb & 1;
        cp_wait<1>();
        __syncthreads();
        convW(p);
        __syncthreads();
        const float* X = sxb + p * E3T_SX_STRIDE;
        const float* W = swb + p * E3T_SW_STRIDE;

        #pragma unroll 1
        for (int ks = 0; ks < 12; ks++) {
            int shift = ks >> 2;
            int cik   = (ks & 3) * 8;
            const float* wr = W + (wc * 16 + g) * 100 + (cik + tg) * 3 + shift;
            uint32_t a0 = __float_as_uint(wr[0]);
            uint32_t a1 = __float_as_uint(wr[8 * 100]);
            uint32_t a2 = __float_as_uint(wr[12]);
            uint32_t a3 = __float_as_uint(wr[8 * 100 + 12]);
            const float* x0 = X + (cik + tg) * 136 + wn * 64 + g + shift + 3;
            const float* x1 = x0 + 4 * 136;
            #pragma unroll
            for (int nt = 0; nt < 8; nt++) {
                uint32_t b0 = __float_as_uint(x0[nt * 8]);
                uint32_t b1 = __float_as_uint(x1[nt * 8]);
                asm volatile(
                    "mma.sync.aligned.m16n8k8.row.col.f32.tf32.tf32.f32 "
                    "{%0,%1,%2,%3}, {%4,%5,%6,%7}, {%8,%9}, {%0,%1,%2,%3};"
                    : "+f"(acc[nt][0]), "+f"(acc[nt][1]),
                      "+f"(acc[nt][2]), "+f"(acc[nt][3])
                    : "r"(a0), "r"(a1), "r"(a2), "r"(a3), "r"(b0), "r"(b1));
            }
        }
        if (tail) {
            // l = 512: input l' = 511+sh -> j = 511+sh - (384-4) = 131+sh
            #pragma unroll 1
            for (int ci = 0; ci < 32; ci++)
                #pragma unroll
                for (int sh = 0; sh < 3; sh++)
                    tacc += X[ci * 136 + 131 + sh] * W[tid * 100 + ci * 3 + sh];
        }
        __syncthreads();
        if (cb + 2 < 4) prefetch(p, cb + 2);
        cp_commit();
    }

    int co_a = cgrp * 64 + wc * 16 + g;
    int co_b = co_a + 8;
    float bias_a = eb3[e * 128 + co_a];
    float bias_b = eb3[e * 128 + co_b];
    float* outa = &g_e3[((size_t)t * 128 + co_a) * L2P];
    float* outb = &g_e3[((size_t)t * 128 + co_b) * L2P];
    #pragma unroll
    for (int nt = 0; nt < 8; nt++) {
        int l = l0 + wn * 64 + nt * 8 + 2 * tg;
        float2 ra, rb;
        ra.x = fmaxf(acc[nt][0] + bias_a, 0.0f);
        ra.y = fmaxf(acc[nt][1] + bias_a, 0.0f);
        rb.x = fmaxf(acc[nt][2] + bias_b, 0.0f);
        rb.y = fmaxf(acc[nt][3] + bias_b, 0.0f);
        *(float2*)(outa + l) = ra;
        *(float2*)(outb + l) = rb;
    }
    if (tail) {
        int co = cgrp * 64 + tid;
        g_e3[((size_t)t * 128 + co) * L2P + 512] = fmaxf(tacc + eb3[e * 128 + co], 0.0f);
    }
}

// ---------------- 8) top-2 combine + adaptive max-pool + aux finalize ----------
__global__ void pool_kernel(float* __restrict__ out, int out_size) {
    int idx = blockIdx.x * blockDim.x + threadIdx.x;
    if (idx == 0) {
        float aux = 0.0f;
        #pragma unroll
        for (int e = 0; e < 8; e++)
            aux += (g_srw[e] * (1.0f / 128.0f)) * (g_slg[e] * (1.0f / 128.0f));
        out[out_size - 1] = 0.01f * 8.0f * aux;
    }
    if (idx >= B * 128 * 256) return;
    int o  = idx & 255;
    int co = (idx >> 8) & 127;
    int b  = idx >> 15;
    float w0 = g_tw[b * 2 + 0];
    float w1 = g_tw[b * 2 + 1];
    const float* p0 = g_e3 + ((size_t)(b * 2 + 0) * 128 + co) * L2P;
    const float* p1 = g_e3 + ((size_t)(b * 2 + 1) * 128 + co) * L2P;
    int s  = (o * 513) >> 8;
    int en = (o * 513 + 513 + 255) >> 8;
    float m = -INFINITY;
    for (int l = s; l < en; l++)
        m = fmaxf(m, w0 * p0[l] + w1 * p1[l]);
    out[idx] = m;
}

// ---------------- launch --------------------------------------------------------
extern "C" void kernel_launch(void* const* d_in, const int* in_sizes, int n_in,
                              void* d_out, int out_size) {
    const float* x    = (const float*)d_in[0];
    const float* gw1  = (const float*)d_in[1];
    const float* gb1  = (const float*)d_in[2];
    const float* gw2  = (const float*)d_in[3];
    const float* gb2  = (const float*)d_in[4];
    const float* mw1  = (const float*)d_in[5];
    const float* mb1  = (const float*)d_in[6];
    const float* mw2  = (const float*)d_in[7];
    const float* mb2  = (const float*)d_in[8];
    const float* ew1  = (const float*)d_in[9];
    const float* eb1  = (const float*)d_in[10];
    const float* ew2  = (const float*)d_in[11];
    const float* eb2  = (const float*)d_in[12];
    const float* ew3  = (const float*)d_in[13];
    const float* eb3  = (const float*)d_in[14];
    float* out = (float*)d_out;

    static int attr_done = 0;
    if (!attr_done) {
        cudaFuncSetAttribute(gconv2_tf32_pool_kernel, cudaFuncAttributeMaxDynamicSharedMemorySize, G2T_SMEM);
        cudaFuncSetAttribute(econv2_tf32_kernel, cudaFuncAttributeMaxDynamicSharedMemorySize, E2T_SMEM);
        cudaFuncSetAttribute(econv3_tf32_kernel, cudaFuncAttributeMaxDynamicSharedMemorySize, E3T_SMEM);
        attr_done = 1;
    }

    fft_kernel<<<B, 512>>>(x);
    gconv1_kernel<<<dim3(2, B), 256>>>(gw1, gb1);
    gconv2_tf32_pool_kernel<<<dim3(16, B), 256, G2T_SMEM>>>(gw2, gb2);
    gate_mlp_kernel<<<B, 128>>>(mw1, mb1, mw2, mb2);
    econv1_kernel<<<NTASK, 256>>>(ew1, eb1);
    econv2_tf32_kernel<<<dim3(4, 2, NTASK), 256, E2T_SMEM>>>(ew2, eb2);
    econv3_tf32_kernel<<<dim3(4, 2, NTASK), 256, E3T_SMEM>>>(ew3, eb3);
    pool_kernel<<<16384, 256>>>(out, out_size);
}

// round 15
// speedup vs baseline: 4.7375x; 1.4530x over previous
#include <cuda_runtime.h>
#include <cuda_fp16.h>
#include <math.h>
#include <stdint.h>

#define B 128
#define LSEQ 4096
#define NF 2049          // rfft bins
#define NFP 2052         // padded row stride for g_h1
#define L1E 1025         // expert conv1 out length
#define L1HP 1028        // g_e1h row pitch (half2 words per ci-pair row)
#define L2E 513          // expert conv2/conv3 out length
#define L2P 516          // fp32 pitch (g_e3) and half2 pitch (g_e2h)
#define NTASK 256        // B * TOP_K

// ---------------- cp.async helpers --------------------------------------------
__device__ __forceinline__ uint32_t s2u(const void* p) {
    return (uint32_t)__cvta_generic_to_shared(p);
}
__device__ __forceinline__ void cp16z(uint32_t saddr, const void* g, int src_bytes) {
    asm volatile("cp.async.ca.shared.global [%0], [%1], 16, %2;"
                 :: "r"(saddr), "l"(g), "r"(src_bytes));
}
__device__ __forceinline__ void cp_commit() {
    asm volatile("cp.async.commit_group;");
}
template <int N>
__device__ __forceinline__ void cp_wait() {
    asm volatile("cp.async.wait_group %0;" :: "n"(N));
}
__device__ __forceinline__ float tf32r(float x) {
    uint32_t u;
    asm("cvt.rna.tf32.f32 %0, %1;" : "=r"(u) : "f"(x));
    return __uint_as_float(u);
}

// ---------------- scratch (device globals) -------------------------------------
__device__ float  g_fft[B * 2 * NF];
__device__ float  g_h1 [B * 32 * NFP];
__device__ float  g_pooled[B * 64];
__device__ float  g_tw[NTASK];
__device__ int    g_ti[NTASK];
__device__ float  g_srw[8];
__device__ float  g_slg[8];
__device__ __half2 g_e1h[NTASK * 32 * L1HP];   // [t][ci/2][l] (.x = even ci)
__device__ __half2 g_e2h[NTASK * 64 * L2P];    // [t][ci/2][l]
__device__ float  g_e3[NTASK * 128 * L2P];
__device__ __half g_ew2h[8 * 128 * 320];       // [coE][cb(4)][shift(5)][ci(16)]
__device__ __half g_ew3h[8 * 128 * 384];       // [coE][cb(4)][shift(3)][ci(32)]

// ---------------- 0) weight prep: fp16 conversion + k-step layout --------------
__global__ void prep_kernel(const float* __restrict__ ew2, const float* __restrict__ ew3) {
    int i = blockIdx.x * 256 + threadIdx.x;
    if (i < 8 * 128 * 320) {
        int r = i % 80, cb = (i / 80) % 4, coE = i / 320;
        int shift = r / 16, ci = r % 16;
        g_ew2h[i] = __float2half_rn(ew2[(coE * 64 + cb * 16 + ci) * 5 + shift]);
    }
    if (i < 8 * 128 * 384) {
        int r = i % 96, cb = (i / 96) % 4, coE = i / 384;
        int shift = r / 32, ci = r % 32;
        g_ew3h[i] = __float2half_rn(ew3[(coE * 128 + cb * 32 + ci) * 3 + shift]);
    }
}

// ---------------- 1) Hann window + 4096-pt radix-2 FFT + zero accumulators -----
__global__ void fft_kernel(const float* __restrict__ x) {
    __shared__ float re[4096];
    __shared__ float im[4096];
    __shared__ float twr[2048];
    __shared__ float twi[2048];
    int b = blockIdx.x;
    const float* xb = x + b * LSEQ;

    if (threadIdx.x < 64) g_pooled[b * 64 + threadIdx.x] = 0.0f;
    if (b == 0 && threadIdx.x >= 64 && threadIdx.x < 72) {
        g_srw[threadIdx.x - 64] = 0.0f;
        g_slg[threadIdx.x - 64] = 0.0f;
    }

    for (int i = threadIdx.x; i < 2048; i += blockDim.x) {
        float si, sr;
        sincospif(-(float)i * (1.0f / 2048.0f), &si, &sr);
        twr[i] = sr; twi[i] = si;
    }
    for (int i = threadIdx.x; i < 4096; i += blockDim.x) {
        float w = 0.5f * (1.0f - cospif((float)i * (1.0f / 2048.0f)));
        int j = __brev((unsigned)i) >> 20;
        re[j] = xb[i] * w;
        im[j] = 0.0f;
    }
    __syncthreads();

    for (int s = 1; s <= 12; s++) {
        int half = 1 << (s - 1);
        int len  = 1 << s;
        int shft = 12 - s;
        for (int t = threadIdx.x; t < 2048; t += blockDim.x) {
            int g   = t >> (s - 1);
            int pos = t & (half - 1);
            int i0  = g * len + pos;
            int i1  = i0 + half;
            int j   = pos << shft;
            float sr = twr[j], si = twi[j];
            float ar = re[i1], ai = im[i1];
            float tr = ar * sr - ai * si;
            float ti = ar * si + ai * sr;
            float br = re[i0], bi = im[i0];
            re[i1] = br - tr; im[i1] = bi - ti;
            re[i0] = br + tr; im[i0] = bi + ti;
        }
        __syncthreads();
    }
    const float sc = 1.0f / 64.0f;
    for (int f = threadIdx.x; f < NF; f += blockDim.x) {
        g_fft[(b * 2 + 0) * NF + f] = re[f] * sc;
        g_fft[(b * 2 + 1) * NF + f] = im[f] * sc;
    }
}

// ---------------- 2) gate conv1: (2 -> 32), k=5, s=1, p=2, relu ----------------
__global__ void gconv1_kernel(const float* __restrict__ w1, const float* __restrict__ b1) {
    __shared__ __align__(16) float sin_[2][1036];
    __shared__ float sw[32][11];
    __shared__ float sb[32];
    int b  = blockIdx.y;
    int l0 = blockIdx.x * 1024;
    int tid = threadIdx.x;   // 256

    for (int i = tid; i < 2 * 1032; i += 256) {
        int ci = i / 1032, j = i % 1032;
        int g = l0 + j - 2;
        sin_[ci][j] = (g >= 0 && g < NF) ? g_fft[(b * 2 + ci) * NF + g] : 0.0f;
    }
    for (int i = tid; i < 320; i += 256) sw[i / 10][i % 10] = w1[i];
    if (tid < 32) sb[tid] = b1[tid];
    __syncthreads();

    float v[2][8];
    #pragma unroll
    for (int ci = 0; ci < 2; ci++) {
        float4 a = *(const float4*)&sin_[ci][4 * tid];
        float4 c = *(const float4*)&sin_[ci][4 * tid + 4];
        v[ci][0] = a.x; v[ci][1] = a.y; v[ci][2] = a.z; v[ci][3] = a.w;
        v[ci][4] = c.x; v[ci][5] = c.y; v[ci][6] = c.z; v[ci][7] = c.w;
    }

    #pragma unroll 4
    for (int co = 0; co < 32; co++) {
        float acc[4];
        #pragma unroll
        for (int i = 0; i < 4; i++) acc[i] = sb[co];
        #pragma unroll
        for (int ci = 0; ci < 2; ci++)
            #pragma unroll
            for (int k = 0; k < 5; k++) {
                float w = sw[co][ci * 5 + k];
                #pragma unroll
                for (int i = 0; i < 4; i++) acc[i] += w * v[ci][i + k];
            }
        float4 r;
        r.x = tf32r(fmaxf(acc[0], 0.0f)); r.y = tf32r(fmaxf(acc[1], 0.0f));
        r.z = tf32r(fmaxf(acc[2], 0.0f)); r.w = tf32r(fmaxf(acc[3], 0.0f));
        *(float4*)&g_h1[(b * 32 + co) * NFP + l0 + 4 * tid] = r;
    }

    if (blockIdx.x == 1 && tid == 0) {
        for (int co = 0; co < 32; co++) {
            float acc = sb[co];
            #pragma unroll
            for (int ci = 0; ci < 2; ci++)
                #pragma unroll
                for (int k = 0; k < 5; k++)
                    acc += sin_[ci][1024 + k] * sw[co][ci * 5 + k];
            g_h1[(b * 32 + co) * NFP + 2048] = tf32r(fmaxf(acc, 0.0f));
        }
    }
}

// ---------------- 3) gate conv2 via TF32 mma + fused mean pool ----------------
#define G2T_SX_STRIDE (16 * 136)
#define G2T_SW_STRIDE (64 * 84)
#define G2T_SMEM ((2 * G2T_SX_STRIDE + 2 * G2T_SW_STRIDE) * 4)
__global__ void __launch_bounds__(256, 2)
gconv2_tf32_pool_kernel(const float* __restrict__ w2, const float* __restrict__ b2) {
    extern __shared__ __align__(16) float dyng[];
    float* sxb = dyng;
    float* swb = dyng + 2 * G2T_SX_STRIDE;
    int b  = blockIdx.y;
    int l0 = blockIdx.x * 128;
    int tid = threadIdx.x;
    int lane = tid & 31;
    int w    = tid >> 5;
    int wc   = w & 3;
    int wn   = w >> 2;
    int g    = lane >> 2;
    int tg   = lane & 3;
    bool tail = (blockIdx.x == 15) && (tid < 64);

    const float* h1base = g_h1 + (size_t)b * 32 * NFP;

    auto prefetch = [&](int p, int cb) {
        float* sx = sxb + p * G2T_SX_STRIDE;
        for (int i = tid; i < 16 * 34; i += 256) {
            int ci = i / 34, jj = i % 34;
            int ls = l0 - 4 + 4 * jj;
            int nf = (ls < 0) ? 0 : min(4, max(0, NF - ls));
            cp16z(s2u(&sx[ci * 136 + 4 * jj]),
                  h1base + (size_t)(cb * 16 + ci) * NFP + max(ls, 0), 4 * nf);
        }
        float* sw = swb + p * G2T_SW_STRIDE;
        for (int i = tid; i < 64 * 20; i += 256) {
            int co = i / 20, kk = i % 20;
            cp16z(s2u(&sw[co * 84 + 4 * kk]),
                  w2 + (size_t)co * 160 + cb * 80 + 4 * kk, 16);
        }
    };
    auto convW = [&](int p) {
        float* sw = swb + p * G2T_SW_STRIDE;
        #pragma unroll
        for (int n = 0; n < 20; n++) {
            int i = n * 256 + tid;
            int co = i / 80, r = i % 80;
            sw[co * 84 + r] = tf32r(sw[co * 84 + r]);
        }
    };

    float acc[8][4];
    #pragma unroll
    for (int nt = 0; nt < 8; nt++)
        #pragma unroll
        for (int i = 0; i < 4; i++) acc[nt][i] = 0.0f;
    float tacc = 0.0f;

    prefetch(0, 0); cp_commit();
    prefetch(1, 1); cp_commit();

    for (int cb = 0; cb < 2; cb++) {
        int p = cb & 1;
        cp_wait<1>();
        __syncthreads();
        convW(p);
        __syncthreads();
        const float* X = sxb + p * G2T_SX_STRIDE;
        const float* W = swb + p * G2T_SW_STRIDE;

        #pragma unroll 1
        for (int ks = 0; ks < 10; ks++) {
            int shift = ks >> 1;
            int cik   = (ks & 1) * 8;
            const float* wr = W + (wc * 16 + g) * 84 + (cik + tg) * 5 + shift;
            uint32_t a0 = __float_as_uint(wr[0]);
            uint32_t a1 = __float_as_uint(wr[8 * 84]);
            uint32_t a2 = __float_as_uint(wr[20]);
            uint32_t a3 = __float_as_uint(wr[8 * 84 + 20]);
            const float* x0 = X + (cik + tg) * 136 + wn * 64 + g + shift + 2;
            const float* x1 = x0 + 4 * 136;
            #pragma unroll
            for (int nt = 0; nt < 8; nt++) {
                uint32_t b0 = __float_as_uint(x0[nt * 8]);
                uint32_t b1 = __float_as_uint(x1[nt * 8]);
                asm volatile(
                    "mma.sync.aligned.m16n8k8.row.col.f32.tf32.tf32.f32 "
                    "{%0,%1,%2,%3}, {%4,%5,%6,%7}, {%8,%9}, {%0,%1,%2,%3};"
                    : "+f"(acc[nt][0]), "+f"(acc[nt][1]),
                      "+f"(acc[nt][2]), "+f"(acc[nt][3])
                    : "r"(a0), "r"(a1), "r"(a2), "r"(a3), "r"(b0), "r"(b1));
            }
        }
        if (tail) {
            // l = 2048: input l' = 2046+k -> j = 130+k
            #pragma unroll 1
            for (int ci = 0; ci < 16; ci++)
                #pragma unroll
                for (int k = 0; k < 5; k++)
                    tacc += X[ci * 136 + 130 + k] * W[tid * 84 + ci * 5 + k];
        }
        __syncthreads();
        cp_commit();
    }

    int co_a = wc * 16 + g;
    int co_b = co_a + 8;
    float bias_a = b2[co_a];
    float bias_b = b2[co_b];
    float pa = 0.0f, pb = 0.0f;
    #pragma unroll
    for (int nt = 0; nt < 8; nt++) {
        pa += fmaxf(acc[nt][0] + bias_a, 0.0f) + fmaxf(acc[nt][1] + bias_a, 0.0f);
        pb += fmaxf(acc[nt][2] + bias_b, 0.0f) + fmaxf(acc[nt][3] + bias_b, 0.0f);
    }
    pa += __shfl_xor_sync(0xffffffffu, pa, 1, 32);
    pa += __shfl_xor_sync(0xffffffffu, pa, 2, 32);
    pb += __shfl_xor_sync(0xffffffffu, pb, 1, 32);
    pb += __shfl_xor_sync(0xffffffffu, pb, 2, 32);
    if (tg == 0) {
        atomicAdd(&g_pooled[b * 64 + co_a], pa);
        atomicAdd(&g_pooled[b * 64 + co_b], pb);
    }
    if (tail)
        atomicAdd(&g_pooled[b * 64 + tid], fmaxf(tacc + b2[tid], 0.0f));
}

// ---------------- 4) router MLP + softmax + top2 + aux accumulation ------------
__global__ void gate_mlp_kernel(const float* __restrict__ w1, const float* __restrict__ b1,
                                const float* __restrict__ w2, const float* __restrict__ b2) {
    __shared__ __align__(16) float sp[64];
    __shared__ __align__(16) float sh[128];
    __shared__ float slg[8];
    int b = blockIdx.x;
    int j = threadIdx.x;

    if (j < 64) sp[j] = g_pooled[b * 64 + j] * (1.0f / 2049.0f);
    __syncthreads();

    {
        const float4* wr = (const float4*)(w1 + j * 64);
        float h0 = 0.f, h1 = 0.f, h2 = 0.f, h3 = 0.f;
        #pragma unroll
        for (int i = 0; i < 16; i++) {
            float4 wv = wr[i];
            float4 pv = *(const float4*)&sp[4 * i];
            h0 += pv.x * wv.x;
            h1 += pv.y * wv.y;
            h2 += pv.z * wv.z;
            h3 += pv.w * wv.w;
        }
        sh[j] = fmaxf((h0 + h1) + (h2 + h3) + b1[j], 0.0f);
    }
    __syncthreads();

    if (j < 8) {
        float acc = b2[j];
        const float4* wr = (const float4*)(w2 + j * 128);
        #pragma unroll
        for (int i = 0; i < 32; i++) {
            float4 wv = wr[i];
            float4 hv = *(const float4*)&sh[4 * i];
            acc += hv.x * wv.x + hv.y * wv.y + hv.z * wv.z + hv.w * wv.w;
        }
        slg[j] = acc;
    }
    __syncthreads();

    if (j == 0) {
        float lg[8];
        #pragma unroll
        for (int e = 0; e < 8; e++) lg[e] = slg[e];
        float m = lg[0];
        #pragma unroll
        for (int e = 1; e < 8; e++) m = fmaxf(m, lg[e]);
        float rw[8], s = 0.0f;
        #pragma unroll
        for (int e = 0; e < 8; e++) { rw[e] = expf(lg[e] - m); s += rw[e]; }
        float invs = 1.0f / s;
        #pragma unroll
        for (int e = 0; e < 8; e++) rw[e] *= invs;

        int i0 = 0;
        #pragma unroll
        for (int e = 1; e < 8; e++) if (rw[e] > rw[i0]) i0 = e;
        int i1 = (i0 == 0) ? 1 : 0;
        #pragma unroll
        for (int e = 0; e < 8; e++) if (e != i1 && e != i0 && rw[e] > rw[i1]) i1 = e;

        float t0 = rw[i0], t1 = rw[i1];
        float tn = 1.0f / (t0 + t1);
        g_ti[b * 2 + 0] = i0; g_ti[b * 2 + 1] = i1;
        g_tw[b * 2 + 0] = t0 * tn; g_tw[b * 2 + 1] = t1 * tn;

        #pragma unroll
        for (int e = 0; e < 8; e++) {
            atomicAdd(&g_srw[e], rw[e]);
            atomicAdd(&g_slg[e], lg[e]);
        }
    }
}

// ---------------- 5) expert conv1: (2 -> 64), k=7, s=2, p=3, relu --------------
// Outputs stored as ci-pair-interleaved half2 (.x = even co) for fp16 econv2.
__global__ void econv1_kernel(const float* __restrict__ ew1, const float* __restrict__ eb1) {
    __shared__ __align__(16) float sin_[2][2056];
    __shared__ float sw[64][16];
    __shared__ float sb[64];
    int t = blockIdx.x;
    int b = t >> 1;
    int e = g_ti[t];
    int tid = threadIdx.x;   // 256

    for (int i = tid; i < 2 * 2056; i += 256) {
        int ci = i / 2056, j = i % 2056;
        int g = j - 3;
        sin_[ci][j] = (g >= 0 && g < NF) ? g_fft[(b * 2 + ci) * NF + g] : 0.0f;
    }
    for (int i = tid; i < 64 * 14; i += 256) sw[i / 14][i % 14] = ew1[e * 896 + i];
    if (tid < 64) sb[tid] = eb1[e * 64 + tid];
    __syncthreads();

    float v[2][16];
    #pragma unroll
    for (int ci = 0; ci < 2; ci++) {
        float4 a = *(const float4*)&sin_[ci][8 * tid];
        float4 c = *(const float4*)&sin_[ci][8 * tid + 4];
        float4 d = *(const float4*)&sin_[ci][8 * tid + 8];
        float4 f = *(const float4*)&sin_[ci][8 * tid + 12];
        v[ci][0]=a.x;  v[ci][1]=a.y;  v[ci][2]=a.z;  v[ci][3]=a.w;
        v[ci][4]=c.x;  v[ci][5]=c.y;  v[ci][6]=c.z;  v[ci][7]=c.w;
        v[ci][8]=d.x;  v[ci][9]=d.y;  v[ci][10]=d.z; v[ci][11]=d.w;
        v[ci][12]=f.x; v[ci][13]=f.y; v[ci][14]=f.z; v[ci][15]=f.w;
    }

    #pragma unroll 2
    for (int cop = 0; cop < 32; cop++) {
        int c0 = 2 * cop, c1 = 2 * cop + 1;
        float a0[4], a1[4];
        #pragma unroll
        for (int i = 0; i < 4; i++) { a0[i] = sb[c0]; a1[i] = sb[c1]; }
        #pragma unroll
        for (int ci = 0; ci < 2; ci++)
            #pragma unroll
            for (int k = 0; k < 7; k++) {
                float w0 = sw[c0][ci * 7 + k];
                float w1 = sw[c1][ci * 7 + k];
                #pragma unroll
                for (int i = 0; i < 4; i++) {
                    a0[i] += w0 * v[ci][2 * i + k];
                    a1[i] += w1 * v[ci][2 * i + k];
                }
            }
        __half2 h[4];
        #pragma unroll
        for (int i = 0; i < 4; i++)
            h[i] = __floats2half2_rn(fmaxf(a0[i], 0.0f), fmaxf(a1[i], 0.0f));
        *(uint4*)&g_e1h[((size_t)t * 32 + cop) * L1HP + 4 * tid] = *(uint4*)h;
    }

    // tail l = 1024: g = 2045+k -> j = 2048+k; tid<32 handles co-pair tid
    if (tid < 32) {
        int c0 = 2 * tid, c1 = c0 + 1;
        float a0 = sb[c0], a1 = sb[c1];
        #pragma unroll
        for (int ci = 0; ci < 2; ci++)
            #pragma unroll
            for (int k = 0; k < 7; k++) {
                float xv = sin_[ci][2048 + k];
                a0 += xv * sw[c0][ci * 7 + k];
                a1 += xv * sw[c1][ci * 7 + k];
            }
        g_e1h[((size_t)t * 32 + tid) * L1HP + 1024] =
            __floats2half2_rn(fmaxf(a0, 0.0f), fmaxf(a1, 0.0f));
    }
}

// ---------------- 6) expert conv2 via FP16 mma (m16n8k16) ----------------------
// X smem: 8 pair-rows x 264 half2 words, word j <-> pos = 2*l0-4+j.
// W smem: halves [64][88] (chunk layout [shift(5)][ci(16)]).
#define E2H_SX_STRIDE (8 * 264)            // uint32 words
#define E2H_SW_STRIDE (64 * 88)            // halves
#define E2H_SMEM (2 * E2H_SX_STRIDE * 4 + 2 * E2H_SW_STRIDE * 2)
__global__ void __launch_bounds__(256, 2)
econv2_f16_kernel(const float* __restrict__ eb2) {
    extern __shared__ __align__(16) uint32_t dynh2[];
    uint32_t* sxb = dynh2;
    __half*   swb = (__half*)(dynh2 + 2 * E2H_SX_STRIDE);
    int t  = blockIdx.z;
    int e  = g_ti[t];
    int l0 = blockIdx.x * 128;
    int cgrp = blockIdx.y;
    int tid = threadIdx.x;
    int lane = tid & 31;
    int w    = tid >> 5;
    int wc   = w & 3;
    int wn   = w >> 2;
    int g    = lane >> 2;
    int tg   = lane & 3;
    bool tail = (blockIdx.x == 3) && (tid < 64);

    const __half2* e1base = g_e1h + (size_t)t * 32 * L1HP;
    const __half*  wbase  = g_ew2h + (size_t)(e * 128 + cgrp * 64) * 320;

    auto prefetch = [&](int p, int cb) {
        uint32_t* sx = sxb + p * E2H_SX_STRIDE;
        // 8 pair-rows x 66 granules (words j = 0..263); pos = 2*l0-4+4*jj
        for (int i = tid; i < 8 * 66; i += 256) {
            int r = i / 66, jj = i % 66;
            int ps = 2 * l0 - 4 + 4 * jj;
            int nf = (ps < 0) ? 0 : min(4, max(0, L1E - ps));
            cp16z(s2u(&sx[r * 264 + 4 * jj]),
                  e1base + (size_t)(cb * 8 + r) * L1HP + max(ps, 0), 4 * nf);
        }
        __half* sw = swb + p * E2H_SW_STRIDE;
        // 64 co x 10 granules (80 halves of chunk cb)
        for (int i = tid; i < 64 * 10; i += 256) {
            int co = i / 10, kk = i % 10;
            cp16z(s2u(&sw[co * 88 + 8 * kk]),
                  wbase + (size_t)co * 320 + cb * 80 + 8 * kk, 16);
        }
    };

    float acc[8][4];
    #pragma unroll
    for (int nt = 0; nt < 8; nt++)
        #pragma unroll
        for (int i = 0; i < 4; i++) acc[nt][i] = 0.0f;
    float tacc = 0.0f;

    prefetch(0, 0); cp_commit();
    prefetch(1, 1); cp_commit();

    for (int cb = 0; cb < 4; cb++) {
        int p = cb & 1;
        cp_wait<1>();
        __syncthreads();
        const uint32_t* X = sxb + p * E2H_SX_STRIDE;
        const uint32_t* W32 = (const uint32_t*)(swb + p * E2H_SW_STRIDE);

        #pragma unroll 1
        for (int ks = 0; ks < 5; ks++) {          // ks = shift, 16 ci per step
            const uint32_t* wr = W32 + (wc * 16 + g) * 44 + ks * 8 + tg;
            uint32_t a0 = wr[0];
            uint32_t a1 = wr[8 * 44];
            uint32_t a2 = wr[4];
            uint32_t a3 = wr[8 * 44 + 4];
            // word j = 2*(l-l0) + ks + 2
            const uint32_t* x0 = X + tg * 264 + 2 * (wn * 64 + g) + ks + 2;
            const uint32_t* x1 = x0 + 4 * 264;
            #pragma unroll
            for (int nt = 0; nt < 8; nt++) {
                uint32_t b0 = x0[nt * 16];
                uint32_t b1 = x1[nt * 16];
                asm volatile(
                    "mma.sync.aligned.m16n8k16.row.col.f32.f16.f16.f32 "
                    "{%0,%1,%2,%3}, {%4,%5,%6,%7}, {%8,%9}, {%0,%1,%2,%3};"
                    : "+f"(acc[nt][0]), "+f"(acc[nt][1]),
                      "+f"(acc[nt][2]), "+f"(acc[nt][3])
                    : "r"(a0), "r"(a1), "r"(a2), "r"(a3), "r"(b0), "r"(b1));
            }
        }
        if (tail) {
            // l = 512: pos = 1022+k -> j = 258+k
            const __half* Wh = swb + p * E2H_SW_STRIDE;
            #pragma unroll 1
            for (int ci = 0; ci < 16; ci++) {
                #pragma unroll
                for (int k = 0; k < 5; k++) {
                    __half2 h2 = *(const __half2*)&X[(ci >> 1) * 264 + 258 + k];
                    float xv = __half2float((ci & 1) ? h2.y : h2.x);
                    tacc += xv * __half2float(Wh[tid * 88 + k * 16 + ci]);
                }
            }
        }
        __syncthreads();
        if (cb + 2 < 4) prefetch(p, cb + 2);
        cp_commit();
    }

    // epilogue: scalar half stores into ci-pair-interleaved g_e2h
    __half* outh = (__half*)g_e2h;
    int co_a = cgrp * 64 + wc * 16 + g;
    int co_b = co_a + 8;
    float bias_a = eb2[e * 128 + co_a];
    float bias_b = eb2[e * 128 + co_b];
    size_t row_a = (size_t)t * 64 + (co_a >> 1);
    size_t row_b = (size_t)t * 64 + (co_b >> 1);
    int ca = co_a & 1, cbp = co_b & 1;
    #pragma unroll
    for (int nt = 0; nt < 8; nt++) {
        int l = l0 + wn * 64 + nt * 8 + 2 * tg;
        outh[(row_a * L2P + l) * 2 + ca]     = __float2half_rn(fmaxf(acc[nt][0] + bias_a, 0.0f));
        outh[(row_a * L2P + l + 1) * 2 + ca] = __float2half_rn(fmaxf(acc[nt][1] + bias_a, 0.0f));
        outh[(row_b * L2P + l) * 2 + cbp]     = __float2half_rn(fmaxf(acc[nt][2] + bias_b, 0.0f));
        outh[(row_b * L2P + l + 1) * 2 + cbp] = __float2half_rn(fmaxf(acc[nt][3] + bias_b, 0.0f));
    }
    if (tail) {
        int co = cgrp * 64 + tid;
        size_t row = (size_t)t * 64 + (co >> 1);
        outh[(row * L2P + 512) * 2 + (co & 1)] =
            __float2half_rn(fmaxf(tacc + eb2[e * 128 + co], 0.0f));
    }
}

// ---------------- 7) expert conv3 via FP16 mma (m16n8k16) ----------------------
// X smem: 16 pair-rows x 136 half2 words, word j <-> l = l0-4+j.
// W smem: halves [64][104] (chunk layout [shift(3)][ci(32)]).
#define E3H_SX_STRIDE (16 * 136)           // uint32 words
#define E3H_SW_STRIDE (64 * 104)           // halves
#define E3H_SMEM (2 * E3H_SX_STRIDE * 4 + 2 * E3H_SW_STRIDE * 2)
__global__ void __launch_bounds__(256, 2)
econv3_f16_kernel(const float* __restrict__ eb3) {
    extern __shared__ __align__(16) uint32_t dynh3[];
    uint32_t* sxb = dynh3;
    __half*   swb = (__half*)(dynh3 + 2 * E3H_SX_STRIDE);
    int t  = blockIdx.z;
    int e  = g_ti[t];
    int l0 = blockIdx.x * 128;
    int cgrp = blockIdx.y;
    int tid = threadIdx.x;
    int lane = tid & 31;
    int w    = tid >> 5;
    int wc   = w & 3;
    int wn   = w >> 2;
    int g    = lane >> 2;
    int tg   = lane & 3;
    bool tail = (blockIdx.x == 3) && (tid < 64);

    const __half2* e2base = g_e2h + (size_t)t * 64 * L2P;
    const __half*  wbase  = g_ew3h + (size_t)(e * 128 + cgrp * 64) * 384;

    auto prefetch = [&](int p, int cb) {
        uint32_t* sx = sxb + p * E3H_SX_STRIDE;
        // 16 pair-rows x 34 granules; l_start = l0-4+4*jj
        for (int i = tid; i < 16 * 34; i += 256) {
            int r = i / 34, jj = i % 34;
            int ls = l0 - 4 + 4 * jj;
            int nf = (ls < 0) ? 0 : min(4, max(0, L2E - ls));
            cp16z(s2u(&sx[r * 136 + 4 * jj]),
                  e2base + (size_t)(cb * 16 + r) * L2P + max(ls, 0), 4 * nf);
        }
        __half* sw = swb + p * E3H_SW_STRIDE;
        // 64 co x 12 granules (96 halves of chunk cb)
        for (int i = tid; i < 64 * 12; i += 256) {
            int co = i / 12, kk = i % 12;
            cp16z(s2u(&sw[co * 104 + 8 * kk]),
                  wbase + (size_t)co * 384 + cb * 96 + 8 * kk, 16);
        }
    };

    float acc[8][4];
    #pragma unroll
    for (int nt = 0; nt < 8; nt++)
        #pragma unroll
        for (int i = 0; i < 4; i++) acc[nt][i] = 0.0f;
    float tacc = 0.0f;

    prefetch(0, 0); cp_commit();
    prefetch(1, 1); cp_commit();

    for (int cb = 0; cb < 4; cb++) {
        int p = cb & 1;
        cp_wait<1>();
        __syncthreads();
        const uint32_t* X = sxb + p * E3H_SX_STRIDE;
        const uint32_t* W32 = (const uint32_t*)(swb + p * E3H_SW_STRIDE);

        #pragma unroll 1
        for (int ks = 0; ks < 6; ks++) {          // ks = shift*2 + grp
            int shift = ks >> 1;
            int grp   = ks & 1;                   // 16-ci group within chunk
            const uint32_t* wr = W32 + (wc * 16 + g) * 52 + shift * 16 + grp * 8 + tg;
            uint32_t a0 = wr[0];
            uint32_t a1 = wr[8 * 52];
            uint32_t a2 = wr[4];
            uint32_t a3 = wr[8 * 52 + 4];
            // word j = (l - l0) + shift + 3
            const uint32_t* x0 = X + (grp * 8 + tg) * 136 + wn * 64 + g + shift + 3;
            const uint32_t* x1 = x0 + 4 * 136;
            #pragma unroll
            for (int nt = 0; nt < 8; nt++) {
                uint32_t b0 = x0[nt * 8];
                uint32_t b1 = x1[nt * 8];
                asm volatile(
                    "mma.sync.aligned.m16n8k16.row.col.f32.f16.f16.f32 "
                    "{%0,%1,%2,%3}, {%4,%5,%6,%7}, {%8,%9}, {%0,%1,%2,%3};"
                    : "+f"(acc[nt][0]), "+f"(acc[nt][1]),
                      "+f"(acc[nt][2]), "+f"(acc[nt][3])
                    : "r"(a0), "r"(a1), "r"(a2), "r"(a3), "r"(b0), "r"(b1));
            }
        }
        if (tail) {
            // l = 512: input l' = 511+sh -> j = 131+sh
            const __half* Wh = swb + p * E3H_SW_STRIDE;
            #pragma unroll 1
            for (int ci = 0; ci < 32; ci++) {
                #pragma unroll
                for (int sh = 0; sh < 3; sh++) {
                    __half2 h2 = *(const __half2*)&X[(ci >> 1) * 136 + 131 + sh];
                    float xv = __half2float((ci & 1) ? h2.y : h2.x);
                    tacc += xv * __half2float(Wh[tid * 104 + sh * 32 + ci]);
                }
            }
        }
        __syncthreads();
        if (cb + 2 < 4) prefetch(p, cb + 2);
        cp_commit();
    }

    int co_a = cgrp * 64 + wc * 16 + g;
    int co_b = co_a + 8;
    float bias_a = eb3[e * 128 + co_a];
    float bias_b = eb3[e * 128 + co_b];
    float* outa = &g_e3[((size_t)t * 128 + co_a) * L2P];
    float* outb = &g_e3[((size_t)t * 128 + co_b) * L2P];
    #pragma unroll
    for (int nt = 0; nt < 8; nt++) {
        int l = l0 + wn * 64 + nt * 8 + 2 * tg;
        float2 ra, rb;
        ra.x = fmaxf(acc[nt][0] + bias_a, 0.0f);
        ra.y = fmaxf(acc[nt][1] + bias_a, 0.0f);
        rb.x = fmaxf(acc[nt][2] + bias_b, 0.0f);
        rb.y = fmaxf(acc[nt][3] + bias_b, 0.0f);
        *(float2*)(outa + l) = ra;
        *(float2*)(outb + l) = rb;
    }
    if (tail) {
        int co = cgrp * 64 + tid;
        g_e3[((size_t)t * 128 + co) * L2P + 512] = fmaxf(tacc + eb3[e * 128 + co], 0.0f);
    }
}

// ---------------- 8) top-2 combine + adaptive max-pool + aux finalize ----------
__global__ void pool_kernel(float* __restrict__ out, int out_size) {
    int idx = blockIdx.x * blockDim.x + threadIdx.x;
    if (idx == 0) {
        float aux = 0.0f;
        #pragma unroll
        for (int e = 0; e < 8; e++)
            aux += (g_srw[e] * (1.0f / 128.0f)) * (g_slg[e] * (1.0f / 128.0f));
        out[out_size - 1] = 0.01f * 8.0f * aux;
    }
    if (idx >= B * 128 * 256) return;
    int o  = idx & 255;
    int co = (idx >> 8) & 127;
    int b  = idx >> 15;
    float w0 = g_tw[b * 2 + 0];
    float w1 = g_tw[b * 2 + 1];
    const float* p0 = g_e3 + ((size_t)(b * 2 + 0) * 128 + co) * L2P;
    const float* p1 = g_e3 + ((size_t)(b * 2 + 1) * 128 + co) * L2P;
    int s  = (o * 513) >> 8;
    int en = (o * 513 + 513 + 255) >> 8;
    float m = -INFINITY;
    for (int l = s; l < en; l++)
        m = fmaxf(m, w0 * p0[l] + w1 * p1[l]);
    out[idx] = m;
}

// ---------------- launch --------------------------------------------------------
extern "C" void kernel_launch(void* const* d_in, const int* in_sizes, int n_in,
                              void* d_out, int out_size) {
    const float* x    = (const float*)d_in[0];
    const float* gw1  = (const float*)d_in[1];
    const float* gb1  = (const float*)d_in[2];
    const float* gw2  = (const float*)d_in[3];
    const float* gb2  = (const float*)d_in[4];
    const float* mw1  = (const float*)d_in[5];
    const float* mb1  = (const float*)d_in[6];
    const float* mw2  = (const float*)d_in[7];
    const float* mb2  = (const float*)d_in[8];
    const float* ew1  = (const float*)d_in[9];
    const float* eb1  = (const float*)d_in[10];
    const float* ew2  = (const float*)d_in[11];
    const float* eb2  = (const float*)d_in[12];
    const float* ew3  = (const float*)d_in[13];
    const float* eb3  = (const float*)d_in[14];
    float* out = (float*)d_out;

    static int attr_done = 0;
    if (!attr_done) {
        cudaFuncSetAttribute(gconv2_tf32_pool_kernel, cudaFuncAttributeMaxDynamicSharedMemorySize, G2T_SMEM);
        cudaFuncSetAttribute(econv2_f16_kernel, cudaFuncAttributeMaxDynamicSharedMemorySize, E2H_SMEM);
        cudaFuncSetAttribute(econv3_f16_kernel, cudaFuncAttributeMaxDynamicSharedMemorySize, E3H_SMEM);
        attr_done = 1;
    }

    prep_kernel<<<1536, 256>>>(ew2, ew3);
    fft_kernel<<<B, 512>>>(x);
    gconv1_kernel<<<dim3(2, B), 256>>>(gw1, gb1);
    gconv2_tf32_pool_kernel<<<dim3(16, B), 256, G2T_SMEM>>>(gw2, gb2);
    gate_mlp_kernel<<<B, 128>>>(mw1, mb1, mw2, mb2);
    econv1_kernel<<<NTASK, 256>>>(ew1, eb1);
    econv2_f16_kernel<<<dim3(4, 2, NTASK), 256, E2H_SMEM>>>(eb2);
    econv3_f16_kernel<<<dim3(4, 2, NTASK), 256, E3H_SMEM>>>(eb3);
    pool_kernel<<<16384, 256>>>(out, out_size);
}

// round 16
// speedup vs baseline: 5.2516x; 1.1085x over previous
#include <cuda_runtime.h>
#include <cuda_fp16.h>
#include <math.h>
#include <stdint.h>

#define B 128
#define LSEQ 4096
#define NF 2049          // rfft bins
#define NFP 2052         // padded pitch (half2 units for g_h1h)
#define L1E 1025         // expert conv1 out length
#define L1HP 1028        // g_e1h row pitch (half2 words per ci-pair row)
#define L2E 513          // expert conv2/conv3 out length
#define L2P 516          // fp32 pitch (g_e3) and half2 pitch (g_e2h)
#define NTASK 256        // B * TOP_K

// ---------------- cp.async helpers --------------------------------------------
__device__ __forceinline__ uint32_t s2u(const void* p) {
    return (uint32_t)__cvta_generic_to_shared(p);
}
__device__ __forceinline__ void cp16z(uint32_t saddr, const void* g, int src_bytes) {
    asm volatile("cp.async.ca.shared.global [%0], [%1], 16, %2;"
                 :: "r"(saddr), "l"(g), "r"(src_bytes));
}
__device__ __forceinline__ void cp_commit() {
    asm volatile("cp.async.commit_group;");
}
template <int N>
__device__ __forceinline__ void cp_wait() {
    asm volatile("cp.async.wait_group %0;" :: "n"(N));
}

// ---------------- scratch (device globals) -------------------------------------
__device__ float   g_fft[B * 2 * NF];
__device__ __half2 g_h1h[B * 16 * NFP];        // [b][ci/2][l] (.x = even ci)
__device__ float   g_pooled[B * 64];
__device__ float   g_tw[NTASK];
__device__ int     g_ti[NTASK];
__device__ float   g_srw[8];
__device__ float   g_slg[8];
__device__ __half2 g_e1h[NTASK * 32 * L1HP];   // [t][ci/2][l]
__device__ __half2 g_e2h[NTASK * 64 * L2P];    // [t][ci/2][l]
__device__ float   g_e3[NTASK * 128 * L2P];
__device__ __half  g_gw2h[64 * 160];           // [co][cb(2)][shift(5)][ci(16)]
__device__ __half  g_ew2h[8 * 128 * 320];      // [coE][cb(4)][shift(5)][ci(16)]
__device__ __half  g_ew3h[8 * 128 * 384];      // [coE][cb(4)][shift(3)][ci(32)]

// ---------------- 0) weight prep: fp16 conversion + k-step layouts -------------
__global__ void prep_kernel(const float* __restrict__ ew2, const float* __restrict__ ew3,
                            const float* __restrict__ gw2) {
    int i = blockIdx.x * 256 + threadIdx.x;
    if (i < 64 * 160) {
        int r = i % 80, cb = (i / 80) % 2, co = i / 160;
        int shift = r / 16, ci = r % 16;
        g_gw2h[i] = __float2half_rn(gw2[co * 160 + (cb * 16 + ci) * 5 + shift]);
    }
    if (i < 8 * 128 * 320) {
        int r = i % 80, cb = (i / 80) % 4, coE = i / 320;
        int shift = r / 16, ci = r % 16;
        g_ew2h[i] = __float2half_rn(ew2[(coE * 64 + cb * 16 + ci) * 5 + shift]);
    }
    if (i < 8 * 128 * 384) {
        int r = i % 96, cb = (i / 96) % 4, coE = i / 384;
        int shift = r / 32, ci = r % 32;
        g_ew3h[i] = __float2half_rn(ew3[(coE * 128 + cb * 32 + ci) * 3 + shift]);
    }
}

// ---------------- 1) Hann window + 4096-pt radix-2 FFT + zero accumulators -----
__global__ void fft_kernel(const float* __restrict__ x) {
    __shared__ float re[4096];
    __shared__ float im[4096];
    __shared__ float twr[2048];
    __shared__ float twi[2048];
    int b = blockIdx.x;
    const float* xb = x + b * LSEQ;

    if (threadIdx.x < 64) g_pooled[b * 64 + threadIdx.x] = 0.0f;
    if (b == 0 && threadIdx.x >= 64 && threadIdx.x < 72) {
        g_srw[threadIdx.x - 64] = 0.0f;
        g_slg[threadIdx.x - 64] = 0.0f;
    }

    for (int i = threadIdx.x; i < 2048; i += blockDim.x) {
        float si, sr;
        sincospif(-(float)i * (1.0f / 2048.0f), &si, &sr);
        twr[i] = sr; twi[i] = si;
    }
    for (int i = threadIdx.x; i < 4096; i += blockDim.x) {
        float w = 0.5f * (1.0f - cospif((float)i * (1.0f / 2048.0f)));
        int j = __brev((unsigned)i) >> 20;
        re[j] = xb[i] * w;
        im[j] = 0.0f;
    }
    __syncthreads();

    for (int s = 1; s <= 12; s++) {
        int half = 1 << (s - 1);
        int len  = 1 << s;
        int shft = 12 - s;
        for (int t = threadIdx.x; t < 2048; t += blockDim.x) {
            int g   = t >> (s - 1);
            int pos = t & (half - 1);
            int i0  = g * len + pos;
            int i1  = i0 + half;
            int j   = pos << shft;
            float sr = twr[j], si = twi[j];
            float ar = re[i1], ai = im[i1];
            float tr = ar * sr - ai * si;
            float ti = ar * si + ai * sr;
            float br = re[i0], bi = im[i0];
            re[i1] = br - tr; im[i1] = bi - ti;
            re[i0] = br + tr; im[i0] = bi + ti;
        }
        __syncthreads();
    }
    const float sc = 1.0f / 64.0f;
    for (int f = threadIdx.x; f < NF; f += blockDim.x) {
        g_fft[(b * 2 + 0) * NF + f] = re[f] * sc;
        g_fft[(b * 2 + 1) * NF + f] = im[f] * sc;
    }
}

// ---------------- 2) gate conv1: (2 -> 32), k=5, s=1, p=2, relu ----------------
// Outputs stored as ci-pair-interleaved half2 for fp16 gconv2.
__global__ void gconv1_kernel(const float* __restrict__ w1, const float* __restrict__ b1) {
    __shared__ __align__(16) float sin_[2][1036];
    __shared__ float sw[32][11];
    __shared__ float sb[32];
    int b  = blockIdx.y;
    int l0 = blockIdx.x * 1024;
    int tid = threadIdx.x;   // 256

    for (int i = tid; i < 2 * 1032; i += 256) {
        int ci = i / 1032, j = i % 1032;
        int g = l0 + j - 2;
        sin_[ci][j] = (g >= 0 && g < NF) ? g_fft[(b * 2 + ci) * NF + g] : 0.0f;
    }
    for (int i = tid; i < 320; i += 256) sw[i / 10][i % 10] = w1[i];
    if (tid < 32) sb[tid] = b1[tid];
    __syncthreads();

    float v[2][8];
    #pragma unroll
    for (int ci = 0; ci < 2; ci++) {
        float4 a = *(const float4*)&sin_[ci][4 * tid];
        float4 c = *(const float4*)&sin_[ci][4 * tid + 4];
        v[ci][0] = a.x; v[ci][1] = a.y; v[ci][2] = a.z; v[ci][3] = a.w;
        v[ci][4] = c.x; v[ci][5] = c.y; v[ci][6] = c.z; v[ci][7] = c.w;
    }

    #pragma unroll 2
    for (int cop = 0; cop < 16; cop++) {
        int c0 = 2 * cop, c1 = c0 + 1;
        float a0[4], a1[4];
        #pragma unroll
        for (int i = 0; i < 4; i++) { a0[i] = sb[c0]; a1[i] = sb[c1]; }
        #pragma unroll
        for (int ci = 0; ci < 2; ci++)
            #pragma unroll
            for (int k = 0; k < 5; k++) {
                float w0 = sw[c0][ci * 5 + k];
                float w1v = sw[c1][ci * 5 + k];
                #pragma unroll
                for (int i = 0; i < 4; i++) {
                    a0[i] += w0 * v[ci][i + k];
                    a1[i] += w1v * v[ci][i + k];
                }
            }
        __half2 h[4];
        #pragma unroll
        for (int i = 0; i < 4; i++)
            h[i] = __floats2half2_rn(fmaxf(a0[i], 0.0f), fmaxf(a1[i], 0.0f));
        *(uint4*)&g_h1h[((size_t)b * 16 + cop) * NFP + l0 + 4 * tid] = *(uint4*)h;
    }

    // tail l = 2048: j = 1024+k (block x=1 only)
    if (blockIdx.x == 1 && tid == 0) {
        for (int cop = 0; cop < 16; cop++) {
            int c0 = 2 * cop, c1 = c0 + 1;
            float a0 = sb[c0], a1 = sb[c1];
            #pragma unroll
            for (int ci = 0; ci < 2; ci++)
                #pragma unroll
                for (int k = 0; k < 5; k++) {
                    float xv = sin_[ci][1024 + k];
                    a0 += xv * sw[c0][ci * 5 + k];
                    a1 += xv * sw[c1][ci * 5 + k];
                }
            g_h1h[((size_t)b * 16 + cop) * NFP + 2048] =
                __floats2half2_rn(fmaxf(a0, 0.0f), fmaxf(a1, 0.0f));
        }
    }
}

// ---------------- 3) gate conv2 via FP16 mma + fused mean pool -----------------
// X smem: 8 pair-rows x 136 half2 words, word j <-> l = l0-4+j.
// W smem: halves [64][88] (chunk layout [shift(5)][ci(16)]); 2 ci-chunks of 16.
#define G2H_SX_STRIDE (8 * 136)            // uint32 words
#define G2H_SW_STRIDE (64 * 88)            // halves
#define G2H_SMEM (2 * G2H_SX_STRIDE * 4 + 2 * G2H_SW_STRIDE * 2)
__global__ void __launch_bounds__(256, 2)
gconv2_f16_pool_kernel(const float* __restrict__ b2) {
    extern __shared__ __align__(16) uint32_t dyng[];
    uint32_t* sxb = dyng;
    __half*   swb = (__half*)(dyng + 2 * G2H_SX_STRIDE);
    int b  = blockIdx.y;
    int l0 = blockIdx.x * 128;
    int tid = threadIdx.x;
    int lane = tid & 31;
    int w    = tid >> 5;
    int wc   = w & 3;
    int wn   = w >> 2;
    int g    = lane >> 2;
    int tg   = lane & 3;
    bool tail = (blockIdx.x == 15) && (tid < 64);

    const __half2* h1base = g_h1h + (size_t)b * 16 * NFP;

    auto prefetch = [&](int p, int cb) {
        uint32_t* sx = sxb + p * G2H_SX_STRIDE;
        // 8 pair-rows x 34 granules; l_start = l0-4+4*jj
        for (int i = tid; i < 8 * 34; i += 256) {
            int r = i / 34, jj = i % 34;
            int ls = l0 - 4 + 4 * jj;
            int nf = (ls < 0) ? 0 : min(4, max(0, NF - ls));
            cp16z(s2u(&sx[r * 136 + 4 * jj]),
                  h1base + (size_t)(cb * 8 + r) * NFP + max(ls, 0), 4 * nf);
        }
        __half* sw = swb + p * G2H_SW_STRIDE;
        // 64 co x 10 granules (80 halves of chunk cb)
        for (int i = tid; i < 64 * 10; i += 256) {
            int co = i / 10, kk = i % 10;
            cp16z(s2u(&sw[co * 88 + 8 * kk]),
                  g_gw2h + (size_t)co * 160 + cb * 80 + 8 * kk, 16);
        }
    };

    float acc[8][4];
    #pragma unroll
    for (int nt = 0; nt < 8; nt++)
        #pragma unroll
        for (int i = 0; i < 4; i++) acc[nt][i] = 0.0f;
    float tacc = 0.0f;

    prefetch(0, 0); cp_commit();
    prefetch(1, 1); cp_commit();

    for (int cb = 0; cb < 2; cb++) {
        int p = cb & 1;
        cp_wait<1>();
        __syncthreads();
        const uint32_t* X = sxb + p * G2H_SX_STRIDE;
        const uint32_t* W32 = (const uint32_t*)(swb + p * G2H_SW_STRIDE);

        #pragma unroll 1
        for (int ks = 0; ks < 5; ks++) {          // ks = shift, 16 ci per step
            const uint32_t* wr = W32 + (wc * 16 + g) * 44 + ks * 8 + tg;
            uint32_t a0 = wr[0];
            uint32_t a1 = wr[8 * 44];
            uint32_t a2 = wr[4];
            uint32_t a3 = wr[8 * 44 + 4];
            // word j = (l - l0) + ks + 2
            const uint32_t* x0 = X + tg * 136 + wn * 64 + g + ks + 2;
            const uint32_t* x1 = x0 + 4 * 136;
            #pragma unroll
            for (int nt = 0; nt < 8; nt++) {
                uint32_t b0 = x0[nt * 8];
                uint32_t b1 = x1[nt * 8];
                asm volatile(
                    "mma.sync.aligned.m16n8k16.row.col.f32.f16.f16.f32 "
                    "{%0,%1,%2,%3}, {%4,%5,%6,%7}, {%8,%9}, {%0,%1,%2,%3};"
                    : "+f"(acc[nt][0]), "+f"(acc[nt][1]),
                      "+f"(acc[nt][2]), "+f"(acc[nt][3])
                    : "r"(a0), "r"(a1), "r"(a2), "r"(a3), "r"(b0), "r"(b1));
            }
        }
        if (tail) {
            // l = 2048: input l' = 2046+k -> j = 2046+k - (1920-4) = 130+k
            const __half* Wh = swb + p * G2H_SW_STRIDE;
            #pragma unroll 1
            for (int ci = 0; ci < 16; ci++) {
                #pragma unroll
                for (int k = 0; k < 5; k++) {
                    __half2 h2 = *(const __half2*)&X[(ci >> 1) * 136 + 130 + k];
                    float xv = __half2float((ci & 1) ? h2.y : h2.x);
                    tacc += xv * __half2float(Wh[tid * 88 + k * 16 + ci]);
                }
            }
        }
        __syncthreads();
        cp_commit();
    }

    // fused mean-pool epilogue
    int co_a = wc * 16 + g;
    int co_b = co_a + 8;
    float bias_a = b2[co_a];
    float bias_b = b2[co_b];
    float pa = 0.0f, pb = 0.0f;
    #pragma unroll
    for (int nt = 0; nt < 8; nt++) {
        pa += fmaxf(acc[nt][0] + bias_a, 0.0f) + fmaxf(acc[nt][1] + bias_a, 0.0f);
        pb += fmaxf(acc[nt][2] + bias_b, 0.0f) + fmaxf(acc[nt][3] + bias_b, 0.0f);
    }
    pa += __shfl_xor_sync(0xffffffffu, pa, 1, 32);
    pa += __shfl_xor_sync(0xffffffffu, pa, 2, 32);
    pb += __shfl_xor_sync(0xffffffffu, pb, 1, 32);
    pb += __shfl_xor_sync(0xffffffffu, pb, 2, 32);
    if (tg == 0) {
        atomicAdd(&g_pooled[b * 64 + co_a], pa);
        atomicAdd(&g_pooled[b * 64 + co_b], pb);
    }
    if (tail)
        atomicAdd(&g_pooled[b * 64 + tid], fmaxf(tacc + b2[tid], 0.0f));
}

// ---------------- 4) router MLP + softmax + top2 + aux accumulation ------------
__global__ void gate_mlp_kernel(const float* __restrict__ w1, const float* __restrict__ b1,
                                const float* __restrict__ w2, const float* __restrict__ b2) {
    __shared__ __align__(16) float sp[64];
    __shared__ __align__(16) float sh[128];
    __shared__ float slg[8];
    int b = blockIdx.x;
    int j = threadIdx.x;

    if (j < 64) sp[j] = g_pooled[b * 64 + j] * (1.0f / 2049.0f);
    __syncthreads();

    {
        const float4* wr = (const float4*)(w1 + j * 64);
        float h0 = 0.f, h1 = 0.f, h2 = 0.f, h3 = 0.f;
        #pragma unroll
        for (int i = 0; i < 16; i++) {
            float4 wv = wr[i];
            float4 pv = *(const float4*)&sp[4 * i];
            h0 += pv.x * wv.x;
            h1 += pv.y * wv.y;
            h2 += pv.z * wv.z;
            h3 += pv.w * wv.w;
        }
        sh[j] = fmaxf((h0 + h1) + (h2 + h3) + b1[j], 0.0f);
    }
    __syncthreads();

    if (j < 8) {
        float acc = b2[j];
        const float4* wr = (const float4*)(w2 + j * 128);
        #pragma unroll
        for (int i = 0; i < 32; i++) {
            float4 wv = wr[i];
            float4 hv = *(const float4*)&sh[4 * i];
            acc += hv.x * wv.x + hv.y * wv.y + hv.z * wv.z + hv.w * wv.w;
        }
        slg[j] = acc;
    }
    __syncthreads();

    if (j == 0) {
        float lg[8];
        #pragma unroll
        for (int e = 0; e < 8; e++) lg[e] = slg[e];
        float m = lg[0];
        #pragma unroll
        for (int e = 1; e < 8; e++) m = fmaxf(m, lg[e]);
        float rw[8], s = 0.0f;
        #pragma unroll
        for (int e = 0; e < 8; e++) { rw[e] = expf(lg[e] - m); s += rw[e]; }
        float invs = 1.0f / s;
        #pragma unroll
        for (int e = 0; e < 8; e++) rw[e] *= invs;

        int i0 = 0;
        #pragma unroll
        for (int e = 1; e < 8; e++) if (rw[e] > rw[i0]) i0 = e;
        int i1 = (i0 == 0) ? 1 : 0;
        #pragma unroll
        for (int e = 0; e < 8; e++) if (e != i1 && e != i0 && rw[e] > rw[i1]) i1 = e;

        float t0 = rw[i0], t1 = rw[i1];
        float tn = 1.0f / (t0 + t1);
        g_ti[b * 2 + 0] = i0; g_ti[b * 2 + 1] = i1;
        g_tw[b * 2 + 0] = t0 * tn; g_tw[b * 2 + 1] = t1 * tn;

        #pragma unroll
        for (int e = 0; e < 8; e++) {
            atomicAdd(&g_srw[e], rw[e]);
            atomicAdd(&g_slg[e], lg[e]);
        }
    }
}

// ---------------- 5) expert conv1: (2 -> 64), k=7, s=2, p=3, relu --------------
__global__ void econv1_kernel(const float* __restrict__ ew1, const float* __restrict__ eb1) {
    __shared__ __align__(16) float sin_[2][2056];
    __shared__ float sw[64][16];
    __shared__ float sb[64];
    int t = blockIdx.x;
    int b = t >> 1;
    int e = g_ti[t];
    int tid = threadIdx.x;   // 256

    for (int i = tid; i < 2 * 2056; i += 256) {
        int ci = i / 2056, j = i % 2056;
        int g = j - 3;
        sin_[ci][j] = (g >= 0 && g < NF) ? g_fft[(b * 2 + ci) * NF + g] : 0.0f;
    }
    for (int i = tid; i < 64 * 14; i += 256) sw[i / 14][i % 14] = ew1[e * 896 + i];
    if (tid < 64) sb[tid] = eb1[e * 64 + tid];
    __syncthreads();

    float v[2][16];
    #pragma unroll
    for (int ci = 0; ci < 2; ci++) {
        float4 a = *(const float4*)&sin_[ci][8 * tid];
        float4 c = *(const float4*)&sin_[ci][8 * tid + 4];
        float4 d = *(const float4*)&sin_[ci][8 * tid + 8];
        float4 f = *(const float4*)&sin_[ci][8 * tid + 12];
        v[ci][0]=a.x;  v[ci][1]=a.y;  v[ci][2]=a.z;  v[ci][3]=a.w;
        v[ci][4]=c.x;  v[ci][5]=c.y;  v[ci][6]=c.z;  v[ci][7]=c.w;
        v[ci][8]=d.x;  v[ci][9]=d.y;  v[ci][10]=d.z; v[ci][11]=d.w;
        v[ci][12]=f.x; v[ci][13]=f.y; v[ci][14]=f.z; v[ci][15]=f.w;
    }

    #pragma unroll 2
    for (int cop = 0; cop < 32; cop++) {
        int c0 = 2 * cop, c1 = 2 * cop + 1;
        float a0[4], a1[4];
        #pragma unroll
        for (int i = 0; i < 4; i++) { a0[i] = sb[c0]; a1[i] = sb[c1]; }
        #pragma unroll
        for (int ci = 0; ci < 2; ci++)
            #pragma unroll
            for (int k = 0; k < 7; k++) {
                float w0 = sw[c0][ci * 7 + k];
                float w1 = sw[c1][ci * 7 + k];
                #pragma unroll
                for (int i = 0; i < 4; i++) {
                    a0[i] += w0 * v[ci][2 * i + k];
                    a1[i] += w1 * v[ci][2 * i + k];
                }
            }
        __half2 h[4];
        #pragma unroll
        for (int i = 0; i < 4; i++)
            h[i] = __floats2half2_rn(fmaxf(a0[i], 0.0f), fmaxf(a1[i], 0.0f));
        *(uint4*)&g_e1h[((size_t)t * 32 + cop) * L1HP + 4 * tid] = *(uint4*)h;
    }

    if (tid < 32) {
        int c0 = 2 * tid, c1 = c0 + 1;
        float a0 = sb[c0], a1 = sb[c1];
        #pragma unroll
        for (int ci = 0; ci < 2; ci++)
            #pragma unroll
            for (int k = 0; k < 7; k++) {
                float xv = sin_[ci][2048 + k];
                a0 += xv * sw[c0][ci * 7 + k];
                a1 += xv * sw[c1][ci * 7 + k];
            }
        g_e1h[((size_t)t * 32 + tid) * L1HP + 1024] =
            __floats2half2_rn(fmaxf(a0, 0.0f), fmaxf(a1, 0.0f));
    }
}

// ---------------- 6) expert conv2 via FP16 mma (m16n8k16) ----------------------
#define E2H_SX_STRIDE (8 * 264)            // uint32 words
#define E2H_SW_STRIDE (64 * 88)            // halves
#define E2H_SMEM (2 * E2H_SX_STRIDE * 4 + 2 * E2H_SW_STRIDE * 2)
__global__ void __launch_bounds__(256, 2)
econv2_f16_kernel(const float* __restrict__ eb2) {
    extern __shared__ __align__(16) uint32_t dynh2[];
    uint32_t* sxb = dynh2;
    __half*   swb = (__half*)(dynh2 + 2 * E2H_SX_STRIDE);
    int t  = blockIdx.z;
    int e  = g_ti[t];
    int l0 = blockIdx.x * 128;
    int cgrp = blockIdx.y;
    int tid = threadIdx.x;
    int lane = tid & 31;
    int w    = tid >> 5;
    int wc   = w & 3;
    int wn   = w >> 2;
    int g    = lane >> 2;
    int tg   = lane & 3;
    bool tail = (blockIdx.x == 3) && (tid < 64);

    const __half2* e1base = g_e1h + (size_t)t * 32 * L1HP;
    const __half*  wbase  = g_ew2h + (size_t)(e * 128 + cgrp * 64) * 320;

    auto prefetch = [&](int p, int cb) {
        uint32_t* sx = sxb + p * E2H_SX_STRIDE;
        for (int i = tid; i < 8 * 66; i += 256) {
            int r = i / 66, jj = i % 66;
            int ps = 2 * l0 - 4 + 4 * jj;
            int nf = (ps < 0) ? 0 : min(4, max(0, L1E - ps));
            cp16z(s2u(&sx[r * 264 + 4 * jj]),
                  e1base + (size_t)(cb * 8 + r) * L1HP + max(ps, 0), 4 * nf);
        }
        __half* sw = swb + p * E2H_SW_STRIDE;
        for (int i = tid; i < 64 * 10; i += 256) {
            int co = i / 10, kk = i % 10;
            cp16z(s2u(&sw[co * 88 + 8 * kk]),
                  wbase + (size_t)co * 320 + cb * 80 + 8 * kk, 16);
        }
    };

    float acc[8][4];
    #pragma unroll
    for (int nt = 0; nt < 8; nt++)
        #pragma unroll
        for (int i = 0; i < 4; i++) acc[nt][i] = 0.0f;
    float tacc = 0.0f;

    prefetch(0, 0); cp_commit();
    prefetch(1, 1); cp_commit();

    for (int cb = 0; cb < 4; cb++) {
        int p = cb & 1;
        cp_wait<1>();
        __syncthreads();
        const uint32_t* X = sxb + p * E2H_SX_STRIDE;
        const uint32_t* W32 = (const uint32_t*)(swb + p * E2H_SW_STRIDE);

        #pragma unroll 1
        for (int ks = 0; ks < 5; ks++) {
            const uint32_t* wr = W32 + (wc * 16 + g) * 44 + ks * 8 + tg;
            uint32_t a0 = wr[0];
            uint32_t a1 = wr[8 * 44];
            uint32_t a2 = wr[4];
            uint32_t a3 = wr[8 * 44 + 4];
            const uint32_t* x0 = X + tg * 264 + 2 * (wn * 64 + g) + ks + 2;
            const uint32_t* x1 = x0 + 4 * 264;
            #pragma unroll
            for (int nt = 0; nt < 8; nt++) {
                uint32_t b0 = x0[nt * 16];
                uint32_t b1 = x1[nt * 16];
                asm volatile(
                    "mma.sync.aligned.m16n8k16.row.col.f32.f16.f16.f32 "
                    "{%0,%1,%2,%3}, {%4,%5,%6,%7}, {%8,%9}, {%0,%1,%2,%3};"
                    : "+f"(acc[nt][0]), "+f"(acc[nt][1]),
                      "+f"(acc[nt][2]), "+f"(acc[nt][3])
                    : "r"(a0), "r"(a1), "r"(a2), "r"(a3), "r"(b0), "r"(b1));
            }
        }
        if (tail) {
            const __half* Wh = swb + p * E2H_SW_STRIDE;
            #pragma unroll 1
            for (int ci = 0; ci < 16; ci++) {
                #pragma unroll
                for (int k = 0; k < 5; k++) {
                    __half2 h2 = *(const __half2*)&X[(ci >> 1) * 264 + 258 + k];
                    float xv = __half2float((ci & 1) ? h2.y : h2.x);
                    tacc += xv * __half2float(Wh[tid * 88 + k * 16 + ci]);
                }
            }
        }
        __syncthreads();
        if (cb + 2 < 4) prefetch(p, cb + 2);
        cp_commit();
    }

    __half* outh = (__half*)g_e2h;
    int co_a = cgrp * 64 + wc * 16 + g;
    int co_b = co_a + 8;
    float bias_a = eb2[e * 128 + co_a];
    float bias_b = eb2[e * 128 + co_b];
    size_t row_a = (size_t)t * 64 + (co_a >> 1);
    size_t row_b = (size_t)t * 64 + (co_b >> 1);
    int ca = co_a & 1, cbp = co_b & 1;
    #pragma unroll
    for (int nt = 0; nt < 8; nt++) {
        int l = l0 + wn * 64 + nt * 8 + 2 * tg;
        outh[(row_a * L2P + l) * 2 + ca]     = __float2half_rn(fmaxf(acc[nt][0] + bias_a, 0.0f));
        outh[(row_a * L2P + l + 1) * 2 + ca] = __float2half_rn(fmaxf(acc[nt][1] + bias_a, 0.0f));
        outh[(row_b * L2P + l) * 2 + cbp]     = __float2half_rn(fmaxf(acc[nt][2] + bias_b, 0.0f));
        outh[(row_b * L2P + l + 1) * 2 + cbp] = __float2half_rn(fmaxf(acc[nt][3] + bias_b, 0.0f));
    }
    if (tail) {
        int co = cgrp * 64 + tid;
        size_t row = (size_t)t * 64 + (co >> 1);
        outh[(row * L2P + 512) * 2 + (co & 1)] =
            __float2half_rn(fmaxf(tacc + eb2[e * 128 + co], 0.0f));
    }
}

// ---------------- 7) expert conv3 via FP16 mma (m16n8k16) ----------------------
#define E3H_SX_STRIDE (16 * 136)           // uint32 words
#define E3H_SW_STRIDE (64 * 104)           // halves
#define E3H_SMEM (2 * E3H_SX_STRIDE * 4 + 2 * E3H_SW_STRIDE * 2)
__global__ void __launch_bounds__(256, 2)
econv3_f16_kernel(const float* __restrict__ eb3) {
    extern __shared__ __align__(16) uint32_t dynh3[];
    uint32_t* sxb = dynh3;
    __half*   swb = (__half*)(dynh3 + 2 * E3H_SX_STRIDE);
    int t  = blockIdx.z;
    int e  = g_ti[t];
    int l0 = blockIdx.x * 128;
    int cgrp = blockIdx.y;
    int tid = threadIdx.x;
    int lane = tid & 31;
    int w    = tid >> 5;
    int wc   = w & 3;
    int wn   = w >> 2;
    int g    = lane >> 2;
    int tg   = lane & 3;
    bool tail = (blockIdx.x == 3) && (tid < 64);

    const __half2* e2base = g_e2h + (size_t)t * 64 * L2P;
    const __half*  wbase  = g_ew3h + (size_t)(e * 128 + cgrp * 64) * 384;

    auto prefetch = [&](int p, int cb) {
        uint32_t* sx = sxb + p * E3H_SX_STRIDE;
        for (int i = tid; i < 16 * 34; i += 256) {
            int r = i / 34, jj = i % 34;
            int ls = l0 - 4 + 4 * jj;
            int nf = (ls < 0) ? 0 : min(4, max(0, L2E - ls));
            cp16z(s2u(&sx[r * 136 + 4 * jj]),
                  e2base + (size_t)(cb * 16 + r) * L2P + max(ls, 0), 4 * nf);
        }
        __half* sw = swb + p * E3H_SW_STRIDE;
        for (int i = tid; i < 64 * 12; i += 256) {
            int co = i / 12, kk = i % 12;
            cp16z(s2u(&sw[co * 104 + 8 * kk]),
                  wbase + (size_t)co * 384 + cb * 96 + 8 * kk, 16);
        }
    };

    float acc[8][4];
    #pragma unroll
    for (int nt = 0; nt < 8; nt++)
        #pragma unroll
        for (int i = 0; i < 4; i++) acc[nt][i] = 0.0f;
    float tacc = 0.0f;

    prefetch(0, 0); cp_commit();
    prefetch(1, 1); cp_commit();

    for (int cb = 0; cb < 4; cb++) {
        int p = cb & 1;
        cp_wait<1>();
        __syncthreads();
        const uint32_t* X = sxb + p * E3H_SX_STRIDE;
        const uint32_t* W32 = (const uint32_t*)(swb + p * E3H_SW_STRIDE);

        #pragma unroll 1
        for (int ks = 0; ks < 6; ks++) {
            int shift = ks >> 1;
            int grp   = ks & 1;
            const uint32_t* wr = W32 + (wc * 16 + g) * 52 + shift * 16 + grp * 8 + tg;
            uint32_t a0 = wr[0];
            uint32_t a1 = wr[8 * 52];
            uint32_t a2 = wr[4];
            uint32_t a3 = wr[8 * 52 + 4];
            const uint32_t* x0 = X + (grp * 8 + tg) * 136 + wn * 64 + g + shift + 3;
            const uint32_t* x1 = x0 + 4 * 136;
            #pragma unroll
            for (int nt = 0; nt < 8; nt++) {
                uint32_t b0 = x0[nt * 8];
                uint32_t b1 = x1[nt * 8];
                asm volatile(
                    "mma.sync.aligned.m16n8k16.row.col.f32.f16.f16.f32 "
                    "{%0,%1,%2,%3}, {%4,%5,%6,%7}, {%8,%9}, {%0,%1,%2,%3};"
                    : "+f"(acc[nt][0]), "+f"(acc[nt][1]),
                      "+f"(acc[nt][2]), "+f"(acc[nt][3])
                    : "r"(a0), "r"(a1), "r"(a2), "r"(a3), "r"(b0), "r"(b1));
            }
        }
        if (tail) {
            const __half* Wh = swb + p * E3H_SW_STRIDE;
            #pragma unroll 1
            for (int ci = 0; ci < 32; ci++) {
                #pragma unroll
                for (int sh = 0; sh < 3; sh++) {
                    __half2 h2 = *(const __half2*)&X[(ci >> 1) * 136 + 131 + sh];
                    float xv = __half2float((ci & 1) ? h2.y : h2.x);
                    tacc += xv * __half2float(Wh[tid * 104 + sh * 32 + ci]);
                }
            }
        }
        __syncthreads();
        if (cb + 2 < 4) prefetch(p, cb + 2);
        cp_commit();
    }

    int co_a = cgrp * 64 + wc * 16 + g;
    int co_b = co_a + 8;
    float bias_a = eb3[e * 128 + co_a];
    float bias_b = eb3[e * 128 + co_b];
    float* outa = &g_e3[((size_t)t * 128 + co_a) * L2P];
    float* outb = &g_e3[((size_t)t * 128 + co_b) * L2P];
    #pragma unroll
    for (int nt = 0; nt < 8; nt++) {
        int l = l0 + wn * 64 + nt * 8 + 2 * tg;
        float2 ra, rb;
        ra.x = fmaxf(acc[nt][0] + bias_a, 0.0f);
        ra.y = fmaxf(acc[nt][1] + bias_a, 0.0f);
        rb.x = fmaxf(acc[nt][2] + bias_b, 0.0f);
        rb.y = fmaxf(acc[nt][3] + bias_b, 0.0f);
        *(float2*)(outa + l) = ra;
        *(float2*)(outb + l) = rb;
    }
    if (tail) {
        int co = cgrp * 64 + tid;
        g_e3[((size_t)t * 128 + co) * L2P + 512] = fmaxf(tacc + eb3[e * 128 + co], 0.0f);
    }
}

// ---------------- 8) top-2 combine + adaptive max-pool + aux finalize ----------
__global__ void pool_kernel(float* __restrict__ out, int out_size) {
    int idx = blockIdx.x * blockDim.x + threadIdx.x;
    if (idx == 0) {
        float aux = 0.0f;
        #pragma unroll
        for (int e = 0; e < 8; e++)
            aux += (g_srw[e] * (1.0f / 128.0f)) * (g_slg[e] * (1.0f / 128.0f));
        out[out_size - 1] = 0.01f * 8.0f * aux;
    }
    if (idx >= B * 128 * 256) return;
    int o  = idx & 255;
    int co = (idx >> 8) & 127;
    int b  = idx >> 15;
    float w0 = g_tw[b * 2 + 0];
    float w1 = g_tw[b * 2 + 1];
    const float* p0 = g_e3 + ((size_t)(b * 2 + 0) * 128 + co) * L2P;
    const float* p1 = g_e3 + ((size_t)(b * 2 + 1) * 128 + co) * L2P;
    int s  = (o * 513) >> 8;
    int en = (o * 513 + 513 + 255) >> 8;
    float m = -INFINITY;
    for (int l = s; l < en; l++)
        m = fmaxf(m, w0 * p0[l] + w1 * p1[l]);
    out[idx] = m;
}

// ---------------- launch --------------------------------------------------------
extern "C" void kernel_launch(void* const* d_in, const int* in_sizes, int n_in,
                              void* d_out, int out_size) {
    const float* x    = (const float*)d_in[0];
    const float* gw1  = (const float*)d_in[1];
    const float* gb1  = (const float*)d_in[2];
    const float* gw2  = (const float*)d_in[3];
    const float* gb2  = (const float*)d_in[4];
    const float* mw1  = (const float*)d_in[5];
    const float* mb1  = (const float*)d_in[6];
    const float* mw2  = (const float*)d_in[7];
    const float* mb2  = (const float*)d_in[8];
    const float* ew1  = (const float*)d_in[9];
    const float* eb1  = (const float*)d_in[10];
    const float* ew2  = (const float*)d_in[11];
    const float* eb2  = (const float*)d_in[12];
    const float* ew3  = (const float*)d_in[13];
    const float* eb3  = (const float*)d_in[14];
    float* out = (float*)d_out;

    static int attr_done = 0;
    if (!attr_done) {
        cudaFuncSetAttribute(gconv2_f16_pool_kernel, cudaFuncAttributeMaxDynamicSharedMemorySize, G2H_SMEM);
        cudaFuncSetAttribute(econv2_f16_kernel, cudaFuncAttributeMaxDynamicSharedMemorySize, E2H_SMEM);
        cudaFuncSetAttribute(econv3_f16_kernel, cudaFuncAttributeMaxDynamicSharedMemorySize, E3H_SMEM);
        attr_done = 1;
    }

    prep_kernel<<<1536, 256>>>(ew2, ew3, gw2);
    fft_kernel<<<B, 512>>>(x);
    gconv1_kernel<<<dim3(2, B), 256>>>(gw1, gb1);
    gconv2_f16_pool_kernel<<<dim3(16, B), 256, G2H_SMEM>>>(gb2);
    gate_mlp_kernel<<<B, 128>>>(mw1, mb1, mw2, mb2);
    econv1_kernel<<<NTASK, 256>>>(ew1, eb1);
    econv2_f16_kernel<<<dim3(4, 2, NTASK), 256, E2H_SMEM>>>(eb2);
    econv3_f16_kernel<<<dim3(4, 2, NTASK), 256, E3H_SMEM>>>(eb3);
    pool_kernel<<<16384, 256>>>(out, out_size);
}

// round 17
// speedup vs baseline: 5.2774x; 1.0049x over previous
#include <cuda_runtime.h>
#include <cuda_fp16.h>
#include <math.h>
#include <stdint.h>

#define B 128
#define LSEQ 4096
#define NF 2049          // rfft bins
#define NFP 2052         // padded pitch (half2 units for g_h1h)
#define L1E 1025         // expert conv1 out length
#define L1HP 1028        // g_e1h row pitch (half2 words per ci-pair row)
#define L2E 513          // expert conv2/conv3 out length
#define L2P 516          // pitch (half2 for g_e2h, half for g_e3h rows)
#define NTASK 256        // B * TOP_K

// ---------------- cp.async helpers --------------------------------------------
__device__ __forceinline__ uint32_t s2u(const void* p) {
    return (uint32_t)__cvta_generic_to_shared(p);
}
__device__ __forceinline__ void cp16z(uint32_t saddr, const void* g, int src_bytes) {
    asm volatile("cp.async.ca.shared.global [%0], [%1], 16, %2;"
                 :: "r"(saddr), "l"(g), "r"(src_bytes));
}
__device__ __forceinline__ void cp_commit() {
    asm volatile("cp.async.commit_group;");
}
template <int N>
__device__ __forceinline__ void cp_wait() {
    asm volatile("cp.async.wait_group %0;" :: "n"(N));
}

// ---------------- scratch (device globals) -------------------------------------
__device__ float   g_fft[B * 2 * NF];
__device__ __half2 g_h1h[B * 16 * NFP];        // [b][ci/2][l] (.x = even ci)
__device__ float   g_pooled[B * 64];
__device__ float   g_tw[NTASK];
__device__ int     g_ti[NTASK];
__device__ float   g_srw[8];
__device__ float   g_slg[8];
__device__ __half2 g_e1h[NTASK * 32 * L1HP];   // [t][ci/2][l]
__device__ __half2 g_e2h[NTASK * 64 * L2P];    // [t][ci/2][l]
__device__ __half  g_e3h[NTASK * 128 * L2P];   // [t][co][l]
__device__ __half  g_gw2h[64 * 160];           // [co][cb(2)][shift(5)][ci(16)]
__device__ __half  g_ew2h[8 * 128 * 320];      // [coE][cb(4)][shift(5)][ci(16)]
__device__ __half  g_ew3h[8 * 128 * 384];      // [coE][cb(4)][shift(3)][ci(32)]

// ---------------- 0) weight prep: fp16 conversion + k-step layouts -------------
__global__ void prep_kernel(const float* __restrict__ ew2, const float* __restrict__ ew3,
                            const float* __restrict__ gw2) {
    int i = blockIdx.x * 256 + threadIdx.x;
    if (i < 64 * 160) {
        int r = i % 80, cb = (i / 80) % 2, co = i / 160;
        int shift = r / 16, ci = r % 16;
        g_gw2h[i] = __float2half_rn(gw2[co * 160 + (cb * 16 + ci) * 5 + shift]);
    }
    if (i < 8 * 128 * 320) {
        int r = i % 80, cb = (i / 80) % 4, coE = i / 320;
        int shift = r / 16, ci = r % 16;
        g_ew2h[i] = __float2half_rn(ew2[(coE * 64 + cb * 16 + ci) * 5 + shift]);
    }
    if (i < 8 * 128 * 384) {
        int r = i % 96, cb = (i / 96) % 4, coE = i / 384;
        int shift = r / 32, ci = r % 32;
        g_ew3h[i] = __float2half_rn(ew3[(coE * 128 + cb * 32 + ci) * 3 + shift]);
    }
}

// ---------------- 1) Hann window + 4096-pt radix-2 FFT + zero accumulators -----
__global__ void fft_kernel(const float* __restrict__ x) {
    __shared__ float re[4096];
    __shared__ float im[4096];
    __shared__ float twr[2048];
    __shared__ float twi[2048];
    int b = blockIdx.x;
    const float* xb = x + b * LSEQ;

    if (threadIdx.x < 64) g_pooled[b * 64 + threadIdx.x] = 0.0f;
    if (b == 0 && threadIdx.x >= 64 && threadIdx.x < 72) {
        g_srw[threadIdx.x - 64] = 0.0f;
        g_slg[threadIdx.x - 64] = 0.0f;
    }

    for (int i = threadIdx.x; i < 2048; i += blockDim.x) {
        float si, sr;
        sincospif(-(float)i * (1.0f / 2048.0f), &si, &sr);
        twr[i] = sr; twi[i] = si;
    }
    for (int i = threadIdx.x; i < 4096; i += blockDim.x) {
        float w = 0.5f * (1.0f - cospif((float)i * (1.0f / 2048.0f)));
        int j = __brev((unsigned)i) >> 20;
        re[j] = xb[i] * w;
        im[j] = 0.0f;
    }
    __syncthreads();

    for (int s = 1; s <= 12; s++) {
        int half = 1 << (s - 1);
        int len  = 1 << s;
        int shft = 12 - s;
        for (int t = threadIdx.x; t < 2048; t += blockDim.x) {
            int g   = t >> (s - 1);
            int pos = t & (half - 1);
            int i0  = g * len + pos;
            int i1  = i0 + half;
            int j   = pos << shft;
            float sr = twr[j], si = twi[j];
            float ar = re[i1], ai = im[i1];
            float tr = ar * sr - ai * si;
            float ti = ar * si + ai * sr;
            float br = re[i0], bi = im[i0];
            re[i1] = br - tr; im[i1] = bi - ti;
            re[i0] = br + tr; im[i0] = bi + ti;
        }
        __syncthreads();
    }
    const float sc = 1.0f / 64.0f;
    for (int f = threadIdx.x; f < NF; f += blockDim.x) {
        g_fft[(b * 2 + 0) * NF + f] = re[f] * sc;
        g_fft[(b * 2 + 1) * NF + f] = im[f] * sc;
    }
}

// ---------------- 2) gate conv1: (2 -> 32), k=5, s=1, p=2, relu ----------------
__global__ void gconv1_kernel(const float* __restrict__ w1, const float* __restrict__ b1) {
    __shared__ __align__(16) float sin_[2][1036];
    __shared__ float sw[32][11];
    __shared__ float sb[32];
    int b  = blockIdx.y;
    int l0 = blockIdx.x * 1024;
    int tid = threadIdx.x;   // 256

    for (int i = tid; i < 2 * 1032; i += 256) {
        int ci = i / 1032, j = i % 1032;
        int g = l0 + j - 2;
        sin_[ci][j] = (g >= 0 && g < NF) ? g_fft[(b * 2 + ci) * NF + g] : 0.0f;
    }
    for (int i = tid; i < 320; i += 256) sw[i / 10][i % 10] = w1[i];
    if (tid < 32) sb[tid] = b1[tid];
    __syncthreads();

    float v[2][8];
    #pragma unroll
    for (int ci = 0; ci < 2; ci++) {
        float4 a = *(const float4*)&sin_[ci][4 * tid];
        float4 c = *(const float4*)&sin_[ci][4 * tid + 4];
        v[ci][0] = a.x; v[ci][1] = a.y; v[ci][2] = a.z; v[ci][3] = a.w;
        v[ci][4] = c.x; v[ci][5] = c.y; v[ci][6] = c.z; v[ci][7] = c.w;
    }

    #pragma unroll 2
    for (int cop = 0; cop < 16; cop++) {
        int c0 = 2 * cop, c1 = c0 + 1;
        float a0[4], a1[4];
        #pragma unroll
        for (int i = 0; i < 4; i++) { a0[i] = sb[c0]; a1[i] = sb[c1]; }
        #pragma unroll
        for (int ci = 0; ci < 2; ci++)
            #pragma unroll
            for (int k = 0; k < 5; k++) {
                float w0 = sw[c0][ci * 5 + k];
                float w1v = sw[c1][ci * 5 + k];
                #pragma unroll
                for (int i = 0; i < 4; i++) {
                    a0[i] += w0 * v[ci][i + k];
                    a1[i] += w1v * v[ci][i + k];
                }
            }
        __half2 h[4];
        #pragma unroll
        for (int i = 0; i < 4; i++)
            h[i] = __floats2half2_rn(fmaxf(a0[i], 0.0f), fmaxf(a1[i], 0.0f));
        *(uint4*)&g_h1h[((size_t)b * 16 + cop) * NFP + l0 + 4 * tid] = *(uint4*)h;
    }

    // tail l = 2048: j = 1024+k (block x=1 only)
    if (blockIdx.x == 1 && tid == 0) {
        for (int cop = 0; cop < 16; cop++) {
            int c0 = 2 * cop, c1 = c0 + 1;
            float a0 = sb[c0], a1 = sb[c1];
            #pragma unroll
            for (int ci = 0; ci < 2; ci++)
                #pragma unroll
                for (int k = 0; k < 5; k++) {
                    float xv = sin_[ci][1024 + k];
                    a0 += xv * sw[c0][ci * 5 + k];
                    a1 += xv * sw[c1][ci * 5 + k];
                }
            g_h1h[((size_t)b * 16 + cop) * NFP + 2048] =
                __floats2half2_rn(fmaxf(a0, 0.0f), fmaxf(a1, 0.0f));
        }
    }
}

// ---------------- 3) gate conv2 via FP16 mma + fused mean pool -----------------
#define G2H_SX_STRIDE (8 * 136)            // uint32 words
#define G2H_SW_STRIDE (64 * 88)            // halves
#define G2H_SMEM (2 * G2H_SX_STRIDE * 4 + 2 * G2H_SW_STRIDE * 2)
__global__ void __launch_bounds__(256, 2)
gconv2_f16_pool_kernel(const float* __restrict__ b2) {
    extern __shared__ __align__(16) uint32_t dyng[];
    uint32_t* sxb = dyng;
    __half*   swb = (__half*)(dyng + 2 * G2H_SX_STRIDE);
    int b  = blockIdx.y;
    int l0 = blockIdx.x * 128;
    int tid = threadIdx.x;
    int lane = tid & 31;
    int w    = tid >> 5;
    int wc   = w & 3;
    int wn   = w >> 2;
    int g    = lane >> 2;
    int tg   = lane & 3;
    bool tail = (blockIdx.x == 15) && (tid < 64);

    const __half2* h1base = g_h1h + (size_t)b * 16 * NFP;

    auto prefetch = [&](int p, int cb) {
        uint32_t* sx = sxb + p * G2H_SX_STRIDE;
        for (int i = tid; i < 8 * 34; i += 256) {
            int r = i / 34, jj = i % 34;
            int ls = l0 - 4 + 4 * jj;
            int nf = (ls < 0) ? 0 : min(4, max(0, NF - ls));
            cp16z(s2u(&sx[r * 136 + 4 * jj]),
                  h1base + (size_t)(cb * 8 + r) * NFP + max(ls, 0), 4 * nf);
        }
        __half* sw = swb + p * G2H_SW_STRIDE;
        for (int i = tid; i < 64 * 10; i += 256) {
            int co = i / 10, kk = i % 10;
            cp16z(s2u(&sw[co * 88 + 8 * kk]),
                  g_gw2h + (size_t)co * 160 + cb * 80 + 8 * kk, 16);
        }
    };

    float acc[8][4];
    #pragma unroll
    for (int nt = 0; nt < 8; nt++)
        #pragma unroll
        for (int i = 0; i < 4; i++) acc[nt][i] = 0.0f;
    float tacc = 0.0f;

    prefetch(0, 0); cp_commit();
    prefetch(1, 1); cp_commit();

    for (int cb = 0; cb < 2; cb++) {
        int p = cb & 1;
        cp_wait<1>();
        __syncthreads();
        const uint32_t* X = sxb + p * G2H_SX_STRIDE;
        const uint32_t* W32 = (const uint32_t*)(swb + p * G2H_SW_STRIDE);

        #pragma unroll 1
        for (int ks = 0; ks < 5; ks++) {
            const uint32_t* wr = W32 + (wc * 16 + g) * 44 + ks * 8 + tg;
            uint32_t a0 = wr[0];
            uint32_t a1 = wr[8 * 44];
            uint32_t a2 = wr[4];
            uint32_t a3 = wr[8 * 44 + 4];
            const uint32_t* x0 = X + tg * 136 + wn * 64 + g + ks + 2;
            const uint32_t* x1 = x0 + 4 * 136;
            #pragma unroll
            for (int nt = 0; nt < 8; nt++) {
                uint32_t b0 = x0[nt * 8];
                uint32_t b1 = x1[nt * 8];
                asm volatile(
                    "mma.sync.aligned.m16n8k16.row.col.f32.f16.f16.f32 "
                    "{%0,%1,%2,%3}, {%4,%5,%6,%7}, {%8,%9}, {%0,%1,%2,%3};"
                    : "+f"(acc[nt][0]), "+f"(acc[nt][1]),
                      "+f"(acc[nt][2]), "+f"(acc[nt][3])
                    : "r"(a0), "r"(a1), "r"(a2), "r"(a3), "r"(b0), "r"(b1));
            }
        }
        if (tail) {
            const __half* Wh = swb + p * G2H_SW_STRIDE;
            #pragma unroll 1
            for (int ci = 0; ci < 16; ci++) {
                #pragma unroll
                for (int k = 0; k < 5; k++) {
                    __half2 h2 = *(const __half2*)&X[(ci >> 1) * 136 + 130 + k];
                    float xv = __half2float((ci & 1) ? h2.y : h2.x);
                    tacc += xv * __half2float(Wh[tid * 88 + k * 16 + ci]);
                }
            }
        }
        __syncthreads();
        cp_commit();
    }

    int co_a = wc * 16 + g;
    int co_b = co_a + 8;
    float bias_a = b2[co_a];
    float bias_b = b2[co_b];
    float pa = 0.0f, pb = 0.0f;
    #pragma unroll
    for (int nt = 0; nt < 8; nt++) {
        pa += fmaxf(acc[nt][0] + bias_a, 0.0f) + fmaxf(acc[nt][1] + bias_a, 0.0f);
        pb += fmaxf(acc[nt][2] + bias_b, 0.0f) + fmaxf(acc[nt][3] + bias_b, 0.0f);
    }
    pa += __shfl_xor_sync(0xffffffffu, pa, 1, 32);
    pa += __shfl_xor_sync(0xffffffffu, pa, 2, 32);
    pb += __shfl_xor_sync(0xffffffffu, pb, 1, 32);
    pb += __shfl_xor_sync(0xffffffffu, pb, 2, 32);
    if (tg == 0) {
        atomicAdd(&g_pooled[b * 64 + co_a], pa);
        atomicAdd(&g_pooled[b * 64 + co_b], pb);
    }
    if (tail)
        atomicAdd(&g_pooled[b * 64 + tid], fmaxf(tacc + b2[tid], 0.0f));
}

// ---------------- 4) router MLP + softmax + top2 + aux accumulation ------------
__global__ void gate_mlp_kernel(const float* __restrict__ w1, const float* __restrict__ b1,
                                const float* __restrict__ w2, const float* __restrict__ b2) {
    __shared__ __align__(16) float sp[64];
    __shared__ __align__(16) float sh[128];
    __shared__ float slg[8];
    int b = blockIdx.x;
    int j = threadIdx.x;

    if (j < 64) sp[j] = g_pooled[b * 64 + j] * (1.0f / 2049.0f);
    __syncthreads();

    {
        const float4* wr = (const float4*)(w1 + j * 64);
        float h0 = 0.f, h1 = 0.f, h2 = 0.f, h3 = 0.f;
        #pragma unroll
        for (int i = 0; i < 16; i++) {
            float4 wv = wr[i];
            float4 pv = *(const float4*)&sp[4 * i];
            h0 += pv.x * wv.x;
            h1 += pv.y * wv.y;
            h2 += pv.z * wv.z;
            h3 += pv.w * wv.w;
        }
        sh[j] = fmaxf((h0 + h1) + (h2 + h3) + b1[j], 0.0f);
    }
    __syncthreads();

    if (j < 8) {
        float acc = b2[j];
        const float4* wr = (const float4*)(w2 + j * 128);
        #pragma unroll
        for (int i = 0; i < 32; i++) {
            float4 wv = wr[i];
            float4 hv = *(const float4*)&sh[4 * i];
            acc += hv.x * wv.x + hv.y * wv.y + hv.z * wv.z + hv.w * wv.w;
        }
        slg[j] = acc;
    }
    __syncthreads();

    if (j == 0) {
        float lg[8];
        #pragma unroll
        for (int e = 0; e < 8; e++) lg[e] = slg[e];
        float m = lg[0];
        #pragma unroll
        for (int e = 1; e < 8; e++) m = fmaxf(m, lg[e]);
        float rw[8], s = 0.0f;
        #pragma unroll
        for (int e = 0; e < 8; e++) { rw[e] = expf(lg[e] - m); s += rw[e]; }
        float invs = 1.0f / s;
        #pragma unroll
        for (int e = 0; e < 8; e++) rw[e] *= invs;

        int i0 = 0;
        #pragma unroll
        for (int e = 1; e < 8; e++) if (rw[e] > rw[i0]) i0 = e;
        int i1 = (i0 == 0) ? 1 : 0;
        #pragma unroll
        for (int e = 0; e < 8; e++) if (e != i1 && e != i0 && rw[e] > rw[i1]) i1 = e;

        float t0 = rw[i0], t1 = rw[i1];
        float tn = 1.0f / (t0 + t1);
        g_ti[b * 2 + 0] = i0; g_ti[b * 2 + 1] = i1;
        g_tw[b * 2 + 0] = t0 * tn; g_tw[b * 2 + 1] = t1 * tn;

        #pragma unroll
        for (int e = 0; e < 8; e++) {
            atomicAdd(&g_srw[e], rw[e]);
            atomicAdd(&g_slg[e], lg[e]);
        }
    }
}

// ---------------- 5) expert conv1: (2 -> 64), k=7, s=2, p=3, relu --------------
__global__ void econv1_kernel(const float* __restrict__ ew1, const float* __restrict__ eb1) {
    __shared__ __align__(16) float sin_[2][2056];
    __shared__ float sw[64][16];
    __shared__ float sb[64];
    int t = blockIdx.x;
    int b = t >> 1;
    int e = g_ti[t];
    int tid = threadIdx.x;   // 256

    for (int i = tid; i < 2 * 2056; i += 256) {
        int ci = i / 2056, j = i % 2056;
        int g = j - 3;
        sin_[ci][j] = (g >= 0 && g < NF) ? g_fft[(b * 2 + ci) * NF + g] : 0.0f;
    }
    for (int i = tid; i < 64 * 14; i += 256) sw[i / 14][i % 14] = ew1[e * 896 + i];
    if (tid < 64) sb[tid] = eb1[e * 64 + tid];
    __syncthreads();

    float v[2][16];
    #pragma unroll
    for (int ci = 0; ci < 2; ci++) {
        float4 a = *(const float4*)&sin_[ci][8 * tid];
        float4 c = *(const float4*)&sin_[ci][8 * tid + 4];
        float4 d = *(const float4*)&sin_[ci][8 * tid + 8];
        float4 f = *(const float4*)&sin_[ci][8 * tid + 12];
        v[ci][0]=a.x;  v[ci][1]=a.y;  v[ci][2]=a.z;  v[ci][3]=a.w;
        v[ci][4]=c.x;  v[ci][5]=c.y;  v[ci][6]=c.z;  v[ci][7]=c.w;
        v[ci][8]=d.x;  v[ci][9]=d.y;  v[ci][10]=d.z; v[ci][11]=d.w;
        v[ci][12]=f.x; v[ci][13]=f.y; v[ci][14]=f.z; v[ci][15]=f.w;
    }

    #pragma unroll 2
    for (int cop = 0; cop < 32; cop++) {
        int c0 = 2 * cop, c1 = 2 * cop + 1;
        float a0[4], a1[4];
        #pragma unroll
        for (int i = 0; i < 4; i++) { a0[i] = sb[c0]; a1[i] = sb[c1]; }
        #pragma unroll
        for (int ci = 0; ci < 2; ci++)
            #pragma unroll
            for (int k = 0; k < 7; k++) {
                float w0 = sw[c0][ci * 7 + k];
                float w1 = sw[c1][ci * 7 + k];
                #pragma unroll
                for (int i = 0; i < 4; i++) {
                    a0[i] += w0 * v[ci][2 * i + k];
                    a1[i] += w1 * v[ci][2 * i + k];
                }
            }
        __half2 h[4];
        #pragma unroll
        for (int i = 0; i < 4; i++)
            h[i] = __floats2half2_rn(fmaxf(a0[i], 0.0f), fmaxf(a1[i], 0.0f));
        *(uint4*)&g_e1h[((size_t)t * 32 + cop) * L1HP + 4 * tid] = *(uint4*)h;
    }

    if (tid < 32) {
        int c0 = 2 * tid, c1 = c0 + 1;
        float a0 = sb[c0], a1 = sb[c1];
        #pragma unroll
        for (int ci = 0; ci < 2; ci++)
            #pragma unroll
            for (int k = 0; k < 7; k++) {
                float xv = sin_[ci][2048 + k];
                a0 += xv * sw[c0][ci * 7 + k];
                a1 += xv * sw[c1][ci * 7 + k];
            }
        g_e1h[((size_t)t * 32 + tid) * L1HP + 1024] =
            __floats2half2_rn(fmaxf(a0, 0.0f), fmaxf(a1, 0.0f));
    }
}

// ---------------- 6) expert conv2 via FP16 mma (m16n8k16) ----------------------
#define E2H_SX_STRIDE (8 * 264)            // uint32 words
#define E2H_SW_STRIDE (64 * 88)            // halves
#define E2H_SMEM (2 * E2H_SX_STRIDE * 4 + 2 * E2H_SW_STRIDE * 2)
__global__ void __launch_bounds__(256, 2)
econv2_f16_kernel(const float* __restrict__ eb2) {
    extern __shared__ __align__(16) uint32_t dynh2[];
    uint32_t* sxb = dynh2;
    __half*   swb = (__half*)(dynh2 + 2 * E2H_SX_STRIDE);
    int t  = blockIdx.z;
    int e  = g_ti[t];
    int l0 = blockIdx.x * 128;
    int cgrp = blockIdx.y;
    int tid = threadIdx.x;
    int lane = tid & 31;
    int w    = tid >> 5;
    int wc   = w & 3;
    int wn   = w >> 2;
    int g    = lane >> 2;
    int tg   = lane & 3;
    bool tail = (blockIdx.x == 3) && (tid < 64);

    const __half2* e1base = g_e1h + (size_t)t * 32 * L1HP;
    const __half*  wbase  = g_ew2h + (size_t)(e * 128 + cgrp * 64) * 320;

    auto prefetch = [&](int p, int cb) {
        uint32_t* sx = sxb + p * E2H_SX_STRIDE;
        for (int i = tid; i < 8 * 66; i += 256) {
            int r = i / 66, jj = i % 66;
            int ps = 2 * l0 - 4 + 4 * jj;
            int nf = (ps < 0) ? 0 : min(4, max(0, L1E - ps));
            cp16z(s2u(&sx[r * 264 + 4 * jj]),
                  e1base + (size_t)(cb * 8 + r) * L1HP + max(ps, 0), 4 * nf);
        }
        __half* sw = swb + p * E2H_SW_STRIDE;
        for (int i = tid; i < 64 * 10; i += 256) {
            int co = i / 10, kk = i % 10;
            cp16z(s2u(&sw[co * 88 + 8 * kk]),
                  wbase + (size_t)co * 320 + cb * 80 + 8 * kk, 16);
        }
    };

    float acc[8][4];
    #pragma unroll
    for (int nt = 0; nt < 8; nt++)
        #pragma unroll
        for (int i = 0; i < 4; i++) acc[nt][i] = 0.0f;
    float tacc = 0.0f;

    prefetch(0, 0); cp_commit();
    prefetch(1, 1); cp_commit();

    for (int cb = 0; cb < 4; cb++) {
        int p = cb & 1;
        cp_wait<1>();
        __syncthreads();
        const uint32_t* X = sxb + p * E2H_SX_STRIDE;
        const uint32_t* W32 = (const uint32_t*)(swb + p * E2H_SW_STRIDE);

        #pragma unroll 1
        for (int ks = 0; ks < 5; ks++) {
            const uint32_t* wr = W32 + (wc * 16 + g) * 44 + ks * 8 + tg;
            uint32_t a0 = wr[0];
            uint32_t a1 = wr[8 * 44];
            uint32_t a2 = wr[4];
            uint32_t a3 = wr[8 * 44 + 4];
            const uint32_t* x0 = X + tg * 264 + 2 * (wn * 64 + g) + ks + 2;
            const uint32_t* x1 = x0 + 4 * 264;
            #pragma unroll
            for (int nt = 0; nt < 8; nt++) {
                uint32_t b0 = x0[nt * 16];
                uint32_t b1 = x1[nt * 16];
                asm volatile(
                    "mma.sync.aligned.m16n8k16.row.col.f32.f16.f16.f32 "
                    "{%0,%1,%2,%3}, {%4,%5,%6,%7}, {%8,%9}, {%0,%1,%2,%3};"
                    : "+f"(acc[nt][0]), "+f"(acc[nt][1]),
                      "+f"(acc[nt][2]), "+f"(acc[nt][3])
                    : "r"(a0), "r"(a1), "r"(a2), "r"(a3), "r"(b0), "r"(b1));
            }
        }
        if (tail) {
            const __half* Wh = swb + p * E2H_SW_STRIDE;
            #pragma unroll 1
            for (int ci = 0; ci < 16; ci++) {
                #pragma unroll
                for (int k = 0; k < 5; k++) {
                    __half2 h2 = *(const __half2*)&X[(ci >> 1) * 264 + 258 + k];
                    float xv = __half2float((ci & 1) ? h2.y : h2.x);
                    tacc += xv * __half2float(Wh[tid * 88 + k * 16 + ci]);
                }
            }
        }
        __syncthreads();
        if (cb + 2 < 4) prefetch(p, cb + 2);
        cp_commit();
    }

    __half* outh = (__half*)g_e2h;
    int co_a = cgrp * 64 + wc * 16 + g;
    int co_b = co_a + 8;
    float bias_a = eb2[e * 128 + co_a];
    float bias_b = eb2[e * 128 + co_b];
    size_t row_a = (size_t)t * 64 + (co_a >> 1);
    size_t row_b = (size_t)t * 64 + (co_b >> 1);
    int ca = co_a & 1, cbp = co_b & 1;
    #pragma unroll
    for (int nt = 0; nt < 8; nt++) {
        int l = l0 + wn * 64 + nt * 8 + 2 * tg;
        outh[(row_a * L2P + l) * 2 + ca]     = __float2half_rn(fmaxf(acc[nt][0] + bias_a, 0.0f));
        outh[(row_a * L2P + l + 1) * 2 + ca] = __float2half_rn(fmaxf(acc[nt][1] + bias_a, 0.0f));
        outh[(row_b * L2P + l) * 2 + cbp]     = __float2half_rn(fmaxf(acc[nt][2] + bias_b, 0.0f));
        outh[(row_b * L2P + l + 1) * 2 + cbp] = __float2half_rn(fmaxf(acc[nt][3] + bias_b, 0.0f));
    }
    if (tail) {
        int co = cgrp * 64 + tid;
        size_t row = (size_t)t * 64 + (co >> 1);
        outh[(row * L2P + 512) * 2 + (co & 1)] =
            __float2half_rn(fmaxf(tacc + eb2[e * 128 + co], 0.0f));
    }
}

// ---------------- 7) expert conv3 via FP16 mma (m16n8k16) ----------------------
// Output stored fp16 (g_e3h) — consumed only by the weighted-max pool.
#define E3H_SX_STRIDE (16 * 136)           // uint32 words
#define E3H_SW_STRIDE (64 * 104)           // halves
#define E3H_SMEM (2 * E3H_SX_STRIDE * 4 + 2 * E3H_SW_STRIDE * 2)
__global__ void __launch_bounds__(256, 2)
econv3_f16_kernel(const float* __restrict__ eb3) {
    extern __shared__ __align__(16) uint32_t dynh3[];
    uint32_t* sxb = dynh3;
    __half*   swb = (__half*)(dynh3 + 2 * E3H_SX_STRIDE);
    int t  = blockIdx.z;
    int e  = g_ti[t];
    int l0 = blockIdx.x * 128;
    int cgrp = blockIdx.y;
    int tid = threadIdx.x;
    int lane = tid & 31;
    int w    = tid >> 5;
    int wc   = w & 3;
    int wn   = w >> 2;
    int g    = lane >> 2;
    int tg   = lane & 3;
    bool tail = (blockIdx.x == 3) && (tid < 64);

    const __half2* e2base = g_e2h + (size_t)t * 64 * L2P;
    const __half*  wbase  = g_ew3h + (size_t)(e * 128 + cgrp * 64) * 384;

    auto prefetch = [&](int p, int cb) {
        uint32_t* sx = sxb + p * E3H_SX_STRIDE;
        for (int i = tid; i < 16 * 34; i += 256) {
            int r = i / 34, jj = i % 34;
            int ls = l0 - 4 + 4 * jj;
            int nf = (ls < 0) ? 0 : min(4, max(0, L2E - ls));
            cp16z(s2u(&sx[r * 136 + 4 * jj]),
                  e2base + (size_t)(cb * 16 + r) * L2P + max(ls, 0), 4 * nf);
        }
        __half* sw = swb + p * E3H_SW_STRIDE;
        for (int i = tid; i < 64 * 12; i += 256) {
            int co = i / 12, kk = i % 12;
            cp16z(s2u(&sw[co * 104 + 8 * kk]),
                  wbase + (size_t)co * 384 + cb * 96 + 8 * kk, 16);
        }
    };

    float acc[8][4];
    #pragma unroll
    for (int nt = 0; nt < 8; nt++)
        #pragma unroll
        for (int i = 0; i < 4; i++) acc[nt][i] = 0.0f;
    float tacc = 0.0f;

    prefetch(0, 0); cp_commit();
    prefetch(1, 1); cp_commit();

    for (int cb = 0; cb < 4; cb++) {
        int p = cb & 1;
        cp_wait<1>();
        __syncthreads();
        const uint32_t* X = sxb + p * E3H_SX_STRIDE;
        const uint32_t* W32 = (const uint32_t*)(swb + p * E3H_SW_STRIDE);

        #pragma unroll 1
        for (int ks = 0; ks < 6; ks++) {
            int shift = ks >> 1;
            int grp   = ks & 1;
            const uint32_t* wr = W32 + (wc * 16 + g) * 52 + shift * 16 + grp * 8 + tg;
            uint32_t a0 = wr[0];
            uint32_t a1 = wr[8 * 52];
            uint32_t a2 = wr[4];
            uint32_t a3 = wr[8 * 52 + 4];
            const uint32_t* x0 = X + (grp * 8 + tg) * 136 + wn * 64 + g + shift + 3;
            const uint32_t* x1 = x0 + 4 * 136;
            #pragma unroll
            for (int nt = 0; nt < 8; nt++) {
                uint32_t b0 = x0[nt * 8];
                uint32_t b1 = x1[nt * 8];
                asm volatile(
                    "mma.sync.aligned.m16n8k16.row.col.f32.f16.f16.f32 "
                    "{%0,%1,%2,%3}, {%4,%5,%6,%7}, {%8,%9}, {%0,%1,%2,%3};"
                    : "+f"(acc[nt][0]), "+f"(acc[nt][1]),
                      "+f"(acc[nt][2]), "+f"(acc[nt][3])
                    : "r"(a0), "r"(a1), "r"(a2), "r"(a3), "r"(b0), "r"(b1));
            }
        }
        if (tail) {
            const __half* Wh = swb + p * E3H_SW_STRIDE;
            #pragma unroll 1
            for (int ci = 0; ci < 32; ci++) {
                #pragma unroll
                for (int sh = 0; sh < 3; sh++) {
                    __half2 h2 = *(const __half2*)&X[(ci >> 1) * 136 + 131 + sh];
                    float xv = __half2float((ci & 1) ? h2.y : h2.x);
                    tacc += xv * __half2float(Wh[tid * 104 + sh * 32 + ci]);
                }
            }
        }
        __syncthreads();
        if (cb + 2 < 4) prefetch(p, cb + 2);
        cp_commit();
    }

    int co_a = cgrp * 64 + wc * 16 + g;
    int co_b = co_a + 8;
    float bias_a = eb3[e * 128 + co_a];
    float bias_b = eb3[e * 128 + co_b];
    __half* outa = &g_e3h[((size_t)t * 128 + co_a) * L2P];
    __half* outb = &g_e3h[((size_t)t * 128 + co_b) * L2P];
    #pragma unroll
    for (int nt = 0; nt < 8; nt++) {
        int l = l0 + wn * 64 + nt * 8 + 2 * tg;   // even -> half2 aligned
        __half2 ra = __floats2half2_rn(fmaxf(acc[nt][0] + bias_a, 0.0f),
                                       fmaxf(acc[nt][1] + bias_a, 0.0f));
        __half2 rb = __floats2half2_rn(fmaxf(acc[nt][2] + bias_b, 0.0f),
                                       fmaxf(acc[nt][3] + bias_b, 0.0f));
        *(__half2*)(outa + l) = ra;
        *(__half2*)(outb + l) = rb;
    }
    if (tail) {
        int co = cgrp * 64 + tid;
        g_e3h[((size_t)t * 128 + co) * L2P + 512] =
            __float2half_rn(fmaxf(tacc + eb3[e * 128 + co], 0.0f));
    }
}

// ---------------- 8) top-2 combine + adaptive max-pool + aux finalize ----------
__global__ void pool_kernel(float* __restrict__ out, int out_size) {
    int idx = blockIdx.x * blockDim.x + threadIdx.x;
    if (idx == 0) {
        float aux = 0.0f;
        #pragma unroll
        for (int e = 0; e < 8; e++)
            aux += (g_srw[e] * (1.0f / 128.0f)) * (g_slg[e] * (1.0f / 128.0f));
        out[out_size - 1] = 0.01f * 8.0f * aux;
    }
    if (idx >= B * 128 * 256) return;
    int o  = idx & 255;
    int co = (idx >> 8) & 127;
    int b  = idx >> 15;
    float w0 = g_tw[b * 2 + 0];
    float w1 = g_tw[b * 2 + 1];
    const __half* p0 = g_e3h + ((size_t)(b * 2 + 0) * 128 + co) * L2P;
    const __half* p1 = g_e3h + ((size_t)(b * 2 + 1) * 128 + co) * L2P;
    int s  = (o * 513) >> 8;
    int en = (o * 513 + 513 + 255) >> 8;
    float m = -INFINITY;
    for (int l = s; l < en; l++)
        m = fmaxf(m, w0 * __half2float(p0[l]) + w1 * __half2float(p1[l]));
    out[idx] = m;
}

// ---------------- launch --------------------------------------------------------
extern "C" void kernel_launch(void* const* d_in, const int* in_sizes, int n_in,
                              void* d_out, int out_size) {
    const float* x    = (const float*)d_in[0];
    const float* gw1  = (const float*)d_in[1];
    const float* gb1  = (const float*)d_in[2];
    const float* gw2  = (const float*)d_in[3];
    const float* gb2  = (const float*)d_in[4];
    const float* mw1  = (const float*)d_in[5];
    const float* mb1  = (const float*)d_in[6];
    const float* mw2  = (const float*)d_in[7];
    const float* mb2  = (const float*)d_in[8];
    const float* ew1  = (const float*)d_in[9];
    const float* eb1  = (const float*)d_in[10];
    const float* ew2  = (const float*)d_in[11];
    const float* eb2  = (const float*)d_in[12];
    const float* ew3  = (const float*)d_in[13];
    const float* eb3  = (const float*)d_in[14];
    float* out = (float*)d_out;

    static int attr_done = 0;
    if (!attr_done) {
        cudaFuncSetAttribute(gconv2_f16_pool_kernel, cudaFuncAttributeMaxDynamicSharedMemorySize, G2H_SMEM);
        cudaFuncSetAttribute(econv2_f16_kernel, cudaFuncAttributeMaxDynamicSharedMemorySize, E2H_SMEM);
        cudaFuncSetAttribute(econv3_f16_kernel, cudaFuncAttributeMaxDynamicSharedMemorySize, E3H_SMEM);
        attr_done = 1;
    }

    prep_kernel<<<1536, 256>>>(ew2, ew3, gw2);
    fft_kernel<<<B, 1024>>>(x);
    gconv1_kernel<<<dim3(2, B), 256>>>(gw1, gb1);
    gconv2_f16_pool_kernel<<<dim3(16, B), 256, G2H_SMEM>>>(gb2);
    gate_mlp_kernel<<<B, 128>>>(mw1, mb1, mw2, mb2);
    econv1_kernel<<<NTASK, 256>>>(ew1, eb1);
    econv2_f16_kernel<<<dim3(4, 2, NTASK), 256, E2H_SMEM>>>(eb2);
    econv3_f16_kernel<<<dim3(4, 2, NTASK), 256, E3H_SMEM>>>(eb3);
    pool_kernel<<<16384, 256>>>(out, out_size);
}